// round 1
// baseline (speedup 1.0000x reference)
#include <cuda_runtime.h>

#define DIM    768
#define SEQ    1024
#define BATCH  8
#define ROWS   (BATCH*SEQ)      /* 8192 */
#define HEADS  12
#define HD     64
#define HIDDEN 3072
#define LN_EPS 1e-6f

/* ---------------- scratch (static device globals; no allocations) -------- */
__device__ float g_y  [ROWS * DIM];              /* LN output (reused)       */
__device__ float g_qkv[ROWS * 3 * DIM];          /* QKV projection           */
__device__ float g_sc [(long)BATCH*HEADS*SEQ*SEQ]; /* attention scores       */
__device__ float g_att[ROWS * DIM];              /* attention output         */
__device__ float g_x1 [ROWS * DIM];              /* residual after attention */
__device__ float g_h  [ROWS * HIDDEN];           /* fc1 output               */

/* ---------------- layernorm: one block per row (768 = 3*256) ------------- */
__global__ void __launch_bounds__(256) ln_kernel(
    const float* __restrict__ x, const float* __restrict__ sc,
    const float* __restrict__ bi, float* __restrict__ y)
{
    long row = blockIdx.x;
    int  t   = threadIdx.x;
    const float* xr = x + row * DIM;
    float v0 = xr[t], v1 = xr[t + 256], v2 = xr[t + 512];

    __shared__ float sbuf[8];
    __shared__ float s_mu, s_r;

    float s = v0 + v1 + v2;
    #pragma unroll
    for (int o = 16; o > 0; o >>= 1) s += __shfl_xor_sync(0xffffffffu, s, o);
    if ((t & 31) == 0) sbuf[t >> 5] = s;
    __syncthreads();
    if (t < 8) {
        float r = sbuf[t];
        #pragma unroll
        for (int o = 4; o > 0; o >>= 1) r += __shfl_xor_sync(0xffu, r, o);
        if (t == 0) s_mu = r * (1.0f / DIM);
    }
    __syncthreads();
    float mu = s_mu;
    float d0 = v0 - mu, d1 = v1 - mu, d2 = v2 - mu;
    float q = d0*d0 + d1*d1 + d2*d2;
    #pragma unroll
    for (int o = 16; o > 0; o >>= 1) q += __shfl_xor_sync(0xffffffffu, q, o);
    if ((t & 31) == 0) sbuf[t >> 5] = q;
    __syncthreads();
    if (t < 8) {
        float r = sbuf[t];
        #pragma unroll
        for (int o = 4; o > 0; o >>= 1) r += __shfl_xor_sync(0xffu, r, o);
        if (t == 0) s_r = rsqrtf(r * (1.0f / DIM) + LN_EPS);
    }
    __syncthreads();
    float rs = s_r;
    float* yr = y + row * DIM;
    yr[t      ] = d0 * rs * sc[t      ] + bi[t      ];
    yr[t + 256] = d1 * rs * sc[t + 256] + bi[t + 256];
    yr[t + 512] = d2 * rs * sc[t + 512] + bi[t + 512];
}

/* ---------------- softmax over rows of 1024 ------------------------------ */
__global__ void __launch_bounds__(256) softmax_kernel(float* __restrict__ S)
{
    long row = blockIdx.x;
    int  t   = threadIdx.x;
    float4* p = reinterpret_cast<float4*>(S + row * SEQ);
    float4 v = p[t];

    __shared__ float sbuf[8];
    __shared__ float s_m, s_sum;

    float m = fmaxf(fmaxf(v.x, v.y), fmaxf(v.z, v.w));
    #pragma unroll
    for (int o = 16; o > 0; o >>= 1) m = fmaxf(m, __shfl_xor_sync(0xffffffffu, m, o));
    if ((t & 31) == 0) sbuf[t >> 5] = m;
    __syncthreads();
    if (t < 8) {
        float r = sbuf[t];
        #pragma unroll
        for (int o = 4; o > 0; o >>= 1) r = fmaxf(r, __shfl_xor_sync(0xffu, r, o));
        if (t == 0) s_m = r;
    }
    __syncthreads();
    float mm = s_m;
    v.x = __expf(v.x - mm); v.y = __expf(v.y - mm);
    v.z = __expf(v.z - mm); v.w = __expf(v.w - mm);
    float s = v.x + v.y + v.z + v.w;
    #pragma unroll
    for (int o = 16; o > 0; o >>= 1) s += __shfl_xor_sync(0xffffffffu, s, o);
    if ((t & 31) == 0) sbuf[t >> 5] = s;
    __syncthreads();
    if (t < 8) {
        float r = sbuf[t];
        #pragma unroll
        for (int o = 4; o > 0; o >>= 1) r += __shfl_xor_sync(0xffu, r, o);
        if (t == 0) s_sum = r;
    }
    __syncthreads();
    float inv = 1.0f / s_sum;
    v.x *= inv; v.y *= inv; v.z *= inv; v.w *= inv;
    p[t] = v;
}

/* ---------------- generic tiled fp32 GEMM --------------------------------
 * C = gelu?(alpha * A@op(B) + bias) + residual
 * 128x128 tile, BK=8, 256 threads, 8x8 per-thread microtile.
 * Batched via blockIdx.z: off = (bz/12)*s?1 + (bz%12)*s?2.
 * M, N multiples of 8; M multiple of 128; N guarded.  K multiple of 8. */
#define BM 128
#define BN 128
#define BK 8
#define SPAD 4

__device__ __forceinline__ float gelu_tanh(float u)
{
    return 0.5f * u * (1.0f + tanhf(0.7978845608028654f * (u + 0.044715f * u * u * u)));
}

template <int TRANSB>
__global__ void __launch_bounds__(256) gemm_kernel(
    const float* __restrict__ A, const float* __restrict__ B,
    const float* __restrict__ bias, const float* __restrict__ Rsd,
    float* __restrict__ C,
    int M, int N, int K, int lda, int ldb, int ldc,
    long sA1, long sA2, long sB1, long sB2, long sC1, long sC2,
    float alpha, int doGelu)
{
    __shared__ float As[BK][BM + SPAD];
    __shared__ float Bs[BK][BN + SPAD];

    int bz = blockIdx.z;
    int bi = bz / HEADS, bj = bz - bi * HEADS;
    const float* Ab = A + bi * sA1 + bj * sA2;
    const float* Bb = B + bi * sB1 + bj * sB2;
    float*       Cb = C + bi * sC1 + bj * sC2;

    int m0 = blockIdx.y * BM;
    int n0 = blockIdx.x * BN;
    int t  = threadIdx.x;
    int tx = t & 15, ty = t >> 4;

    int am = t >> 1,  ak = (t & 1) * 4;          /* A tile loader      */
    int bkN = t >> 5, bnN = (t & 31) * 4;        /* B loader (NN)      */
    int bnT = t >> 1, bkT = (t & 1) * 4;         /* B loader (NT)      */

    float acc[8][8];
    #pragma unroll
    for (int i = 0; i < 8; i++)
        #pragma unroll
        for (int j = 0; j < 8; j++) acc[i][j] = 0.0f;

    int kt = K / BK;
    for (int kk = 0; kk < kt; kk++) {
        int k0 = kk * BK;
        float4 a4 = *reinterpret_cast<const float4*>(
            Ab + (long)(m0 + am) * lda + k0 + ak);
        As[ak + 0][am] = a4.x; As[ak + 1][am] = a4.y;
        As[ak + 2][am] = a4.z; As[ak + 3][am] = a4.w;

        if (TRANSB) {
            float4 b4 = make_float4(0.f, 0.f, 0.f, 0.f);
            if (n0 + bnT < N)
                b4 = *reinterpret_cast<const float4*>(
                    Bb + (long)(n0 + bnT) * ldb + k0 + bkT);
            Bs[bkT + 0][bnT] = b4.x; Bs[bkT + 1][bnT] = b4.y;
            Bs[bkT + 2][bnT] = b4.z; Bs[bkT + 3][bnT] = b4.w;
        } else {
            float4 b4 = make_float4(0.f, 0.f, 0.f, 0.f);
            if (n0 + bnN < N)
                b4 = *reinterpret_cast<const float4*>(
                    Bb + (long)(k0 + bkN) * ldb + n0 + bnN);
            *reinterpret_cast<float4*>(&Bs[bkN][bnN]) = b4;
        }
        __syncthreads();

        #pragma unroll
        for (int k = 0; k < BK; k++) {
            float4 a0 = *reinterpret_cast<const float4*>(&As[k][ty * 8]);
            float4 a1 = *reinterpret_cast<const float4*>(&As[k][ty * 8 + 4]);
            float4 b0 = *reinterpret_cast<const float4*>(&Bs[k][tx * 8]);
            float4 b1 = *reinterpret_cast<const float4*>(&Bs[k][tx * 8 + 4]);
            float ra[8] = {a0.x, a0.y, a0.z, a0.w, a1.x, a1.y, a1.z, a1.w};
            float rb[8] = {b0.x, b0.y, b0.z, b0.w, b1.x, b1.y, b1.z, b1.w};
            #pragma unroll
            for (int i = 0; i < 8; i++)
                #pragma unroll
                for (int j = 0; j < 8; j++)
                    acc[i][j] += ra[i] * rb[j];
        }
        __syncthreads();
    }

    int n = n0 + tx * 8;
    if (n >= N) return;
    float bv[8];
    #pragma unroll
    for (int j = 0; j < 8; j++) bv[j] = bias ? bias[n + j] : 0.0f;

    #pragma unroll
    for (int i = 0; i < 8; i++) {
        long crow = (long)(m0 + ty * 8 + i) * ldc + n;
        float out[8];
        #pragma unroll
        for (int j = 0; j < 8; j++) {
            float v = acc[i][j] * alpha + bv[j];
            if (doGelu) v = gelu_tanh(v);
            out[j] = v;
        }
        if (Rsd) {
            #pragma unroll
            for (int j = 0; j < 8; j++) out[j] += Rsd[crow + j];
        }
        *reinterpret_cast<float4*>(Cb + crow)     = make_float4(out[0], out[1], out[2], out[3]);
        *reinterpret_cast<float4*>(Cb + crow + 4) = make_float4(out[4], out[5], out[6], out[7]);
    }
}

/* ---------------- launch -------------------------------------------------- */
extern "C" void kernel_launch(void* const* d_in, const int* in_sizes, int n_in,
                              void* d_out, int out_size)
{
    const float* x     = (const float*)d_in[0];
    const float* ln1s  = (const float*)d_in[1];
    const float* ln1b  = (const float*)d_in[2];
    const float* qkvw  = (const float*)d_in[3];
    const float* qkvb  = (const float*)d_in[4];
    const float* projw = (const float*)d_in[5];
    const float* projb = (const float*)d_in[6];
    const float* ln2s  = (const float*)d_in[7];
    const float* ln2b  = (const float*)d_in[8];
    const float* fc1w  = (const float*)d_in[9];
    const float* fc1b  = (const float*)d_in[10];
    const float* fc2w  = (const float*)d_in[11];
    const float* fc2b  = (const float*)d_in[12];
    float* out = (float*)d_out;

    float *y, *qkv, *sc, *att, *x1, *hb;
    cudaGetSymbolAddress((void**)&y,   g_y);
    cudaGetSymbolAddress((void**)&qkv, g_qkv);
    cudaGetSymbolAddress((void**)&sc,  g_sc);
    cudaGetSymbolAddress((void**)&att, g_att);
    cudaGetSymbolAddress((void**)&x1,  g_x1);
    cudaGetSymbolAddress((void**)&hb,  g_h);

    /* 1. LN1 */
    ln_kernel<<<ROWS, 256>>>(x, ln1s, ln1b, y);

    /* 2. QKV: [8192,768] @ [768,2304] + b */
    gemm_kernel<0><<<dim3(18, 64, 1), 256>>>(
        y, qkvw, qkvb, nullptr, qkv,
        ROWS, 3 * DIM, DIM, DIM, 3 * DIM, 3 * DIM,
        0, 0, 0, 0, 0, 0, 1.0f, 0);

    /* 3. scores[b,h] = Q @ K^T * 0.125   (96 batched NT GEMMs) */
    gemm_kernel<1><<<dim3(8, 8, BATCH * HEADS), 256>>>(
        qkv, qkv + DIM, nullptr, nullptr, sc,
        SEQ, SEQ, HD, 3 * DIM, 3 * DIM, SEQ,
        (long)SEQ * 3 * DIM, HD, (long)SEQ * 3 * DIM, HD,
        (long)HEADS * SEQ * SEQ, (long)SEQ * SEQ,
        0.125f, 0);

    /* 4. softmax over k */
    softmax_kernel<<<BATCH * HEADS * SEQ, 256>>>(sc);

    /* 5. O[b,h] = P @ V   (96 batched NN GEMMs) */
    gemm_kernel<0><<<dim3(1, 8, BATCH * HEADS), 256>>>(
        sc, qkv + 2 * DIM, nullptr, nullptr, att,
        SEQ, HD, SEQ, SEQ, 3 * DIM, DIM,
        (long)HEADS * SEQ * SEQ, (long)SEQ * SEQ,
        (long)SEQ * 3 * DIM, HD,
        (long)SEQ * DIM, HD,
        1.0f, 0);

    /* 6. proj + residual: x1 = x + att @ Wp + bp */
    gemm_kernel<0><<<dim3(6, 64, 1), 256>>>(
        att, projw, projb, x, x1,
        ROWS, DIM, DIM, DIM, DIM, DIM,
        0, 0, 0, 0, 0, 0, 1.0f, 0);

    /* 7. LN2 */
    ln_kernel<<<ROWS, 256>>>(x1, ln2s, ln2b, y);

    /* 8. fc1 + gelu */
    gemm_kernel<0><<<dim3(24, 64, 1), 256>>>(
        y, fc1w, fc1b, nullptr, hb,
        ROWS, HIDDEN, DIM, DIM, HIDDEN, HIDDEN,
        0, 0, 0, 0, 0, 0, 1.0f, 1);

    /* 9. fc2 + residual -> out */
    gemm_kernel<0><<<dim3(6, 64, 1), 256>>>(
        hb, fc2w, fc2b, x1, out,
        ROWS, DIM, HIDDEN, HIDDEN, DIM, DIM,
        0, 0, 0, 0, 0, 0, 1.0f, 0);
}

// round 2
// speedup vs baseline: 1.7873x; 1.7873x over previous
#include <cuda_runtime.h>
#include <cuda_bf16.h>
#include <cstdint>

#define DIM    768
#define SEQ    1024
#define BATCH  8
#define ROWS   (BATCH*SEQ)      /* 8192 */
#define HEADS  12
#define HD     64
#define HIDDEN 3072
#define LN_EPS 1e-6f

/* ---------------- scratch (static device globals; no allocations) -------- */
__device__ float g_y  [ROWS * DIM];
__device__ float g_qkv[ROWS * 3 * DIM];
__device__ float g_sc [(long)BATCH*HEADS*SEQ*SEQ];
__device__ float g_att[ROWS * DIM];
__device__ float g_x1 [ROWS * DIM];
__device__ float g_h  [ROWS * HIDDEN];

/* ---------------- layernorm ------------------------------------------------ */
__global__ void __launch_bounds__(256) ln_kernel(
    const float* __restrict__ x, const float* __restrict__ sc,
    const float* __restrict__ bi, float* __restrict__ y)
{
    long row = blockIdx.x;
    int  t   = threadIdx.x;
    const float* xr = x + row * DIM;
    float v0 = xr[t], v1 = xr[t + 256], v2 = xr[t + 512];

    __shared__ float sbuf[8];
    __shared__ float s_mu, s_r;

    float s = v0 + v1 + v2;
    #pragma unroll
    for (int o = 16; o > 0; o >>= 1) s += __shfl_xor_sync(0xffffffffu, s, o);
    if ((t & 31) == 0) sbuf[t >> 5] = s;
    __syncthreads();
    if (t < 8) {
        float r = sbuf[t];
        #pragma unroll
        for (int o = 4; o > 0; o >>= 1) r += __shfl_xor_sync(0xffu, r, o);
        if (t == 0) s_mu = r * (1.0f / DIM);
    }
    __syncthreads();
    float mu = s_mu;
    float d0 = v0 - mu, d1 = v1 - mu, d2 = v2 - mu;
    float q = d0*d0 + d1*d1 + d2*d2;
    #pragma unroll
    for (int o = 16; o > 0; o >>= 1) q += __shfl_xor_sync(0xffffffffu, q, o);
    if ((t & 31) == 0) sbuf[t >> 5] = q;
    __syncthreads();
    if (t < 8) {
        float r = sbuf[t];
        #pragma unroll
        for (int o = 4; o > 0; o >>= 1) r += __shfl_xor_sync(0xffu, r, o);
        if (t == 0) s_r = rsqrtf(r * (1.0f / DIM) + LN_EPS);
    }
    __syncthreads();
    float rs = s_r;
    float* yr = y + row * DIM;
    yr[t      ] = d0 * rs * sc[t      ] + bi[t      ];
    yr[t + 256] = d1 * rs * sc[t + 256] + bi[t + 256];
    yr[t + 512] = d2 * rs * sc[t + 512] + bi[t + 512];
}

/* ---------------- softmax over rows of 1024 ------------------------------- */
__global__ void __launch_bounds__(256) softmax_kernel(float* __restrict__ S)
{
    long row = blockIdx.x;
    int  t   = threadIdx.x;
    float4* p = reinterpret_cast<float4*>(S + row * SEQ);
    float4 v = p[t];

    __shared__ float sbuf[8];
    __shared__ float s_m, s_sum;

    float m = fmaxf(fmaxf(v.x, v.y), fmaxf(v.z, v.w));
    #pragma unroll
    for (int o = 16; o > 0; o >>= 1) m = fmaxf(m, __shfl_xor_sync(0xffffffffu, m, o));
    if ((t & 31) == 0) sbuf[t >> 5] = m;
    __syncthreads();
    if (t < 8) {
        float r = sbuf[t];
        #pragma unroll
        for (int o = 4; o > 0; o >>= 1) r = fmaxf(r, __shfl_xor_sync(0xffu, r, o));
        if (t == 0) s_m = r;
    }
    __syncthreads();
    float mm = s_m;
    v.x = __expf(v.x - mm); v.y = __expf(v.y - mm);
    v.z = __expf(v.z - mm); v.w = __expf(v.w - mm);
    float s = v.x + v.y + v.z + v.w;
    #pragma unroll
    for (int o = 16; o > 0; o >>= 1) s += __shfl_xor_sync(0xffffffffu, s, o);
    if ((t & 31) == 0) sbuf[t >> 5] = s;
    __syncthreads();
    if (t < 8) {
        float r = sbuf[t];
        #pragma unroll
        for (int o = 4; o > 0; o >>= 1) r += __shfl_xor_sync(0xffu, r, o);
        if (t == 0) s_sum = r;
    }
    __syncthreads();
    float inv = 1.0f / s_sum;
    v.x *= inv; v.y *= inv; v.z *= inv; v.w *= inv;
    p[t] = v;
}

/* ================= tensor-core GEMM (bf16 split, fp32-accurate) ===========
 * C = gelu?(alpha * A@op(B) + bias) + residual
 * Block 128x128, BK=16, 8 warps (warp tile 64x32), mma.m16n8k16.bf16.
 * Each fp32 operand x = hi + lo (bf16 each); product uses hi*hi+hi*lo+lo*hi.
 */
#define BM 128
#define BN 128
#define BK 16
#define SE 24           /* padded smem row stride (bf16 elems) — conflict-free */

__device__ __forceinline__ float gelu_tanh(float u)
{
    return 0.5f * u * (1.0f + tanhf(0.7978845608028654f * (u + 0.044715f * u * u * u)));
}

__device__ __forceinline__ void mma16816(
    float& c0, float& c1, float& c2, float& c3,
    uint32_t a0, uint32_t a1, uint32_t a2, uint32_t a3,
    uint32_t b0, uint32_t b1)
{
    asm volatile(
        "mma.sync.aligned.m16n8k16.row.col.f32.bf16.bf16.f32 "
        "{%0,%1,%2,%3},{%4,%5,%6,%7},{%8,%9},{%0,%1,%2,%3};"
        : "+f"(c0), "+f"(c1), "+f"(c2), "+f"(c3)
        : "r"(a0), "r"(a1), "r"(a2), "r"(a3), "r"(b0), "r"(b1));
}

/* split 8 fp32 into hi/lo bf16 uint4s */
__device__ __forceinline__ void cvt8(const float* f, uint4& hi4, uint4& lo4)
{
    uint32_t h[4], l[4];
    #pragma unroll
    for (int i = 0; i < 4; i++) {
        float x0 = f[2*i], x1 = f[2*i+1];
        __nv_bfloat16 h0 = __float2bfloat16(x0);
        __nv_bfloat16 h1 = __float2bfloat16(x1);
        float r0 = x0 - __bfloat162float(h0);
        float r1 = x1 - __bfloat162float(h1);
        __nv_bfloat16 l0 = __float2bfloat16(r0);
        __nv_bfloat16 l1 = __float2bfloat16(r1);
        h[i] = ((uint32_t)__bfloat16_as_ushort(h1) << 16) | __bfloat16_as_ushort(h0);
        l[i] = ((uint32_t)__bfloat16_as_ushort(l1) << 16) | __bfloat16_as_ushort(l0);
    }
    hi4 = make_uint4(h[0], h[1], h[2], h[3]);
    lo4 = make_uint4(l[0], l[1], l[2], l[3]);
}

template <int TRANSB>
__global__ void __launch_bounds__(256) gemm_tc(
    const float* __restrict__ A, const float* __restrict__ B,
    const float* __restrict__ bias, const float* __restrict__ Rsd,
    float* __restrict__ C,
    int M, int N, int K, int lda, int ldb, int ldc,
    long sA1, long sA2, long sB1, long sB2, long sC1, long sC2,
    float alpha, int doGelu)
{
    __shared__ __nv_bfloat16 AsH[2][BM][SE];
    __shared__ __nv_bfloat16 AsL[2][BM][SE];
    __shared__ __nv_bfloat16 BsH[2][BN][SE];
    __shared__ __nv_bfloat16 BsL[2][BN][SE];

    int bz = blockIdx.z;
    int bi = bz / HEADS, bj = bz - bi * HEADS;
    const float* Ab = A + bi * sA1 + bj * sA2;
    const float* Bb = B + bi * sB1 + bj * sB2;
    float*       Cb = C + bi * sC1 + bj * sC2;

    int m0 = blockIdx.y * BM;
    int n0 = blockIdx.x * BN;
    int t  = threadIdx.x;
    int lane = t & 31, wid = t >> 5;
    int gid = lane >> 2, tig = lane & 3;
    int warp_m = (wid >> 2) << 6;      /* 0 or 64  */
    int warp_n = (wid & 3) << 5;       /* 0,32,64,96 */

    /* loader mapping (A and B tile both 128x16 fp32 per buffer) */
    int lrow = t >> 1;                 /* 0..127 */
    int lcol = (t & 1) * 8;            /* 0 or 8 */

    float acc[4][4][4];
    #pragma unroll
    for (int i = 0; i < 4; i++)
        #pragma unroll
        for (int j = 0; j < 4; j++)
            #pragma unroll
            for (int r = 0; r < 4; r++) acc[i][j][r] = 0.0f;

    float fa[8], fb[8];
    int kt = K / BK;

    /* ---- gmem fetch for k-chunk kk into registers ---- */
    auto fetch = [&](int kk) {
        int k0 = kk * BK;
        float4 a0 = *reinterpret_cast<const float4*>(Ab + (long)(m0 + lrow) * lda + k0 + lcol);
        float4 a1 = *reinterpret_cast<const float4*>(Ab + (long)(m0 + lrow) * lda + k0 + lcol + 4);
        fa[0]=a0.x; fa[1]=a0.y; fa[2]=a0.z; fa[3]=a0.w;
        fa[4]=a1.x; fa[5]=a1.y; fa[6]=a1.z; fa[7]=a1.w;
        if (TRANSB) {
            if (n0 + lrow < N) {
                float4 b0 = *reinterpret_cast<const float4*>(Bb + (long)(n0 + lrow) * ldb + k0 + lcol);
                float4 b1 = *reinterpret_cast<const float4*>(Bb + (long)(n0 + lrow) * ldb + k0 + lcol + 4);
                fb[0]=b0.x; fb[1]=b0.y; fb[2]=b0.z; fb[3]=b0.w;
                fb[4]=b1.x; fb[5]=b1.y; fb[6]=b1.z; fb[7]=b1.w;
            } else {
                #pragma unroll
                for (int i = 0; i < 8; i++) fb[i] = 0.0f;
            }
        } else {
            if (n0 + lrow < N) {
                #pragma unroll
                for (int i = 0; i < 8; i++)
                    fb[i] = Bb[(long)(k0 + lcol + i) * ldb + n0 + lrow];
            } else {
                #pragma unroll
                for (int i = 0; i < 8; i++) fb[i] = 0.0f;
            }
        }
    };

    /* ---- convert + store registers into smem buffer nb ---- */
    auto store = [&](int nb) {
        uint4 h4, l4;
        cvt8(fa, h4, l4);
        *reinterpret_cast<uint4*>(&AsH[nb][lrow][lcol]) = h4;
        *reinterpret_cast<uint4*>(&AsL[nb][lrow][lcol]) = l4;
        cvt8(fb, h4, l4);
        *reinterpret_cast<uint4*>(&BsH[nb][lrow][lcol]) = h4;
        *reinterpret_cast<uint4*>(&BsL[nb][lrow][lcol]) = l4;
    };

    fetch(0);
    store(0);
    __syncthreads();

    for (int kk = 0; kk < kt; kk++) {
        int cur = kk & 1;
        if (kk + 1 < kt) fetch(kk + 1);

        /* load fragments */
        uint32_t aH[4][4], aL[4][4], bH[4][2], bL[4][2];
        #pragma unroll
        for (int tm = 0; tm < 4; tm++) {
            int ar = warp_m + tm * 16 + gid;
            aH[tm][0] = *reinterpret_cast<const uint32_t*>(&AsH[cur][ar    ][tig*2    ]);
            aH[tm][1] = *reinterpret_cast<const uint32_t*>(&AsH[cur][ar + 8][tig*2    ]);
            aH[tm][2] = *reinterpret_cast<const uint32_t*>(&AsH[cur][ar    ][tig*2 + 8]);
            aH[tm][3] = *reinterpret_cast<const uint32_t*>(&AsH[cur][ar + 8][tig*2 + 8]);
            aL[tm][0] = *reinterpret_cast<const uint32_t*>(&AsL[cur][ar    ][tig*2    ]);
            aL[tm][1] = *reinterpret_cast<const uint32_t*>(&AsL[cur][ar + 8][tig*2    ]);
            aL[tm][2] = *reinterpret_cast<const uint32_t*>(&AsL[cur][ar    ][tig*2 + 8]);
            aL[tm][3] = *reinterpret_cast<const uint32_t*>(&AsL[cur][ar + 8][tig*2 + 8]);
        }
        #pragma unroll
        for (int tn = 0; tn < 4; tn++) {
            int br = warp_n + tn * 8 + gid;
            bH[tn][0] = *reinterpret_cast<const uint32_t*>(&BsH[cur][br][tig*2    ]);
            bH[tn][1] = *reinterpret_cast<const uint32_t*>(&BsH[cur][br][tig*2 + 8]);
            bL[tn][0] = *reinterpret_cast<const uint32_t*>(&BsL[cur][br][tig*2    ]);
            bL[tn][1] = *reinterpret_cast<const uint32_t*>(&BsL[cur][br][tig*2 + 8]);
        }

        #pragma unroll
        for (int tm = 0; tm < 4; tm++)
            #pragma unroll
            for (int tn = 0; tn < 4; tn++) {
                float* c = acc[tm][tn];
                mma16816(c[0], c[1], c[2], c[3],
                         aH[tm][0], aH[tm][1], aH[tm][2], aH[tm][3],
                         bH[tn][0], bH[tn][1]);
                mma16816(c[0], c[1], c[2], c[3],
                         aH[tm][0], aH[tm][1], aH[tm][2], aH[tm][3],
                         bL[tn][0], bL[tn][1]);
                mma16816(c[0], c[1], c[2], c[3],
                         aL[tm][0], aL[tm][1], aL[tm][2], aL[tm][3],
                         bH[tn][0], bH[tn][1]);
            }

        if (kk + 1 < kt) {
            store((kk + 1) & 1);
            __syncthreads();
        }
    }

    /* ---- epilogue: alpha, bias, gelu, residual, store fp32 ---- */
    #pragma unroll
    for (int tn = 0; tn < 4; tn++) {
        int col = n0 + warp_n + tn * 8 + tig * 2;
        if (col >= N) continue;
        float b0 = bias ? bias[col]     : 0.0f;
        float b1 = bias ? bias[col + 1] : 0.0f;
        #pragma unroll
        for (int tm = 0; tm < 4; tm++) {
            int row0 = m0 + warp_m + tm * 16 + gid;
            float* c = acc[tm][tn];
            #pragma unroll
            for (int half = 0; half < 2; half++) {
                int row = row0 + half * 8;
                float v0 = c[half*2 + 0] * alpha + b0;
                float v1 = c[half*2 + 1] * alpha + b1;
                if (doGelu) { v0 = gelu_tanh(v0); v1 = gelu_tanh(v1); }
                long off = (long)row * ldc + col;
                if (Rsd) {
                    float2 r = *reinterpret_cast<const float2*>(Rsd + off);
                    v0 += r.x; v1 += r.y;
                }
                *reinterpret_cast<float2*>(Cb + off) = make_float2(v0, v1);
            }
        }
    }
}

/* ---------------- launch --------------------------------------------------- */
extern "C" void kernel_launch(void* const* d_in, const int* in_sizes, int n_in,
                              void* d_out, int out_size)
{
    const float* x     = (const float*)d_in[0];
    const float* ln1s  = (const float*)d_in[1];
    const float* ln1b  = (const float*)d_in[2];
    const float* qkvw  = (const float*)d_in[3];
    const float* qkvb  = (const float*)d_in[4];
    const float* projw = (const float*)d_in[5];
    const float* projb = (const float*)d_in[6];
    const float* ln2s  = (const float*)d_in[7];
    const float* ln2b  = (const float*)d_in[8];
    const float* fc1w  = (const float*)d_in[9];
    const float* fc1b  = (const float*)d_in[10];
    const float* fc2w  = (const float*)d_in[11];
    const float* fc2b  = (const float*)d_in[12];
    float* out = (float*)d_out;

    float *y, *qkv, *sc, *att, *x1, *hb;
    cudaGetSymbolAddress((void**)&y,   g_y);
    cudaGetSymbolAddress((void**)&qkv, g_qkv);
    cudaGetSymbolAddress((void**)&sc,  g_sc);
    cudaGetSymbolAddress((void**)&att, g_att);
    cudaGetSymbolAddress((void**)&x1,  g_x1);
    cudaGetSymbolAddress((void**)&hb,  g_h);

    /* 1. LN1 */
    ln_kernel<<<ROWS, 256>>>(x, ln1s, ln1b, y);

    /* 2. QKV: [8192,768] @ [768,2304] + b */
    gemm_tc<0><<<dim3(18, 64, 1), 256>>>(
        y, qkvw, qkvb, nullptr, qkv,
        ROWS, 3 * DIM, DIM, DIM, 3 * DIM, 3 * DIM,
        0, 0, 0, 0, 0, 0, 1.0f, 0);

    /* 3. scores[b,h] = Q @ K^T * 0.125 */
    gemm_tc<1><<<dim3(8, 8, BATCH * HEADS), 256>>>(
        qkv, qkv + DIM, nullptr, nullptr, sc,
        SEQ, SEQ, HD, 3 * DIM, 3 * DIM, SEQ,
        (long)SEQ * 3 * DIM, HD, (long)SEQ * 3 * DIM, HD,
        (long)HEADS * SEQ * SEQ, (long)SEQ * SEQ,
        0.125f, 0);

    /* 4. softmax */
    softmax_kernel<<<BATCH * HEADS * SEQ, 256>>>(sc);

    /* 5. O[b,h] = P @ V */
    gemm_tc<0><<<dim3(1, 8, BATCH * HEADS), 256>>>(
        sc, qkv + 2 * DIM, nullptr, nullptr, att,
        SEQ, HD, SEQ, SEQ, 3 * DIM, DIM,
        (long)HEADS * SEQ * SEQ, (long)SEQ * SEQ,
        (long)SEQ * 3 * DIM, HD,
        (long)SEQ * DIM, HD,
        1.0f, 0);

    /* 6. proj + residual */
    gemm_tc<0><<<dim3(6, 64, 1), 256>>>(
        att, projw, projb, x, x1,
        ROWS, DIM, DIM, DIM, DIM, DIM,
        0, 0, 0, 0, 0, 0, 1.0f, 0);

    /* 7. LN2 */
    ln_kernel<<<ROWS, 256>>>(x1, ln2s, ln2b, y);

    /* 8. fc1 + gelu */
    gemm_tc<0><<<dim3(24, 64, 1), 256>>>(
        y, fc1w, fc1b, nullptr, hb,
        ROWS, HIDDEN, DIM, DIM, HIDDEN, HIDDEN,
        0, 0, 0, 0, 0, 0, 1.0f, 1);

    /* 9. fc2 + residual -> out */
    gemm_tc<0><<<dim3(6, 64, 1), 256>>>(
        hb, fc2w, fc2b, x1, out,
        ROWS, DIM, HIDDEN, HIDDEN, DIM, DIM,
        0, 0, 0, 0, 0, 0, 1.0f, 0);
}

// round 3
// speedup vs baseline: 2.1141x; 1.1829x over previous
#include <cuda_runtime.h>
#include <cuda_bf16.h>
#include <cstdint>

#define DIM    768
#define SEQ    1024
#define BATCH  8
#define ROWS   (BATCH*SEQ)      /* 8192 */
#define HEADS  12
#define HD     64
#define HIDDEN 3072
#define LN_EPS 1e-6f

/* ---------------- scratch (static device globals; no allocations) -------- */
__device__ float g_y  [ROWS * DIM];
__device__ float g_qkv[ROWS * 3 * DIM];
__device__ float g_att[ROWS * DIM];
__device__ float g_x1 [ROWS * DIM];
__device__ float g_h  [ROWS * HIDDEN];

/* ---------------- layernorm ------------------------------------------------ */
__global__ void __launch_bounds__(256) ln_kernel(
    const float* __restrict__ x, const float* __restrict__ sc,
    const float* __restrict__ bi, float* __restrict__ y)
{
    long row = blockIdx.x;
    int  t   = threadIdx.x;
    const float* xr = x + row * DIM;
    float v0 = xr[t], v1 = xr[t + 256], v2 = xr[t + 512];

    __shared__ float sbuf[8];
    __shared__ float s_mu, s_r;

    float s = v0 + v1 + v2;
    #pragma unroll
    for (int o = 16; o > 0; o >>= 1) s += __shfl_xor_sync(0xffffffffu, s, o);
    if ((t & 31) == 0) sbuf[t >> 5] = s;
    __syncthreads();
    if (t < 8) {
        float r = sbuf[t];
        #pragma unroll
        for (int o = 4; o > 0; o >>= 1) r += __shfl_xor_sync(0xffu, r, o);
        if (t == 0) s_mu = r * (1.0f / DIM);
    }
    __syncthreads();
    float mu = s_mu;
    float d0 = v0 - mu, d1 = v1 - mu, d2 = v2 - mu;
    float q = d0*d0 + d1*d1 + d2*d2;
    #pragma unroll
    for (int o = 16; o > 0; o >>= 1) q += __shfl_xor_sync(0xffffffffu, q, o);
    if ((t & 31) == 0) sbuf[t >> 5] = q;
    __syncthreads();
    if (t < 8) {
        float r = sbuf[t];
        #pragma unroll
        for (int o = 4; o > 0; o >>= 1) r += __shfl_xor_sync(0xffu, r, o);
        if (t == 0) s_r = rsqrtf(r * (1.0f / DIM) + LN_EPS);
    }
    __syncthreads();
    float rs = s_r;
    float* yr = y + row * DIM;
    yr[t      ] = d0 * rs * sc[t      ] + bi[t      ];
    yr[t + 256] = d1 * rs * sc[t + 256] + bi[t + 256];
    yr[t + 512] = d2 * rs * sc[t + 512] + bi[t + 512];
}

/* ---------------- common helpers ------------------------------------------ */
__device__ __forceinline__ float gelu_tanh(float u)
{
    return 0.5f * u * (1.0f + tanhf(0.7978845608028654f * (u + 0.044715f * u * u * u)));
}

__device__ __forceinline__ void mma16816(
    float& c0, float& c1, float& c2, float& c3,
    uint32_t a0, uint32_t a1, uint32_t a2, uint32_t a3,
    uint32_t b0, uint32_t b1)
{
    asm volatile(
        "mma.sync.aligned.m16n8k16.row.col.f32.bf16.bf16.f32 "
        "{%0,%1,%2,%3},{%4,%5,%6,%7},{%8,%9},{%0,%1,%2,%3};"
        : "+f"(c0), "+f"(c1), "+f"(c2), "+f"(c3)
        : "r"(a0), "r"(a1), "r"(a2), "r"(a3), "r"(b0), "r"(b1));
}

/* split two fp32 into packed bf16x2 hi and lo */
__device__ __forceinline__ void pack_hl(float x0, float x1, uint32_t& hi, uint32_t& lo)
{
    __nv_bfloat16 h0 = __float2bfloat16(x0);
    __nv_bfloat16 h1 = __float2bfloat16(x1);
    float r0 = x0 - __bfloat162float(h0);
    float r1 = x1 - __bfloat162float(h1);
    __nv_bfloat16 l0 = __float2bfloat16(r0);
    __nv_bfloat16 l1 = __float2bfloat16(r1);
    hi = ((uint32_t)__bfloat16_as_ushort(h1) << 16) | __bfloat16_as_ushort(h0);
    lo = ((uint32_t)__bfloat16_as_ushort(l1) << 16) | __bfloat16_as_ushort(l0);
}

/* split 8 fp32 into hi/lo bf16 uint4s */
__device__ __forceinline__ void cvt8(const float* f, uint4& hi4, uint4& lo4)
{
    uint32_t h[4], l[4];
    #pragma unroll
    for (int i = 0; i < 4; i++) pack_hl(f[2*i], f[2*i+1], h[i], l[i]);
    hi4 = make_uint4(h[0], h[1], h[2], h[3]);
    lo4 = make_uint4(l[0], l[1], l[2], l[3]);
}

/* ================= flash attention =========================================
 * Block: 128 q rows of one (b,h). 4 warps, each warp m=32 (2 m16 tiles),
 * full kv tile n=64. 16 KV iterations of 64 rows. Online softmax.
 * Q pre-scaled by 0.125; hi/lo bf16 in smem. V stored transposed [d][kv].
 */
#define BQ  128
#define BKV 64
#define QST 72                      /* smem row stride in bf16 elems */
#define SQ_ELE (BQ*QST)             /* 9216  */
#define SK_ELE (BKV*QST)            /* 4608  */
#define FA_SMEM ((2*SQ_ELE + 4*SK_ELE) * 2)  /* 73728 bytes */

__global__ void __launch_bounds__(128) flash_kernel(
    const float* __restrict__ qkv, float* __restrict__ att)
{
    extern __shared__ __nv_bfloat16 sm[];
    __nv_bfloat16* QsH = sm;
    __nv_bfloat16* QsL = QsH + SQ_ELE;
    __nv_bfloat16* KsH = QsL + SQ_ELE;
    __nv_bfloat16* KsL = KsH + SK_ELE;
    __nv_bfloat16* VsH = KsL + SK_ELE;
    __nv_bfloat16* VsL = VsH + SK_ELE;
    uint32_t* VWH = reinterpret_cast<uint32_t*>(VsH);
    uint32_t* VWL = reinterpret_cast<uint32_t*>(VsL);

    int t = threadIdx.x, lane = t & 31, wid = t >> 5;
    int gid = lane >> 2, tig = lane & 3;
    int bh = blockIdx.y, b = bh / HEADS, h = bh % HEADS;
    int q0 = blockIdx.x * BQ;

    const float* Qp = qkv + ((long)b * SEQ + q0) * (3*DIM) + h * HD;
    const float* Kp = qkv + (long)b * SEQ * (3*DIM) + DIM     + h * HD;
    const float* Vp = qkv + (long)b * SEQ * (3*DIM) + 2*DIM   + h * HD;

    /* ---- Q preload: one row per thread, scaled ---- */
    {
        const float* qr = Qp + (long)t * (3*DIM);
        #pragma unroll
        for (int c = 0; c < HD; c += 8) {
            float4 u0 = *reinterpret_cast<const float4*>(qr + c);
            float4 u1 = *reinterpret_cast<const float4*>(qr + c + 4);
            float f[8] = {u0.x*0.125f, u0.y*0.125f, u0.z*0.125f, u0.w*0.125f,
                          u1.x*0.125f, u1.y*0.125f, u1.z*0.125f, u1.w*0.125f};
            uint4 h4, l4; cvt8(f, h4, l4);
            *reinterpret_cast<uint4*>(&QsH[t*QST + c]) = h4;
            *reinterpret_cast<uint4*>(&QsL[t*QST + c]) = l4;
        }
    }

    /* ---- per-thread state ---- */
    float acc[2][8][4];                  /* S / P values */
    float oacc[2][8][4];                 /* O accumulator */
    float mrow[2][2], lrow[2][2];
    #pragma unroll
    for (int i = 0; i < 2; i++) {
        mrow[i][0] = mrow[i][1] = -1e30f;
        lrow[i][0] = lrow[i][1] = 0.0f;
        #pragma unroll
        for (int j = 0; j < 8; j++)
            #pragma unroll
            for (int r = 0; r < 4; r++) oacc[i][j][r] = 0.0f;
    }

    int wm = wid * 32;

    /* K loader: row kr, cols kh..kh+31 */
    int kr = t >> 1, kh = (t & 1) * 32;
    float kreg[32];
    /* V loader: rows 2vrp,2vrp+1, cols vdb..vdb+15 */
    int vrp = t & 31, vdb = (t >> 5) * 16;
    float vreg[32];

    auto loadK = [&](int it) {
        const float* p = Kp + (long)(it * BKV + kr) * (3*DIM) + kh;
        #pragma unroll
        for (int i = 0; i < 8; i++) {
            float4 v = *reinterpret_cast<const float4*>(p + i*4);
            kreg[i*4] = v.x; kreg[i*4+1] = v.y; kreg[i*4+2] = v.z; kreg[i*4+3] = v.w;
        }
    };
    auto loadV = [&](int it) {
        const float* p0 = Vp + (long)(it * BKV + 2*vrp) * (3*DIM) + vdb;
        const float* p1 = p0 + 3*DIM;
        #pragma unroll
        for (int i = 0; i < 4; i++) {
            float4 a = *reinterpret_cast<const float4*>(p0 + i*4);
            float4 c = *reinterpret_cast<const float4*>(p1 + i*4);
            vreg[i*4] = a.x; vreg[i*4+1] = a.y; vreg[i*4+2] = a.z; vreg[i*4+3] = a.w;
            vreg[16+i*4] = c.x; vreg[16+i*4+1] = c.y; vreg[16+i*4+2] = c.z; vreg[16+i*4+3] = c.w;
        }
    };

    loadK(0);

    for (int it = 0; it < SEQ / BKV; it++) {
        __syncthreads();            /* smem free from previous iteration */
        /* store K tile */
        #pragma unroll
        for (int i = 0; i < 4; i++) {
            uint4 h4, l4; cvt8(kreg + i*8, h4, l4);
            *reinterpret_cast<uint4*>(&KsH[kr*QST + kh + i*8]) = h4;
            *reinterpret_cast<uint4*>(&KsL[kr*QST + kh + i*8]) = l4;
        }
        loadV(it);                  /* in flight during S phase */
        __syncthreads();

        /* ---- S = Q K^T ---- */
        #pragma unroll
        for (int i = 0; i < 2; i++)
            #pragma unroll
            for (int j = 0; j < 8; j++)
                #pragma unroll
                for (int r = 0; r < 4; r++) acc[i][j][r] = 0.0f;

        #pragma unroll
        for (int ks = 0; ks < 4; ks++) {
            uint32_t qh[2][4], ql[2][4];
            #pragma unroll
            for (int tm = 0; tm < 2; tm++) {
                int row = wm + tm*16 + gid;
                qh[tm][0] = *reinterpret_cast<const uint32_t*>(&QsH[ row    *QST + ks*16 + tig*2    ]);
                qh[tm][1] = *reinterpret_cast<const uint32_t*>(&QsH[(row+8)*QST + ks*16 + tig*2    ]);
                qh[tm][2] = *reinterpret_cast<const uint32_t*>(&QsH[ row    *QST + ks*16 + tig*2 + 8]);
                qh[tm][3] = *reinterpret_cast<const uint32_t*>(&QsH[(row+8)*QST + ks*16 + tig*2 + 8]);
                ql[tm][0] = *reinterpret_cast<const uint32_t*>(&QsL[ row    *QST + ks*16 + tig*2    ]);
                ql[tm][1] = *reinterpret_cast<const uint32_t*>(&QsL[(row+8)*QST + ks*16 + tig*2    ]);
                ql[tm][2] = *reinterpret_cast<const uint32_t*>(&QsL[ row    *QST + ks*16 + tig*2 + 8]);
                ql[tm][3] = *reinterpret_cast<const uint32_t*>(&QsL[(row+8)*QST + ks*16 + tig*2 + 8]);
            }
            #pragma unroll
            for (int tn = 0; tn < 8; tn++) {
                int nr = tn*8 + gid;
                uint32_t bh0 = *reinterpret_cast<const uint32_t*>(&KsH[nr*QST + ks*16 + tig*2    ]);
                uint32_t bh1 = *reinterpret_cast<const uint32_t*>(&KsH[nr*QST + ks*16 + tig*2 + 8]);
                uint32_t bl0 = *reinterpret_cast<const uint32_t*>(&KsL[nr*QST + ks*16 + tig*2    ]);
                uint32_t bl1 = *reinterpret_cast<const uint32_t*>(&KsL[nr*QST + ks*16 + tig*2 + 8]);
                #pragma unroll
                for (int tm = 0; tm < 2; tm++) {
                    float* c = acc[tm][tn];
                    mma16816(c[0],c[1],c[2],c[3], qh[tm][0],qh[tm][1],qh[tm][2],qh[tm][3], bh0,bh1);
                    mma16816(c[0],c[1],c[2],c[3], qh[tm][0],qh[tm][1],qh[tm][2],qh[tm][3], bl0,bl1);
                    mma16816(c[0],c[1],c[2],c[3], ql[tm][0],ql[tm][1],ql[tm][2],ql[tm][3], bh0,bh1);
                }
            }
        }

        /* ---- online softmax update ---- */
        #pragma unroll
        for (int tm = 0; tm < 2; tm++) {
            float mx0 = -1e30f, mx1 = -1e30f;
            #pragma unroll
            for (int tn = 0; tn < 8; tn++) {
                mx0 = fmaxf(mx0, fmaxf(acc[tm][tn][0], acc[tm][tn][1]));
                mx1 = fmaxf(mx1, fmaxf(acc[tm][tn][2], acc[tm][tn][3]));
            }
            #pragma unroll
            for (int o = 1; o <= 2; o <<= 1) {
                mx0 = fmaxf(mx0, __shfl_xor_sync(0xffffffffu, mx0, o));
                mx1 = fmaxf(mx1, __shfl_xor_sync(0xffffffffu, mx1, o));
            }
            float mn0 = fmaxf(mrow[tm][0], mx0);
            float mn1 = fmaxf(mrow[tm][1], mx1);
            float sc0 = __expf(mrow[tm][0] - mn0);
            float sc1 = __expf(mrow[tm][1] - mn1);
            float ls0 = 0.0f, ls1 = 0.0f;
            #pragma unroll
            for (int tn = 0; tn < 8; tn++) {
                float* c = acc[tm][tn];
                c[0] = __expf(c[0] - mn0);
                c[1] = __expf(c[1] - mn0);
                c[2] = __expf(c[2] - mn1);
                c[3] = __expf(c[3] - mn1);
                ls0 += c[0] + c[1];
                ls1 += c[2] + c[3];
            }
            #pragma unroll
            for (int o = 1; o <= 2; o <<= 1) {
                ls0 += __shfl_xor_sync(0xffffffffu, ls0, o);
                ls1 += __shfl_xor_sync(0xffffffffu, ls1, o);
            }
            lrow[tm][0] = lrow[tm][0] * sc0 + ls0;
            lrow[tm][1] = lrow[tm][1] * sc1 + ls1;
            mrow[tm][0] = mn0;
            mrow[tm][1] = mn1;
            #pragma unroll
            for (int to = 0; to < 8; to++) {
                oacc[tm][to][0] *= sc0; oacc[tm][to][1] *= sc0;
                oacc[tm][to][2] *= sc1; oacc[tm][to][3] *= sc1;
            }
        }

        /* store V tile (transposed, pair-packed -> conflict-free) */
        #pragma unroll
        for (int j = 0; j < 16; j++) {
            uint32_t hw, lw;
            pack_hl(vreg[j], vreg[16 + j], hw, lw);
            VWH[(vdb + j) * (QST/2) + vrp] = hw;
            VWL[(vdb + j) * (QST/2) + vrp] = lw;
        }
        if (it + 1 < SEQ / BKV) loadK(it + 1);   /* in flight during PV */
        __syncthreads();

        /* ---- O += P V ---- */
        #pragma unroll
        for (int j = 0; j < 4; j++) {
            uint32_t pH[2][4], pL[2][4];
            #pragma unroll
            for (int tm = 0; tm < 2; tm++) {
                pack_hl(acc[tm][2*j  ][0], acc[tm][2*j  ][1], pH[tm][0], pL[tm][0]);
                pack_hl(acc[tm][2*j  ][2], acc[tm][2*j  ][3], pH[tm][1], pL[tm][1]);
                pack_hl(acc[tm][2*j+1][0], acc[tm][2*j+1][1], pH[tm][2], pL[tm][2]);
                pack_hl(acc[tm][2*j+1][2], acc[tm][2*j+1][3], pH[tm][3], pL[tm][3]);
            }
            #pragma unroll
            for (int to = 0; to < 8; to++) {
                int d = to*8 + gid;
                uint32_t bh0 = *reinterpret_cast<const uint32_t*>(&VsH[d*QST + j*16 + tig*2    ]);
                uint32_t bh1 = *reinterpret_cast<const uint32_t*>(&VsH[d*QST + j*16 + tig*2 + 8]);
                uint32_t bl0 = *reinterpret_cast<const uint32_t*>(&VsL[d*QST + j*16 + tig*2    ]);
                uint32_t bl1 = *reinterpret_cast<const uint32_t*>(&VsL[d*QST + j*16 + tig*2 + 8]);
                #pragma unroll
                for (int tm = 0; tm < 2; tm++) {
                    float* c = oacc[tm][to];
                    mma16816(c[0],c[1],c[2],c[3], pH[tm][0],pH[tm][1],pH[tm][2],pH[tm][3], bh0,bh1);
                    mma16816(c[0],c[1],c[2],c[3], pH[tm][0],pH[tm][1],pH[tm][2],pH[tm][3], bl0,bl1);
                    mma16816(c[0],c[1],c[2],c[3], pL[tm][0],pL[tm][1],pL[tm][2],pL[tm][3], bh0,bh1);
                }
            }
        }
    }

    /* ---- epilogue: O / l -> att ---- */
    #pragma unroll
    for (int tm = 0; tm < 2; tm++) {
        float inv0 = 1.0f / lrow[tm][0];
        float inv1 = 1.0f / lrow[tm][1];
        int row = q0 + wm + tm*16 + gid;
        #pragma unroll
        for (int to = 0; to < 8; to++) {
            int col = h*HD + to*8 + tig*2;
            float* c = oacc[tm][to];
            long o0 = ((long)b*SEQ + row    ) * DIM + col;
            long o1 = ((long)b*SEQ + row + 8) * DIM + col;
            *reinterpret_cast<float2*>(att + o0) = make_float2(c[0]*inv0, c[1]*inv0);
            *reinterpret_cast<float2*>(att + o1) = make_float2(c[2]*inv1, c[3]*inv1);
        }
    }
}

/* ================= dense tensor-core GEMM (unchanged from R2) ============== */
#define BM 128
#define BN 128
#define BK 16
#define SE 24

template <int TRANSB>
__global__ void __launch_bounds__(256) gemm_tc(
    const float* __restrict__ A, const float* __restrict__ B,
    const float* __restrict__ bias, const float* __restrict__ Rsd,
    float* __restrict__ C,
    int M, int N, int K, int lda, int ldb, int ldc,
    float alpha, int doGelu)
{
    __shared__ __nv_bfloat16 AsH[2][BM][SE];
    __shared__ __nv_bfloat16 AsL[2][BM][SE];
    __shared__ __nv_bfloat16 BsH[2][BN][SE];
    __shared__ __nv_bfloat16 BsL[2][BN][SE];

    int m0 = blockIdx.y * BM;
    int n0 = blockIdx.x * BN;
    int t  = threadIdx.x;
    int lane = t & 31, wid = t >> 5;
    int gid = lane >> 2, tig = lane & 3;
    int warp_m = (wid >> 2) << 6;
    int warp_n = (wid & 3) << 5;

    int lrow = t >> 1;
    int lcol = (t & 1) * 8;

    float acc[4][4][4];
    #pragma unroll
    for (int i = 0; i < 4; i++)
        #pragma unroll
        for (int j = 0; j < 4; j++)
            #pragma unroll
            for (int r = 0; r < 4; r++) acc[i][j][r] = 0.0f;

    float fa[8], fb[8];
    int kt = K / BK;

    auto fetch = [&](int kk) {
        int k0 = kk * BK;
        float4 a0 = *reinterpret_cast<const float4*>(A + (long)(m0 + lrow) * lda + k0 + lcol);
        float4 a1 = *reinterpret_cast<const float4*>(A + (long)(m0 + lrow) * lda + k0 + lcol + 4);
        fa[0]=a0.x; fa[1]=a0.y; fa[2]=a0.z; fa[3]=a0.w;
        fa[4]=a1.x; fa[5]=a1.y; fa[6]=a1.z; fa[7]=a1.w;
        if (TRANSB) {
            float4 b0 = *reinterpret_cast<const float4*>(B + (long)(n0 + lrow) * ldb + k0 + lcol);
            float4 b1 = *reinterpret_cast<const float4*>(B + (long)(n0 + lrow) * ldb + k0 + lcol + 4);
            fb[0]=b0.x; fb[1]=b0.y; fb[2]=b0.z; fb[3]=b0.w;
            fb[4]=b1.x; fb[5]=b1.y; fb[6]=b1.z; fb[7]=b1.w;
        } else {
            #pragma unroll
            for (int i = 0; i < 8; i++)
                fb[i] = B[(long)(k0 + lcol + i) * ldb + n0 + lrow];
        }
    };
    auto store = [&](int nb) {
        uint4 h4, l4;
        cvt8(fa, h4, l4);
        *reinterpret_cast<uint4*>(&AsH[nb][lrow][lcol]) = h4;
        *reinterpret_cast<uint4*>(&AsL[nb][lrow][lcol]) = l4;
        cvt8(fb, h4, l4);
        *reinterpret_cast<uint4*>(&BsH[nb][lrow][lcol]) = h4;
        *reinterpret_cast<uint4*>(&BsL[nb][lrow][lcol]) = l4;
    };

    fetch(0);
    store(0);
    __syncthreads();

    for (int kk = 0; kk < kt; kk++) {
        int cur = kk & 1;
        if (kk + 1 < kt) fetch(kk + 1);

        uint32_t aH[4][4], aL[4][4], bH[4][2], bL[4][2];
        #pragma unroll
        for (int tm = 0; tm < 4; tm++) {
            int ar = warp_m + tm * 16 + gid;
            aH[tm][0] = *reinterpret_cast<const uint32_t*>(&AsH[cur][ar    ][tig*2    ]);
            aH[tm][1] = *reinterpret_cast<const uint32_t*>(&AsH[cur][ar + 8][tig*2    ]);
            aH[tm][2] = *reinterpret_cast<const uint32_t*>(&AsH[cur][ar    ][tig*2 + 8]);
            aH[tm][3] = *reinterpret_cast<const uint32_t*>(&AsH[cur][ar + 8][tig*2 + 8]);
            aL[tm][0] = *reinterpret_cast<const uint32_t*>(&AsL[cur][ar    ][tig*2    ]);
            aL[tm][1] = *reinterpret_cast<const uint32_t*>(&AsL[cur][ar + 8][tig*2    ]);
            aL[tm][2] = *reinterpret_cast<const uint32_t*>(&AsL[cur][ar    ][tig*2 + 8]);
            aL[tm][3] = *reinterpret_cast<const uint32_t*>(&AsL[cur][ar + 8][tig*2 + 8]);
        }
        #pragma unroll
        for (int tn = 0; tn < 4; tn++) {
            int br = warp_n + tn * 8 + gid;
            bH[tn][0] = *reinterpret_cast<const uint32_t*>(&BsH[cur][br][tig*2    ]);
            bH[tn][1] = *reinterpret_cast<const uint32_t*>(&BsH[cur][br][tig*2 + 8]);
            bL[tn][0] = *reinterpret_cast<const uint32_t*>(&BsL[cur][br][tig*2    ]);
            bL[tn][1] = *reinterpret_cast<const uint32_t*>(&BsL[cur][br][tig*2 + 8]);
        }

        #pragma unroll
        for (int tm = 0; tm < 4; tm++)
            #pragma unroll
            for (int tn = 0; tn < 4; tn++) {
                float* c = acc[tm][tn];
                mma16816(c[0], c[1], c[2], c[3],
                         aH[tm][0], aH[tm][1], aH[tm][2], aH[tm][3],
                         bH[tn][0], bH[tn][1]);
                mma16816(c[0], c[1], c[2], c[3],
                         aH[tm][0], aH[tm][1], aH[tm][2], aH[tm][3],
                         bL[tn][0], bL[tn][1]);
                mma16816(c[0], c[1], c[2], c[3],
                         aL[tm][0], aL[tm][1], aL[tm][2], aL[tm][3],
                         bH[tn][0], bH[tn][1]);
            }

        if (kk + 1 < kt) {
            store((kk + 1) & 1);
            __syncthreads();
        }
    }

    #pragma unroll
    for (int tn = 0; tn < 4; tn++) {
        int col = n0 + warp_n + tn * 8 + tig * 2;
        float b0 = bias ? bias[col]     : 0.0f;
        float b1 = bias ? bias[col + 1] : 0.0f;
        #pragma unroll
        for (int tm = 0; tm < 4; tm++) {
            int row0 = m0 + warp_m + tm * 16 + gid;
            float* c = acc[tm][tn];
            #pragma unroll
            for (int half = 0; half < 2; half++) {
                int row = row0 + half * 8;
                float v0 = c[half*2 + 0] * alpha + b0;
                float v1 = c[half*2 + 1] * alpha + b1;
                if (doGelu) { v0 = gelu_tanh(v0); v1 = gelu_tanh(v1); }
                long off = (long)row * ldc + col;
                if (Rsd) {
                    float2 r = *reinterpret_cast<const float2*>(Rsd + off);
                    v0 += r.x; v1 += r.y;
                }
                *reinterpret_cast<float2*>(C + off) = make_float2(v0, v1);
            }
        }
    }
}

/* ---------------- launch --------------------------------------------------- */
extern "C" void kernel_launch(void* const* d_in, const int* in_sizes, int n_in,
                              void* d_out, int out_size)
{
    const float* x     = (const float*)d_in[0];
    const float* ln1s  = (const float*)d_in[1];
    const float* ln1b  = (const float*)d_in[2];
    const float* qkvw  = (const float*)d_in[3];
    const float* qkvb  = (const float*)d_in[4];
    const float* projw = (const float*)d_in[5];
    const float* projb = (const float*)d_in[6];
    const float* ln2s  = (const float*)d_in[7];
    const float* ln2b  = (const float*)d_in[8];
    const float* fc1w  = (const float*)d_in[9];
    const float* fc1b  = (const float*)d_in[10];
    const float* fc2w  = (const float*)d_in[11];
    const float* fc2b  = (const float*)d_in[12];
    float* out = (float*)d_out;

    float *y, *qkv, *att, *x1, *hb;
    cudaGetSymbolAddress((void**)&y,   g_y);
    cudaGetSymbolAddress((void**)&qkv, g_qkv);
    cudaGetSymbolAddress((void**)&att, g_att);
    cudaGetSymbolAddress((void**)&x1,  g_x1);
    cudaGetSymbolAddress((void**)&hb,  g_h);

    cudaFuncSetAttribute(flash_kernel,
        cudaFuncAttributeMaxDynamicSharedMemorySize, FA_SMEM);

    /* 1. LN1 */
    ln_kernel<<<ROWS, 256>>>(x, ln1s, ln1b, y);

    /* 2. QKV */
    gemm_tc<0><<<dim3(18, 64, 1), 256>>>(
        y, qkvw, qkvb, nullptr, qkv,
        ROWS, 3 * DIM, DIM, DIM, 3 * DIM, 3 * DIM, 1.0f, 0);

    /* 3-5. fused flash attention */
    flash_kernel<<<dim3(SEQ / BQ, BATCH * HEADS), 128, FA_SMEM>>>(qkv, att);

    /* 6. proj + residual */
    gemm_tc<0><<<dim3(6, 64, 1), 256>>>(
        att, projw, projb, x, x1,
        ROWS, DIM, DIM, DIM, DIM, DIM, 1.0f, 0);

    /* 7. LN2 */
    ln_kernel<<<ROWS, 256>>>(x1, ln2s, ln2b, y);

    /* 8. fc1 + gelu */
    gemm_tc<0><<<dim3(24, 64, 1), 256>>>(
        y, fc1w, fc1b, nullptr, hb,
        ROWS, HIDDEN, DIM, DIM, HIDDEN, HIDDEN, 1.0f, 1);

    /* 9. fc2 + residual -> out */
    gemm_tc<0><<<dim3(6, 64, 1), 256>>>(
        hb, fc2w, fc2b, x1, out,
        ROWS, DIM, HIDDEN, HIDDEN, DIM, DIM, 1.0f, 0);
}

// round 4
// speedup vs baseline: 3.1855x; 1.5068x over previous
#include <cuda_runtime.h>
#include <cuda_bf16.h>
#include <cstdint>

#define DIM    768
#define SEQ    1024
#define BATCH  8
#define ROWS   (BATCH*SEQ)      /* 8192 */
#define HEADS  12
#define HD     64
#define HIDDEN 3072
#define LN_EPS 1e-6f

typedef __nv_bfloat16 bf16;

/* ---------------- scratch (static device globals; no allocations) -------- */
__device__ bf16  g_yh [ROWS * DIM];
__device__ bf16  g_yl [ROWS * DIM];
__device__ float g_qkv[ROWS * 3 * DIM];
__device__ bf16  g_ath[ROWS * DIM];
__device__ bf16  g_atl[ROWS * DIM];
__device__ float g_x1 [ROWS * DIM];
__device__ bf16  g_hh [ROWS * HIDDEN];
__device__ bf16  g_hl [ROWS * HIDDEN];
/* transposed hi/lo weights, [N][K] */
__device__ bf16  g_wqh[3*DIM*DIM], g_wql[3*DIM*DIM];
__device__ bf16  g_wph[DIM*DIM],   g_wpl[DIM*DIM];
__device__ bf16  g_w1h[HIDDEN*DIM], g_w1l[HIDDEN*DIM];
__device__ bf16  g_w2h[DIM*HIDDEN], g_w2l[DIM*HIDDEN];

/* ---------------- helpers -------------------------------------------------- */
__device__ __forceinline__ float gelu_tanh(float u)
{
    return 0.5f * u * (1.0f + tanhf(0.7978845608028654f * (u + 0.044715f * u * u * u)));
}

__device__ __forceinline__ void mma16816(
    float& c0, float& c1, float& c2, float& c3,
    uint32_t a0, uint32_t a1, uint32_t a2, uint32_t a3,
    uint32_t b0, uint32_t b1)
{
    asm volatile(
        "mma.sync.aligned.m16n8k16.row.col.f32.bf16.bf16.f32 "
        "{%0,%1,%2,%3},{%4,%5,%6,%7},{%8,%9},{%0,%1,%2,%3};"
        : "+f"(c0), "+f"(c1), "+f"(c2), "+f"(c3)
        : "r"(a0), "r"(a1), "r"(a2), "r"(a3), "r"(b0), "r"(b1));
}

__device__ __forceinline__ void pack_hl(float x0, float x1, uint32_t& hi, uint32_t& lo)
{
    bf16 h0 = __float2bfloat16(x0);
    bf16 h1 = __float2bfloat16(x1);
    float r0 = x0 - __bfloat162float(h0);
    float r1 = x1 - __bfloat162float(h1);
    bf16 l0 = __float2bfloat16(r0);
    bf16 l1 = __float2bfloat16(r1);
    hi = ((uint32_t)__bfloat16_as_ushort(h1) << 16) | __bfloat16_as_ushort(h0);
    lo = ((uint32_t)__bfloat16_as_ushort(l1) << 16) | __bfloat16_as_ushort(l0);
}

__device__ __forceinline__ void split1(float x, bf16& h, bf16& l)
{
    h = __float2bfloat16(x);
    l = __float2bfloat16(x - __bfloat162float(h));
}

__device__ __forceinline__ void cvt8(const float* f, uint4& hi4, uint4& lo4)
{
    uint32_t h[4], l[4];
    #pragma unroll
    for (int i = 0; i < 4; i++) pack_hl(f[2*i], f[2*i+1], h[i], l[i]);
    hi4 = make_uint4(h[0], h[1], h[2], h[3]);
    lo4 = make_uint4(l[0], l[1], l[2], l[3]);
}

__device__ __forceinline__ void cp16(uint32_t s, const void* g)
{
    asm volatile("cp.async.cg.shared.global [%0], [%1], 16;" :: "r"(s), "l"(g));
}
__device__ __forceinline__ void ldm_x4(uint32_t* r, uint32_t addr)
{
    asm volatile("ldmatrix.sync.aligned.m8n8.x4.shared.b16 {%0,%1,%2,%3}, [%4];"
        : "=r"(r[0]), "=r"(r[1]), "=r"(r[2]), "=r"(r[3]) : "r"(addr));
}

/* ---------------- weight transpose + split: W[K][N] -> Th/Tl[N][K] -------- */
__global__ void __launch_bounds__(256) wt_kernel(
    const float* __restrict__ W, bf16* __restrict__ Th, bf16* __restrict__ Tl,
    int K, int N)
{
    __shared__ float s[32][33];
    int tx = threadIdx.x, ty = threadIdx.y;
    int n0 = blockIdx.x * 32, k0 = blockIdx.y * 32;
    #pragma unroll
    for (int j = 0; j < 4; j++)
        s[ty + j*8][tx] = W[(long)(k0 + ty + j*8) * N + n0 + tx];
    __syncthreads();
    #pragma unroll
    for (int j = 0; j < 4; j++) {
        float v = s[tx][ty + j*8];
        bf16 h, l; split1(v, h, l);
        long o = (long)(n0 + ty + j*8) * K + k0 + tx;
        Th[o] = h; Tl[o] = l;
    }
}

/* ---------------- layernorm -> bf16 hi/lo --------------------------------- */
__global__ void __launch_bounds__(256) ln_kernel(
    const float* __restrict__ x, const float* __restrict__ sc,
    const float* __restrict__ bi, bf16* __restrict__ yh, bf16* __restrict__ yl)
{
    long row = blockIdx.x;
    int  t   = threadIdx.x;
    const float* xr = x + row * DIM;
    float v0 = xr[t], v1 = xr[t + 256], v2 = xr[t + 512];

    __shared__ float sbuf[8];
    __shared__ float s_mu, s_r;

    float s = v0 + v1 + v2;
    #pragma unroll
    for (int o = 16; o > 0; o >>= 1) s += __shfl_xor_sync(0xffffffffu, s, o);
    if ((t & 31) == 0) sbuf[t >> 5] = s;
    __syncthreads();
    if (t < 8) {
        float r = sbuf[t];
        #pragma unroll
        for (int o = 4; o > 0; o >>= 1) r += __shfl_xor_sync(0xffu, r, o);
        if (t == 0) s_mu = r * (1.0f / DIM);
    }
    __syncthreads();
    float mu = s_mu;
    float d0 = v0 - mu, d1 = v1 - mu, d2 = v2 - mu;
    float q = d0*d0 + d1*d1 + d2*d2;
    #pragma unroll
    for (int o = 16; o > 0; o >>= 1) q += __shfl_xor_sync(0xffffffffu, q, o);
    if ((t & 31) == 0) sbuf[t >> 5] = q;
    __syncthreads();
    if (t < 8) {
        float r = sbuf[t];
        #pragma unroll
        for (int o = 4; o > 0; o >>= 1) r += __shfl_xor_sync(0xffu, r, o);
        if (t == 0) s_r = rsqrtf(r * (1.0f / DIM) + LN_EPS);
    }
    __syncthreads();
    float rs = s_r;
    long base = row * DIM;
    float o0 = d0 * rs * sc[t      ] + bi[t      ];
    float o1 = d1 * rs * sc[t + 256] + bi[t + 256];
    float o2 = d2 * rs * sc[t + 512] + bi[t + 512];
    bf16 h, l;
    split1(o0, h, l); yh[base + t      ] = h; yl[base + t      ] = l;
    split1(o1, h, l); yh[base + t + 256] = h; yl[base + t + 256] = l;
    split1(o2, h, l); yh[base + t + 512] = h; yl[base + t + 512] = l;
}

/* ================= flash attention (outputs bf16 hi/lo) ==================== */
#define BQ  128
#define BKV 64
#define QST 72
#define SQ_ELE (BQ*QST)
#define SK_ELE (BKV*QST)
#define FA_SMEM ((2*SQ_ELE + 4*SK_ELE) * 2)

__global__ void __launch_bounds__(128) flash_kernel(
    const float* __restrict__ qkv, bf16* __restrict__ attH, bf16* __restrict__ attL)
{
    extern __shared__ bf16 sm[];
    bf16* QsH = sm;
    bf16* QsL = QsH + SQ_ELE;
    bf16* KsH = QsL + SQ_ELE;
    bf16* KsL = KsH + SK_ELE;
    bf16* VsH = KsL + SK_ELE;
    bf16* VsL = VsH + SK_ELE;
    uint32_t* VWH = reinterpret_cast<uint32_t*>(VsH);
    uint32_t* VWL = reinterpret_cast<uint32_t*>(VsL);

    int t = threadIdx.x, lane = t & 31, wid = t >> 5;
    int gid = lane >> 2, tig = lane & 3;
    int bh = blockIdx.y, b = bh / HEADS, h = bh % HEADS;
    int q0 = blockIdx.x * BQ;

    const float* Qp = qkv + ((long)b * SEQ + q0) * (3*DIM) + h * HD;
    const float* Kp = qkv + (long)b * SEQ * (3*DIM) + DIM     + h * HD;
    const float* Vp = qkv + (long)b * SEQ * (3*DIM) + 2*DIM   + h * HD;

    {
        const float* qr = Qp + (long)t * (3*DIM);
        #pragma unroll
        for (int c = 0; c < HD; c += 8) {
            float4 u0 = *reinterpret_cast<const float4*>(qr + c);
            float4 u1 = *reinterpret_cast<const float4*>(qr + c + 4);
            float f[8] = {u0.x*0.125f, u0.y*0.125f, u0.z*0.125f, u0.w*0.125f,
                          u1.x*0.125f, u1.y*0.125f, u1.z*0.125f, u1.w*0.125f};
            uint4 h4, l4; cvt8(f, h4, l4);
            *reinterpret_cast<uint4*>(&QsH[t*QST + c]) = h4;
            *reinterpret_cast<uint4*>(&QsL[t*QST + c]) = l4;
        }
    }

    float acc[2][8][4];
    float oacc[2][8][4];
    float mrow[2][2], lrow[2][2];
    #pragma unroll
    for (int i = 0; i < 2; i++) {
        mrow[i][0] = mrow[i][1] = -1e30f;
        lrow[i][0] = lrow[i][1] = 0.0f;
        #pragma unroll
        for (int j = 0; j < 8; j++)
            #pragma unroll
            for (int r = 0; r < 4; r++) oacc[i][j][r] = 0.0f;
    }

    int wm = wid * 32;
    int kr = t >> 1, kh = (t & 1) * 32;
    float kreg[32];
    int vrp = t & 31, vdb = (t >> 5) * 16;
    float vreg[32];

    auto loadK = [&](int it) {
        const float* p = Kp + (long)(it * BKV + kr) * (3*DIM) + kh;
        #pragma unroll
        for (int i = 0; i < 8; i++) {
            float4 v = *reinterpret_cast<const float4*>(p + i*4);
            kreg[i*4] = v.x; kreg[i*4+1] = v.y; kreg[i*4+2] = v.z; kreg[i*4+3] = v.w;
        }
    };
    auto loadV = [&](int it) {
        const float* p0 = Vp + (long)(it * BKV + 2*vrp) * (3*DIM) + vdb;
        const float* p1 = p0 + 3*DIM;
        #pragma unroll
        for (int i = 0; i < 4; i++) {
            float4 a = *reinterpret_cast<const float4*>(p0 + i*4);
            float4 c = *reinterpret_cast<const float4*>(p1 + i*4);
            vreg[i*4] = a.x; vreg[i*4+1] = a.y; vreg[i*4+2] = a.z; vreg[i*4+3] = a.w;
            vreg[16+i*4] = c.x; vreg[16+i*4+1] = c.y; vreg[16+i*4+2] = c.z; vreg[16+i*4+3] = c.w;
        }
    };

    loadK(0);

    for (int it = 0; it < SEQ / BKV; it++) {
        __syncthreads();
        #pragma unroll
        for (int i = 0; i < 4; i++) {
            uint4 h4, l4; cvt8(kreg + i*8, h4, l4);
            *reinterpret_cast<uint4*>(&KsH[kr*QST + kh + i*8]) = h4;
            *reinterpret_cast<uint4*>(&KsL[kr*QST + kh + i*8]) = l4;
        }
        loadV(it);
        __syncthreads();

        #pragma unroll
        for (int i = 0; i < 2; i++)
            #pragma unroll
            for (int j = 0; j < 8; j++)
                #pragma unroll
                for (int r = 0; r < 4; r++) acc[i][j][r] = 0.0f;

        #pragma unroll
        for (int ks = 0; ks < 4; ks++) {
            uint32_t qh[2][4], ql[2][4];
            #pragma unroll
            for (int tm = 0; tm < 2; tm++) {
                int row = wm + tm*16 + gid;
                qh[tm][0] = *reinterpret_cast<const uint32_t*>(&QsH[ row    *QST + ks*16 + tig*2    ]);
                qh[tm][1] = *reinterpret_cast<const uint32_t*>(&QsH[(row+8)*QST + ks*16 + tig*2    ]);
                qh[tm][2] = *reinterpret_cast<const uint32_t*>(&QsH[ row    *QST + ks*16 + tig*2 + 8]);
                qh[tm][3] = *reinterpret_cast<const uint32_t*>(&QsH[(row+8)*QST + ks*16 + tig*2 + 8]);
                ql[tm][0] = *reinterpret_cast<const uint32_t*>(&QsL[ row    *QST + ks*16 + tig*2    ]);
                ql[tm][1] = *reinterpret_cast<const uint32_t*>(&QsL[(row+8)*QST + ks*16 + tig*2    ]);
                ql[tm][2] = *reinterpret_cast<const uint32_t*>(&QsL[ row    *QST + ks*16 + tig*2 + 8]);
                ql[tm][3] = *reinterpret_cast<const uint32_t*>(&QsL[(row+8)*QST + ks*16 + tig*2 + 8]);
            }
            #pragma unroll
            for (int tn = 0; tn < 8; tn++) {
                int nr = tn*8 + gid;
                uint32_t bh0 = *reinterpret_cast<const uint32_t*>(&KsH[nr*QST + ks*16 + tig*2    ]);
                uint32_t bh1 = *reinterpret_cast<const uint32_t*>(&KsH[nr*QST + ks*16 + tig*2 + 8]);
                uint32_t bl0 = *reinterpret_cast<const uint32_t*>(&KsL[nr*QST + ks*16 + tig*2    ]);
                uint32_t bl1 = *reinterpret_cast<const uint32_t*>(&KsL[nr*QST + ks*16 + tig*2 + 8]);
                #pragma unroll
                for (int tm = 0; tm < 2; tm++) {
                    float* c = acc[tm][tn];
                    mma16816(c[0],c[1],c[2],c[3], qh[tm][0],qh[tm][1],qh[tm][2],qh[tm][3], bh0,bh1);
                    mma16816(c[0],c[1],c[2],c[3], qh[tm][0],qh[tm][1],qh[tm][2],qh[tm][3], bl0,bl1);
                    mma16816(c[0],c[1],c[2],c[3], ql[tm][0],ql[tm][1],ql[tm][2],ql[tm][3], bh0,bh1);
                }
            }
        }

        #pragma unroll
        for (int tm = 0; tm < 2; tm++) {
            float mx0 = -1e30f, mx1 = -1e30f;
            #pragma unroll
            for (int tn = 0; tn < 8; tn++) {
                mx0 = fmaxf(mx0, fmaxf(acc[tm][tn][0], acc[tm][tn][1]));
                mx1 = fmaxf(mx1, fmaxf(acc[tm][tn][2], acc[tm][tn][3]));
            }
            #pragma unroll
            for (int o = 1; o <= 2; o <<= 1) {
                mx0 = fmaxf(mx0, __shfl_xor_sync(0xffffffffu, mx0, o));
                mx1 = fmaxf(mx1, __shfl_xor_sync(0xffffffffu, mx1, o));
            }
            float mn0 = fmaxf(mrow[tm][0], mx0);
            float mn1 = fmaxf(mrow[tm][1], mx1);
            float sc0 = __expf(mrow[tm][0] - mn0);
            float sc1 = __expf(mrow[tm][1] - mn1);
            float ls0 = 0.0f, ls1 = 0.0f;
            #pragma unroll
            for (int tn = 0; tn < 8; tn++) {
                float* c = acc[tm][tn];
                c[0] = __expf(c[0] - mn0);
                c[1] = __expf(c[1] - mn0);
                c[2] = __expf(c[2] - mn1);
                c[3] = __expf(c[3] - mn1);
                ls0 += c[0] + c[1];
                ls1 += c[2] + c[3];
            }
            #pragma unroll
            for (int o = 1; o <= 2; o <<= 1) {
                ls0 += __shfl_xor_sync(0xffffffffu, ls0, o);
                ls1 += __shfl_xor_sync(0xffffffffu, ls1, o);
            }
            lrow[tm][0] = lrow[tm][0] * sc0 + ls0;
            lrow[tm][1] = lrow[tm][1] * sc1 + ls1;
            mrow[tm][0] = mn0;
            mrow[tm][1] = mn1;
            #pragma unroll
            for (int to = 0; to < 8; to++) {
                oacc[tm][to][0] *= sc0; oacc[tm][to][1] *= sc0;
                oacc[tm][to][2] *= sc1; oacc[tm][to][3] *= sc1;
            }
        }

        #pragma unroll
        for (int j = 0; j < 16; j++) {
            uint32_t hw, lw;
            pack_hl(vreg[j], vreg[16 + j], hw, lw);
            VWH[(vdb + j) * (QST/2) + vrp] = hw;
            VWL[(vdb + j) * (QST/2) + vrp] = lw;
        }
        if (it + 1 < SEQ / BKV) loadK(it + 1);
        __syncthreads();

        #pragma unroll
        for (int j = 0; j < 4; j++) {
            uint32_t pH[2][4], pL[2][4];
            #pragma unroll
            for (int tm = 0; tm < 2; tm++) {
                pack_hl(acc[tm][2*j  ][0], acc[tm][2*j  ][1], pH[tm][0], pL[tm][0]);
                pack_hl(acc[tm][2*j  ][2], acc[tm][2*j  ][3], pH[tm][1], pL[tm][1]);
                pack_hl(acc[tm][2*j+1][0], acc[tm][2*j+1][1], pH[tm][2], pL[tm][2]);
                pack_hl(acc[tm][2*j+1][2], acc[tm][2*j+1][3], pH[tm][3], pL[tm][3]);
            }
            #pragma unroll
            for (int to = 0; to < 8; to++) {
                int d = to*8 + gid;
                uint32_t bh0 = *reinterpret_cast<const uint32_t*>(&VsH[d*QST + j*16 + tig*2    ]);
                uint32_t bh1 = *reinterpret_cast<const uint32_t*>(&VsH[d*QST + j*16 + tig*2 + 8]);
                uint32_t bl0 = *reinterpret_cast<const uint32_t*>(&VsL[d*QST + j*16 + tig*2    ]);
                uint32_t bl1 = *reinterpret_cast<const uint32_t*>(&VsL[d*QST + j*16 + tig*2 + 8]);
                #pragma unroll
                for (int tm = 0; tm < 2; tm++) {
                    float* c = oacc[tm][to];
                    mma16816(c[0],c[1],c[2],c[3], pH[tm][0],pH[tm][1],pH[tm][2],pH[tm][3], bh0,bh1);
                    mma16816(c[0],c[1],c[2],c[3], pH[tm][0],pH[tm][1],pH[tm][2],pH[tm][3], bl0,bl1);
                    mma16816(c[0],c[1],c[2],c[3], pL[tm][0],pL[tm][1],pL[tm][2],pL[tm][3], bh0,bh1);
                }
            }
        }
    }

    /* epilogue: O / l -> att hi/lo bf16 */
    uint32_t* AH = reinterpret_cast<uint32_t*>(attH);
    uint32_t* AL = reinterpret_cast<uint32_t*>(attL);
    #pragma unroll
    for (int tm = 0; tm < 2; tm++) {
        float inv0 = 1.0f / lrow[tm][0];
        float inv1 = 1.0f / lrow[tm][1];
        int row = q0 + wm + tm*16 + gid;
        #pragma unroll
        for (int to = 0; to < 8; to++) {
            int col = h*HD + to*8 + tig*2;
            float* c = oacc[tm][to];
            long o0 = (((long)b*SEQ + row    ) * DIM + col) >> 1;
            long o1 = (((long)b*SEQ + row + 8) * DIM + col) >> 1;
            uint32_t hw, lw;
            pack_hl(c[0]*inv0, c[1]*inv0, hw, lw);
            AH[o0] = hw; AL[o0] = lw;
            pack_hl(c[2]*inv1, c[3]*inv1, hw, lw);
            AH[o1] = hw; AL[o1] = lw;
        }
    }
}

/* ================= dense GEMM: bf16 hi/lo inputs, cp.async pipeline ========
 * A: [M][K] bf16 (hi,lo), B: [N][K] bf16 (hi,lo).
 * Block 128x128, BK=32, 256 thr (8 warps, warp tile 64x32), 2 CTAs/SM.
 * Output: f32 (+bias, +opt residual) or gelu -> bf16 hi/lo split.
 */
#define BM  128
#define BN  128
#define BK2 32
#define SEB 40                    /* smem row stride in bf16 */
#define TSZ (BM*SEB)              /* 5120 elems per tile-buffer */
#define GEMM_SMEM (8*TSZ*2)       /* 81920 bytes */

__global__ void __launch_bounds__(256, 2) gemm_bf(
    const bf16* __restrict__ Agh, const bf16* __restrict__ Agl,
    const bf16* __restrict__ Bgh, const bf16* __restrict__ Bgl,
    const float* __restrict__ bias, const float* __restrict__ Rsd,
    float* __restrict__ Cf, bf16* __restrict__ Ch, bf16* __restrict__ Cl,
    int M, int N, int K)
{
    extern __shared__ bf16 gsm[];
    /* layout: [Ah0 Ah1 Al0 Al1 Bh0 Bh1 Bl0 Bl1], each TSZ */
    uint32_t sbase = (uint32_t)__cvta_generic_to_shared(gsm);

    int m0 = blockIdx.y * BM;
    int n0 = blockIdx.x * BN;
    int t  = threadIdx.x;
    int lane = t & 31, wid = t >> 5;
    int gid = lane >> 2, tig = lane & 3;
    int warp_m = (wid >> 2) << 6;
    int warp_n = (wid & 3) << 5;

    /* loader: chunks c = t, t+256 ; row = c>>2, col = (c&3)*8 */
    int r0c = t >> 2,        c0c = (t & 3) * 8;
    int r1c = (t + 256) >> 2, c1c = ((t + 256) & 3) * 8;

    auto issue = [&](int kk) {
        int buf = kk & 1;
        long k0 = (long)kk * BK2;
        uint32_t dA = sbase + (buf*TSZ)*2;
        uint32_t dAl = sbase + ((2+buf)*TSZ)*2;
        uint32_t dB = sbase + ((4+buf)*TSZ)*2;
        uint32_t dBl = sbase + ((6+buf)*TSZ)*2;
        cp16(dA  + (r0c*SEB + c0c)*2, Agh + (long)(m0 + r0c)*K + k0 + c0c);
        cp16(dA  + (r1c*SEB + c1c)*2, Agh + (long)(m0 + r1c)*K + k0 + c1c);
        cp16(dAl + (r0c*SEB + c0c)*2, Agl + (long)(m0 + r0c)*K + k0 + c0c);
        cp16(dAl + (r1c*SEB + c1c)*2, Agl + (long)(m0 + r1c)*K + k0 + c1c);
        cp16(dB  + (r0c*SEB + c0c)*2, Bgh + (long)(n0 + r0c)*K + k0 + c0c);
        cp16(dB  + (r1c*SEB + c1c)*2, Bgh + (long)(n0 + r1c)*K + k0 + c1c);
        cp16(dBl + (r0c*SEB + c0c)*2, Bgl + (long)(n0 + r0c)*K + k0 + c0c);
        cp16(dBl + (r1c*SEB + c1c)*2, Bgl + (long)(n0 + r1c)*K + k0 + c1c);
        asm volatile("cp.async.commit_group;");
    };

    float acc[4][4][4];
    #pragma unroll
    for (int i = 0; i < 4; i++)
        #pragma unroll
        for (int j = 0; j < 4; j++)
            #pragma unroll
            for (int r = 0; r < 4; r++) acc[i][j][r] = 0.0f;

    /* per-lane ldmatrix address components */
    int t4 = lane >> 3, li = lane & 7;
    int a_row = (t4 & 1) * 8 + li,  a_col = (t4 >> 1) * 8;     /* A tiles */
    int b_row = (t4 >> 1) * 8 + li, b_col = (t4 & 1) * 8;      /* B tile-pairs */

    int kt = K / BK2;
    issue(0);

    for (int kk = 0; kk < kt; kk++) {
        if (kk + 1 < kt) {
            issue(kk + 1);
            asm volatile("cp.async.wait_group 1;");
        } else {
            asm volatile("cp.async.wait_group 0;");
        }
        __syncthreads();

        int buf = kk & 1;
        uint32_t sAh = sbase + (buf*TSZ)*2;
        uint32_t sAl = sbase + ((2+buf)*TSZ)*2;
        uint32_t sBh = sbase + ((4+buf)*TSZ)*2;
        uint32_t sBl = sbase + ((6+buf)*TSZ)*2;

        #pragma unroll
        for (int ks = 0; ks < 2; ks++) {
            int kc = ks * 16;
            uint32_t ah[4][4], bh[2][4];
            #pragma unroll
            for (int tm = 0; tm < 4; tm++)
                ldm_x4(ah[tm], sAh + ((warp_m + tm*16 + a_row)*SEB + kc + a_col)*2);
            #pragma unroll
            for (int p = 0; p < 2; p++)
                ldm_x4(bh[p], sBh + ((warp_n + p*16 + b_row)*SEB + kc + b_col)*2);

            #pragma unroll
            for (int tm = 0; tm < 4; tm++)
                #pragma unroll
                for (int tn = 0; tn < 4; tn++) {
                    float* c = acc[tm][tn];
                    uint32_t* bb = bh[tn >> 1];
                    mma16816(c[0],c[1],c[2],c[3],
                             ah[tm][0],ah[tm][1],ah[tm][2],ah[tm][3],
                             bb[(tn&1)*2], bb[(tn&1)*2+1]);
                }

            uint32_t bl[2][4];
            #pragma unroll
            for (int p = 0; p < 2; p++)
                ldm_x4(bl[p], sBl + ((warp_n + p*16 + b_row)*SEB + kc + b_col)*2);
            #pragma unroll
            for (int tm = 0; tm < 4; tm++)
                #pragma unroll
                for (int tn = 0; tn < 4; tn++) {
                    float* c = acc[tm][tn];
                    uint32_t* bb = bl[tn >> 1];
                    mma16816(c[0],c[1],c[2],c[3],
                             ah[tm][0],ah[tm][1],ah[tm][2],ah[tm][3],
                             bb[(tn&1)*2], bb[(tn&1)*2+1]);
                }

            uint32_t al[4][4];
            #pragma unroll
            for (int tm = 0; tm < 4; tm++)
                ldm_x4(al[tm], sAl + ((warp_m + tm*16 + a_row)*SEB + kc + a_col)*2);
            #pragma unroll
            for (int tm = 0; tm < 4; tm++)
                #pragma unroll
                for (int tn = 0; tn < 4; tn++) {
                    float* c = acc[tm][tn];
                    uint32_t* bb = bh[tn >> 1];
                    mma16816(c[0],c[1],c[2],c[3],
                             al[tm][0],al[tm][1],al[tm][2],al[tm][3],
                             bb[(tn&1)*2], bb[(tn&1)*2+1]);
                }
        }
        __syncthreads();
    }

    /* epilogue */
    #pragma unroll
    for (int tn = 0; tn < 4; tn++) {
        int col = n0 + warp_n + tn * 8 + tig * 2;
        float b0 = bias ? bias[col]     : 0.0f;
        float b1 = bias ? bias[col + 1] : 0.0f;
        #pragma unroll
        for (int tm = 0; tm < 4; tm++) {
            int row0 = m0 + warp_m + tm * 16 + gid;
            float* c = acc[tm][tn];
            #pragma unroll
            for (int half = 0; half < 2; half++) {
                int row = row0 + half * 8;
                float v0 = c[half*2 + 0] + b0;
                float v1 = c[half*2 + 1] + b1;
                long off = (long)row * N + col;
                if (Ch) {
                    v0 = gelu_tanh(v0);
                    v1 = gelu_tanh(v1);
                    uint32_t hw, lw;
                    pack_hl(v0, v1, hw, lw);
                    reinterpret_cast<uint32_t*>(Ch)[off >> 1] = hw;
                    reinterpret_cast<uint32_t*>(Cl)[off >> 1] = lw;
                } else {
                    if (Rsd) {
                        float2 r = *reinterpret_cast<const float2*>(Rsd + off);
                        v0 += r.x; v1 += r.y;
                    }
                    *reinterpret_cast<float2*>(Cf + off) = make_float2(v0, v1);
                }
            }
        }
    }
}

/* ---------------- launch --------------------------------------------------- */
extern "C" void kernel_launch(void* const* d_in, const int* in_sizes, int n_in,
                              void* d_out, int out_size)
{
    const float* x     = (const float*)d_in[0];
    const float* ln1s  = (const float*)d_in[1];
    const float* ln1b  = (const float*)d_in[2];
    const float* qkvw  = (const float*)d_in[3];
    const float* qkvb  = (const float*)d_in[4];
    const float* projw = (const float*)d_in[5];
    const float* projb = (const float*)d_in[6];
    const float* ln2s  = (const float*)d_in[7];
    const float* ln2b  = (const float*)d_in[8];
    const float* fc1w  = (const float*)d_in[9];
    const float* fc1b  = (const float*)d_in[10];
    const float* fc2w  = (const float*)d_in[11];
    const float* fc2b  = (const float*)d_in[12];
    float* out = (float*)d_out;

    bf16 *yh, *yl, *ath, *atl, *hh, *hl;
    bf16 *wqh, *wql, *wph, *wpl, *w1h, *w1l, *w2h, *w2l;
    float *qkv, *x1;
    cudaGetSymbolAddress((void**)&yh,  g_yh);
    cudaGetSymbolAddress((void**)&yl,  g_yl);
    cudaGetSymbolAddress((void**)&qkv, g_qkv);
    cudaGetSymbolAddress((void**)&ath, g_ath);
    cudaGetSymbolAddress((void**)&atl, g_atl);
    cudaGetSymbolAddress((void**)&x1,  g_x1);
    cudaGetSymbolAddress((void**)&hh,  g_hh);
    cudaGetSymbolAddress((void**)&hl,  g_hl);
    cudaGetSymbolAddress((void**)&wqh, g_wqh);
    cudaGetSymbolAddress((void**)&wql, g_wql);
    cudaGetSymbolAddress((void**)&wph, g_wph);
    cudaGetSymbolAddress((void**)&wpl, g_wpl);
    cudaGetSymbolAddress((void**)&w1h, g_w1h);
    cudaGetSymbolAddress((void**)&w1l, g_w1l);
    cudaGetSymbolAddress((void**)&w2h, g_w2h);
    cudaGetSymbolAddress((void**)&w2l, g_w2l);

    cudaFuncSetAttribute(flash_kernel,
        cudaFuncAttributeMaxDynamicSharedMemorySize, FA_SMEM);
    cudaFuncSetAttribute(gemm_bf,
        cudaFuncAttributeMaxDynamicSharedMemorySize, GEMM_SMEM);

    /* 0. weight transpose + split (cheap; runs every call, deterministic) */
    wt_kernel<<<dim3(3*DIM/32, DIM/32), dim3(32,8)>>>(qkvw, wqh, wql, DIM, 3*DIM);
    wt_kernel<<<dim3(DIM/32,   DIM/32), dim3(32,8)>>>(projw, wph, wpl, DIM, DIM);
    wt_kernel<<<dim3(HIDDEN/32,DIM/32), dim3(32,8)>>>(fc1w, w1h, w1l, DIM, HIDDEN);
    wt_kernel<<<dim3(DIM/32,HIDDEN/32), dim3(32,8)>>>(fc2w, w2h, w2l, HIDDEN, DIM);

    /* 1. LN1 -> y hi/lo */
    ln_kernel<<<ROWS, 256>>>(x, ln1s, ln1b, yh, yl);

    /* 2. QKV = y @ Wq + b  (f32 out) */
    gemm_bf<<<dim3(3*DIM/BN, ROWS/BM), 256, GEMM_SMEM>>>(
        yh, yl, wqh, wql, qkvb, nullptr, qkv, nullptr, nullptr,
        ROWS, 3*DIM, DIM);

    /* 3-5. flash attention -> att hi/lo */
    flash_kernel<<<dim3(SEQ / BQ, BATCH * HEADS), 128, FA_SMEM>>>(qkv, ath, atl);

    /* 6. x1 = att @ Wp + b + x */
    gemm_bf<<<dim3(DIM/BN, ROWS/BM), 256, GEMM_SMEM>>>(
        ath, atl, wph, wpl, projb, x, x1, nullptr, nullptr,
        ROWS, DIM, DIM);

    /* 7. LN2 -> y hi/lo */
    ln_kernel<<<ROWS, 256>>>(x1, ln2s, ln2b, yh, yl);

    /* 8. h = gelu(y @ W1 + b)  (bf16 hi/lo out) */
    gemm_bf<<<dim3(HIDDEN/BN, ROWS/BM), 256, GEMM_SMEM>>>(
        yh, yl, w1h, w1l, fc1b, nullptr, nullptr, hh, hl,
        ROWS, HIDDEN, DIM);

    /* 9. out = h @ W2 + b + x1 */
    gemm_bf<<<dim3(DIM/BN, ROWS/BM), 256, GEMM_SMEM>>>(
        hh, hl, w2h, w2l, fc2b, x1, out, nullptr, nullptr,
        ROWS, DIM, HIDDEN);
}

// round 6
// speedup vs baseline: 4.4543x; 1.3983x over previous
#include <cuda_runtime.h>
#include <cuda_fp16.h>
#include <cstdint>

#define DIM    768
#define SEQ    1024
#define BATCH  8
#define ROWS   (BATCH*SEQ)      /* 8192 */
#define HEADS  12
#define HD     64
#define HIDDEN 3072
#define LN_EPS 1e-6f

typedef __half hf;

/* ---------------- scratch (static device globals; no allocations) -------- */
__device__ __align__(16) hf    g_y  [ROWS * DIM];       /* LN out, fp16 */
__device__ __align__(16) float g_qkv[ROWS * 3 * DIM];
__device__ __align__(16) hf    g_att[ROWS * DIM];       /* attention out */
__device__ __align__(16) float g_x1 [ROWS * DIM];
__device__ __align__(16) hf    g_h  [ROWS * HIDDEN];    /* fc1 out */
/* transposed fp16 hi/lo weights, [N][K] */
__device__ __align__(16) hf g_wqh[3*DIM*DIM], g_wql[3*DIM*DIM];
__device__ __align__(16) hf g_wph[DIM*DIM],   g_wpl[DIM*DIM];
__device__ __align__(16) hf g_w1h[HIDDEN*DIM], g_w1l[HIDDEN*DIM];
__device__ __align__(16) hf g_w2h[DIM*HIDDEN], g_w2l[DIM*HIDDEN];

/* ---------------- helpers -------------------------------------------------- */
__device__ __forceinline__ float gelu_tanh(float u)
{
    return 0.5f * u * (1.0f + tanhf(0.7978845608028654f * (u + 0.044715f * u * u * u)));
}

__device__ __forceinline__ void mma16816(
    float& c0, float& c1, float& c2, float& c3,
    uint32_t a0, uint32_t a1, uint32_t a2, uint32_t a3,
    uint32_t b0, uint32_t b1)
{
    asm volatile(
        "mma.sync.aligned.m16n8k16.row.col.f32.f16.f16.f32 "
        "{%0,%1,%2,%3},{%4,%5,%6,%7},{%8,%9},{%0,%1,%2,%3};"
        : "+f"(c0), "+f"(c1), "+f"(c2), "+f"(c3)
        : "r"(a0), "r"(a1), "r"(a2), "r"(a3), "r"(b0), "r"(b1));
}

__device__ __forceinline__ uint32_t pack1(float x0, float x1)
{
    hf h0 = __float2half_rn(x0), h1 = __float2half_rn(x1);
    return ((uint32_t)__half_as_ushort(h1) << 16) | __half_as_ushort(h0);
}

__device__ __forceinline__ void pack_hl(float x0, float x1, uint32_t& hi, uint32_t& lo)
{
    hf h0 = __float2half_rn(x0), h1 = __float2half_rn(x1);
    float r0 = x0 - __half2float(h0);
    float r1 = x1 - __half2float(h1);
    hi = ((uint32_t)__half_as_ushort(h1) << 16) | __half_as_ushort(h0);
    lo = pack1(r0, r1);
}

__device__ __forceinline__ void split1(float x, hf& h, hf& l)
{
    h = __float2half_rn(x);
    l = __float2half_rn(x - __half2float(h));
}

/* 8 floats -> hi/lo fp16 uint4s */
__device__ __forceinline__ void cvt8hl(const float* f, uint4& hi4, uint4& lo4)
{
    uint32_t h[4], l[4];
    #pragma unroll
    for (int i = 0; i < 4; i++) pack_hl(f[2*i], f[2*i+1], h[i], l[i]);
    hi4 = make_uint4(h[0], h[1], h[2], h[3]);
    lo4 = make_uint4(l[0], l[1], l[2], l[3]);
}

/* 8 floats -> single fp16 uint4 */
__device__ __forceinline__ uint4 cvt8s(const float* f)
{
    return make_uint4(pack1(f[0], f[1]), pack1(f[2], f[3]),
                      pack1(f[4], f[5]), pack1(f[6], f[7]));
}

__device__ __forceinline__ void cp16(uint32_t s, const void* g)
{
    asm volatile("cp.async.cg.shared.global [%0], [%1], 16;" :: "r"(s), "l"(g));
}
__device__ __forceinline__ void ldm_x4(uint32_t* r, uint32_t addr)
{
    asm volatile("ldmatrix.sync.aligned.m8n8.x4.shared.b16 {%0,%1,%2,%3}, [%4];"
        : "=r"(r[0]), "=r"(r[1]), "=r"(r[2]), "=r"(r[3]) : "r"(addr));
}

/* ---------------- weight transpose + split: W[K][N] -> Th/Tl[N][K] -------- */
__global__ void __launch_bounds__(256) wt_kernel(
    const float* __restrict__ W, hf* __restrict__ Th, hf* __restrict__ Tl,
    int K, int N)
{
    __shared__ float s[32][33];
    int tx = threadIdx.x, ty = threadIdx.y;
    int n0 = blockIdx.x * 32, k0 = blockIdx.y * 32;
    #pragma unroll
    for (int j = 0; j < 4; j++)
        s[ty + j*8][tx] = W[(long)(k0 + ty + j*8) * N + n0 + tx];
    __syncthreads();
    #pragma unroll
    for (int j = 0; j < 4; j++) {
        float v = s[tx][ty + j*8];
        hf h, l; split1(v, h, l);
        long o = (long)(n0 + ty + j*8) * K + k0 + tx;
        Th[o] = h; Tl[o] = l;
    }
}

/* ---------------- layernorm -> single fp16 --------------------------------- */
__global__ void __launch_bounds__(256) ln_kernel(
    const float* __restrict__ x, const float* __restrict__ sc,
    const float* __restrict__ bi, hf* __restrict__ y)
{
    long row = blockIdx.x;
    int  t   = threadIdx.x;
    const float* xr = x + row * DIM;
    float v0 = xr[t], v1 = xr[t + 256], v2 = xr[t + 512];

    __shared__ float sbuf[8];
    __shared__ float s_mu, s_r;

    float s = v0 + v1 + v2;
    #pragma unroll
    for (int o = 16; o > 0; o >>= 1) s += __shfl_xor_sync(0xffffffffu, s, o);
    if ((t & 31) == 0) sbuf[t >> 5] = s;
    __syncthreads();
    if (t < 8) {
        float r = sbuf[t];
        #pragma unroll
        for (int o = 4; o > 0; o >>= 1) r += __shfl_xor_sync(0xffu, r, o);
        if (t == 0) s_mu = r * (1.0f / DIM);
    }
    __syncthreads();
    float mu = s_mu;
    float d0 = v0 - mu, d1 = v1 - mu, d2 = v2 - mu;
    float q = d0*d0 + d1*d1 + d2*d2;
    #pragma unroll
    for (int o = 16; o > 0; o >>= 1) q += __shfl_xor_sync(0xffffffffu, q, o);
    if ((t & 31) == 0) sbuf[t >> 5] = q;
    __syncthreads();
    if (t < 8) {
        float r = sbuf[t];
        #pragma unroll
        for (int o = 4; o > 0; o >>= 1) r += __shfl_xor_sync(0xffu, r, o);
        if (t == 0) s_r = rsqrtf(r * (1.0f / DIM) + LN_EPS);
    }
    __syncthreads();
    float rs = s_r;
    long base = row * DIM;
    y[base + t      ] = __float2half_rn(d0 * rs * sc[t      ] + bi[t      ]);
    y[base + t + 256] = __float2half_rn(d1 * rs * sc[t + 256] + bi[t + 256]);
    y[base + t + 512] = __float2half_rn(d2 * rs * sc[t + 512] + bi[t + 512]);
}

/* ================= flash attention (fp16) ==================================
 * Q split hi/lo (pre-scaled), K single, V single transposed, P split hi/lo.
 * S = (Qh+Ql)@K : 2 mma ; O += (Ph+Pl)@V : 2 mma.
 */
#define BQ  128
#define BKV 64
#define QST 72
#define SQ_ELE (BQ*QST)
#define SK_ELE (BKV*QST)
#define FA_SMEM ((2*SQ_ELE + 2*SK_ELE) * 2)   /* 55296 B */

__global__ void __launch_bounds__(128) flash_kernel(
    const float* __restrict__ qkv, hf* __restrict__ att)
{
    extern __shared__ hf sm[];
    hf* QsH = sm;
    hf* QsL = QsH + SQ_ELE;
    hf* Ks  = QsL + SQ_ELE;
    hf* Vs  = Ks  + SK_ELE;
    uint32_t* KW = reinterpret_cast<uint32_t*>(Ks);
    uint32_t* VW = reinterpret_cast<uint32_t*>(Vs);

    int t = threadIdx.x, lane = t & 31, wid = t >> 5;
    int gid = lane >> 2, tig = lane & 3;
    int bh = blockIdx.y, b = bh / HEADS, h = bh % HEADS;
    int q0 = blockIdx.x * BQ;

    const float* Qp = qkv + ((long)b * SEQ + q0) * (3*DIM) + h * HD;
    const float* Kp = qkv + (long)b * SEQ * (3*DIM) + DIM     + h * HD;
    const float* Vp = qkv + (long)b * SEQ * (3*DIM) + 2*DIM   + h * HD;

    /* Q preload: one row per thread, scaled, split hi/lo */
    {
        const float* qr = Qp + (long)t * (3*DIM);
        #pragma unroll
        for (int c = 0; c < HD; c += 8) {
            float4 u0 = *reinterpret_cast<const float4*>(qr + c);
            float4 u1 = *reinterpret_cast<const float4*>(qr + c + 4);
            float f[8] = {u0.x*0.125f, u0.y*0.125f, u0.z*0.125f, u0.w*0.125f,
                          u1.x*0.125f, u1.y*0.125f, u1.z*0.125f, u1.w*0.125f};
            uint4 h4, l4; cvt8hl(f, h4, l4);
            *reinterpret_cast<uint4*>(&QsH[t*QST + c]) = h4;
            *reinterpret_cast<uint4*>(&QsL[t*QST + c]) = l4;
        }
    }

    float acc[2][8][4];
    float oacc[2][8][4];
    float mrow[2][2], lrow[2][2];
    #pragma unroll
    for (int i = 0; i < 2; i++) {
        mrow[i][0] = mrow[i][1] = -1e30f;
        lrow[i][0] = lrow[i][1] = 0.0f;
        #pragma unroll
        for (int j = 0; j < 8; j++)
            #pragma unroll
            for (int r = 0; r < 4; r++) oacc[i][j][r] = 0.0f;
    }

    int wm = wid * 32;
    int kr = t >> 1, kh = (t & 1) * 32;
    float kreg[32];
    int vrp = t & 31, vdb = (t >> 5) * 16;
    float vreg[32];

    auto loadK = [&](int it) {
        const float* p = Kp + (long)(it * BKV + kr) * (3*DIM) + kh;
        #pragma unroll
        for (int i = 0; i < 8; i++) {
            float4 v = *reinterpret_cast<const float4*>(p + i*4);
            kreg[i*4] = v.x; kreg[i*4+1] = v.y; kreg[i*4+2] = v.z; kreg[i*4+3] = v.w;
        }
    };
    auto loadV = [&](int it) {
        const float* p0 = Vp + (long)(it * BKV + 2*vrp) * (3*DIM) + vdb;
        const float* p1 = p0 + 3*DIM;
        #pragma unroll
        for (int i = 0; i < 4; i++) {
            float4 a = *reinterpret_cast<const float4*>(p0 + i*4);
            float4 c = *reinterpret_cast<const float4*>(p1 + i*4);
            vreg[i*4] = a.x; vreg[i*4+1] = a.y; vreg[i*4+2] = a.z; vreg[i*4+3] = a.w;
            vreg[16+i*4] = c.x; vreg[16+i*4+1] = c.y; vreg[16+i*4+2] = c.z; vreg[16+i*4+3] = c.w;
        }
    };

    loadK(0);

    for (int it = 0; it < SEQ / BKV; it++) {
        __syncthreads();
        /* store K tile (single fp16) */
        #pragma unroll
        for (int i = 0; i < 2; i++) {
            uint4 s4 = cvt8s(kreg + i*8);
            *reinterpret_cast<uint4*>(&KW[(kr*QST + kh)/2 + i*4]) = s4;
        }
        #pragma unroll
        for (int i = 2; i < 4; i++) {
            uint4 s4 = cvt8s(kreg + i*8);
            *reinterpret_cast<uint4*>(&KW[(kr*QST + kh)/2 + i*4]) = s4;
        }
        loadV(it);
        __syncthreads();

        #pragma unroll
        for (int i = 0; i < 2; i++)
            #pragma unroll
            for (int j = 0; j < 8; j++)
                #pragma unroll
                for (int r = 0; r < 4; r++) acc[i][j][r] = 0.0f;

        /* S = (Qh + Ql) @ K^T */
        #pragma unroll
        for (int ks = 0; ks < 4; ks++) {
            uint32_t qh[2][4], ql[2][4];
            #pragma unroll
            for (int tm = 0; tm < 2; tm++) {
                int row = wm + tm*16 + gid;
                qh[tm][0] = *reinterpret_cast<const uint32_t*>(&QsH[ row    *QST + ks*16 + tig*2    ]);
                qh[tm][1] = *reinterpret_cast<const uint32_t*>(&QsH[(row+8)*QST + ks*16 + tig*2    ]);
                qh[tm][2] = *reinterpret_cast<const uint32_t*>(&QsH[ row    *QST + ks*16 + tig*2 + 8]);
                qh[tm][3] = *reinterpret_cast<const uint32_t*>(&QsH[(row+8)*QST + ks*16 + tig*2 + 8]);
                ql[tm][0] = *reinterpret_cast<const uint32_t*>(&QsL[ row    *QST + ks*16 + tig*2    ]);
                ql[tm][1] = *reinterpret_cast<const uint32_t*>(&QsL[(row+8)*QST + ks*16 + tig*2    ]);
                ql[tm][2] = *reinterpret_cast<const uint32_t*>(&QsL[ row    *QST + ks*16 + tig*2 + 8]);
                ql[tm][3] = *reinterpret_cast<const uint32_t*>(&QsL[(row+8)*QST + ks*16 + tig*2 + 8]);
            }
            #pragma unroll
            for (int tn = 0; tn < 8; tn++) {
                int nr = tn*8 + gid;
                uint32_t b0 = *reinterpret_cast<const uint32_t*>(&Ks[nr*QST + ks*16 + tig*2    ]);
                uint32_t b1 = *reinterpret_cast<const uint32_t*>(&Ks[nr*QST + ks*16 + tig*2 + 8]);
                #pragma unroll
                for (int tm = 0; tm < 2; tm++) {
                    float* c = acc[tm][tn];
                    mma16816(c[0],c[1],c[2],c[3], qh[tm][0],qh[tm][1],qh[tm][2],qh[tm][3], b0,b1);
                    mma16816(c[0],c[1],c[2],c[3], ql[tm][0],ql[tm][1],ql[tm][2],ql[tm][3], b0,b1);
                }
            }
        }

        /* online softmax update */
        #pragma unroll
        for (int tm = 0; tm < 2; tm++) {
            float mx0 = -1e30f, mx1 = -1e30f;
            #pragma unroll
            for (int tn = 0; tn < 8; tn++) {
                mx0 = fmaxf(mx0, fmaxf(acc[tm][tn][0], acc[tm][tn][1]));
                mx1 = fmaxf(mx1, fmaxf(acc[tm][tn][2], acc[tm][tn][3]));
            }
            #pragma unroll
            for (int o = 1; o <= 2; o <<= 1) {
                mx0 = fmaxf(mx0, __shfl_xor_sync(0xffffffffu, mx0, o));
                mx1 = fmaxf(mx1, __shfl_xor_sync(0xffffffffu, mx1, o));
            }
            float mn0 = fmaxf(mrow[tm][0], mx0);
            float mn1 = fmaxf(mrow[tm][1], mx1);
            float sc0 = __expf(mrow[tm][0] - mn0);
            float sc1 = __expf(mrow[tm][1] - mn1);
            float ls0 = 0.0f, ls1 = 0.0f;
            #pragma unroll
            for (int tn = 0; tn < 8; tn++) {
                float* c = acc[tm][tn];
                c[0] = __expf(c[0] - mn0);
                c[1] = __expf(c[1] - mn0);
                c[2] = __expf(c[2] - mn1);
                c[3] = __expf(c[3] - mn1);
                ls0 += c[0] + c[1];
                ls1 += c[2] + c[3];
            }
            #pragma unroll
            for (int o = 1; o <= 2; o <<= 1) {
                ls0 += __shfl_xor_sync(0xffffffffu, ls0, o);
                ls1 += __shfl_xor_sync(0xffffffffu, ls1, o);
            }
            lrow[tm][0] = lrow[tm][0] * sc0 + ls0;
            lrow[tm][1] = lrow[tm][1] * sc1 + ls1;
            mrow[tm][0] = mn0;
            mrow[tm][1] = mn1;
            #pragma unroll
            for (int to = 0; to < 8; to++) {
                oacc[tm][to][0] *= sc0; oacc[tm][to][1] *= sc0;
                oacc[tm][to][2] *= sc1; oacc[tm][to][3] *= sc1;
            }
        }

        /* store V tile transposed (single fp16, pair-packed) */
        #pragma unroll
        for (int j = 0; j < 16; j++)
            VW[(vdb + j) * (QST/2) + vrp] = pack1(vreg[j], vreg[16 + j]);
        if (it + 1 < SEQ / BKV) loadK(it + 1);
        __syncthreads();

        /* O += (Ph + Pl) @ V */
        #pragma unroll
        for (int j = 0; j < 4; j++) {
            uint32_t pH[2][4], pL[2][4];
            #pragma unroll
            for (int tm = 0; tm < 2; tm++) {
                pack_hl(acc[tm][2*j  ][0], acc[tm][2*j  ][1], pH[tm][0], pL[tm][0]);
                pack_hl(acc[tm][2*j  ][2], acc[tm][2*j  ][3], pH[tm][1], pL[tm][1]);
                pack_hl(acc[tm][2*j+1][0], acc[tm][2*j+1][1], pH[tm][2], pL[tm][2]);
                pack_hl(acc[tm][2*j+1][2], acc[tm][2*j+1][3], pH[tm][3], pL[tm][3]);
            }
            #pragma unroll
            for (int to = 0; to < 8; to++) {
                int d = to*8 + gid;
                uint32_t b0 = *reinterpret_cast<const uint32_t*>(&Vs[d*QST + j*16 + tig*2    ]);
                uint32_t b1 = *reinterpret_cast<const uint32_t*>(&Vs[d*QST + j*16 + tig*2 + 8]);
                #pragma unroll
                for (int tm = 0; tm < 2; tm++) {
                    float* c = oacc[tm][to];
                    mma16816(c[0],c[1],c[2],c[3], pH[tm][0],pH[tm][1],pH[tm][2],pH[tm][3], b0,b1);
                    mma16816(c[0],c[1],c[2],c[3], pL[tm][0],pL[tm][1],pL[tm][2],pL[tm][3], b0,b1);
                }
            }
        }
    }

    /* epilogue: O / l -> att (single fp16) */
    uint32_t* AW = reinterpret_cast<uint32_t*>(att);
    #pragma unroll
    for (int tm = 0; tm < 2; tm++) {
        float inv0 = 1.0f / lrow[tm][0];
        float inv1 = 1.0f / lrow[tm][1];
        int row = q0 + wm + tm*16 + gid;
        #pragma unroll
        for (int to = 0; to < 8; to++) {
            int col = h*HD + to*8 + tig*2;
            float* c = oacc[tm][to];
            long o0 = (((long)b*SEQ + row    ) * DIM + col) >> 1;
            long o1 = (((long)b*SEQ + row + 8) * DIM + col) >> 1;
            AW[o0] = pack1(c[0]*inv0, c[1]*inv0);
            AW[o1] = pack1(c[2]*inv1, c[3]*inv1);
        }
    }
}

/* ================= dense GEMM: A single fp16, B = Bh+Bl fp16 ===============
 * Block 128x128, BK=32, 256 thr (8 warps, warp tile 64x32), 2 CTAs/SM.
 * C = A @ (Bh+Bl)^T + bias [+residual -> f32] or gelu -> fp16.
 */
#define BM  128
#define BN  128
#define BK2 32
#define SEB 40
#define TSZ (BM*SEB)              /* 5120 half per tile-buffer */
#define GEMM_SMEM (6*TSZ*2)       /* 61440 bytes */

__global__ void __launch_bounds__(256, 2) gemm_hf(
    const hf* __restrict__ Ag,
    const hf* __restrict__ Bgh, const hf* __restrict__ Bgl,
    const float* __restrict__ bias, const float* __restrict__ Rsd,
    float* __restrict__ Cf, hf* __restrict__ Ch,
    int M, int N, int K)
{
    extern __shared__ hf gsm[];
    /* layout: [A0 A1 Bh0 Bh1 Bl0 Bl1], each TSZ */
    uint32_t sbase = (uint32_t)__cvta_generic_to_shared(gsm);

    int m0 = blockIdx.y * BM;
    int n0 = blockIdx.x * BN;
    int t  = threadIdx.x;
    int lane = t & 31, wid = t >> 5;
    int gid = lane >> 2, tig = lane & 3;
    int warp_m = (wid >> 2) << 6;
    int warp_n = (wid & 3) << 5;

    int r0c = t >> 2,         c0c = (t & 3) * 8;
    int r1c = (t >> 2) + 64,  c1c = c0c;

    auto issue = [&](int kk) {
        int buf = kk & 1;
        long k0 = (long)kk * BK2;
        uint32_t dA  = sbase + (buf*TSZ)*2;
        uint32_t dBh = sbase + ((2+buf)*TSZ)*2;
        uint32_t dBl = sbase + ((4+buf)*TSZ)*2;
        cp16(dA  + (r0c*SEB + c0c)*2, Ag  + (long)(m0 + r0c)*K + k0 + c0c);
        cp16(dA  + (r1c*SEB + c1c)*2, Ag  + (long)(m0 + r1c)*K + k0 + c1c);
        cp16(dBh + (r0c*SEB + c0c)*2, Bgh + (long)(n0 + r0c)*K + k0 + c0c);
        cp16(dBh + (r1c*SEB + c1c)*2, Bgh + (long)(n0 + r1c)*K + k0 + c1c);
        cp16(dBl + (r0c*SEB + c0c)*2, Bgl + (long)(n0 + r0c)*K + k0 + c0c);
        cp16(dBl + (r1c*SEB + c1c)*2, Bgl + (long)(n0 + r1c)*K + k0 + c1c);
        asm volatile("cp.async.commit_group;");
    };

    float acc[4][4][4];
    #pragma unroll
    for (int i = 0; i < 4; i++)
        #pragma unroll
        for (int j = 0; j < 4; j++)
            #pragma unroll
            for (int r = 0; r < 4; r++) acc[i][j][r] = 0.0f;

    int t4 = lane >> 3, li = lane & 7;
    int a_row = (t4 & 1) * 8 + li,  a_col = (t4 >> 1) * 8;
    int b_row = (t4 >> 1) * 8 + li, b_col = (t4 & 1) * 8;

    int kt = K / BK2;
    issue(0);

    for (int kk = 0; kk < kt; kk++) {
        if (kk + 1 < kt) {
            issue(kk + 1);
            asm volatile("cp.async.wait_group 1;");
        } else {
            asm volatile("cp.async.wait_group 0;");
        }
        __syncthreads();

        int buf = kk & 1;
        uint32_t sA  = sbase + (buf*TSZ)*2;
        uint32_t sBh = sbase + ((2+buf)*TSZ)*2;
        uint32_t sBl = sbase + ((4+buf)*TSZ)*2;

        #pragma unroll
        for (int ks = 0; ks < 2; ks++) {
            int kc = ks * 16;
            uint32_t a[4][4], bh[2][4];
            #pragma unroll
            for (int tm = 0; tm < 4; tm++)
                ldm_x4(a[tm], sA + ((warp_m + tm*16 + a_row)*SEB + kc + a_col)*2);
            #pragma unroll
            for (int p = 0; p < 2; p++)
                ldm_x4(bh[p], sBh + ((warp_n + p*16 + b_row)*SEB + kc + b_col)*2);

            #pragma unroll
            for (int tm = 0; tm < 4; tm++)
                #pragma unroll
                for (int tn = 0; tn < 4; tn++) {
                    float* c = acc[tm][tn];
                    uint32_t* bb = bh[tn >> 1];
                    mma16816(c[0],c[1],c[2],c[3],
                             a[tm][0],a[tm][1],a[tm][2],a[tm][3],
                             bb[(tn&1)*2], bb[(tn&1)*2+1]);
                }

            uint32_t bl[2][4];
            #pragma unroll
            for (int p = 0; p < 2; p++)
                ldm_x4(bl[p], sBl + ((warp_n + p*16 + b_row)*SEB + kc + b_col)*2);
            #pragma unroll
            for (int tm = 0; tm < 4; tm++)
                #pragma unroll
                for (int tn = 0; tn < 4; tn++) {
                    float* c = acc[tm][tn];
                    uint32_t* bb = bl[tn >> 1];
                    mma16816(c[0],c[1],c[2],c[3],
                             a[tm][0],a[tm][1],a[tm][2],a[tm][3],
                             bb[(tn&1)*2], bb[(tn&1)*2+1]);
                }
        }
        __syncthreads();
    }

    /* epilogue */
    #pragma unroll
    for (int tn = 0; tn < 4; tn++) {
        int col = n0 + warp_n + tn * 8 + tig * 2;
        float b0 = bias ? bias[col]     : 0.0f;
        float b1 = bias ? bias[col + 1] : 0.0f;
        #pragma unroll
        for (int tm = 0; tm < 4; tm++) {
            int row0 = m0 + warp_m + tm * 16 + gid;
            float* c = acc[tm][tn];
            #pragma unroll
            for (int half = 0; half < 2; half++) {
                int row = row0 + half * 8;
                float v0 = c[half*2 + 0] + b0;
                float v1 = c[half*2 + 1] + b1;
                long off = (long)row * N + col;
                if (Ch) {
                    v0 = gelu_tanh(v0);
                    v1 = gelu_tanh(v1);
                    reinterpret_cast<uint32_t*>(Ch)[off >> 1] = pack1(v0, v1);
                } else {
                    if (Rsd) {
                        float2 r = *reinterpret_cast<const float2*>(Rsd + off);
                        v0 += r.x; v1 += r.y;
                    }
                    *reinterpret_cast<float2*>(Cf + off) = make_float2(v0, v1);
                }
            }
        }
    }
}

/* ---------------- launch --------------------------------------------------- */
extern "C" void kernel_launch(void* const* d_in, const int* in_sizes, int n_in,
                              void* d_out, int out_size)
{
    const float* x     = (const float*)d_in[0];
    const float* ln1s  = (const float*)d_in[1];
    const float* ln1b  = (const float*)d_in[2];
    const float* qkvw  = (const float*)d_in[3];
    const float* qkvb  = (const float*)d_in[4];
    const float* projw = (const float*)d_in[5];
    const float* projb = (const float*)d_in[6];
    const float* ln2s  = (const float*)d_in[7];
    const float* ln2b  = (const float*)d_in[8];
    const float* fc1w  = (const float*)d_in[9];
    const float* fc1b  = (const float*)d_in[10];
    const float* fc2w  = (const float*)d_in[11];
    const float* fc2b  = (const float*)d_in[12];
    float* out = (float*)d_out;

    hf *y, *att, *hb;
    hf *wqh, *wql, *wph, *wpl, *w1h, *w1l, *w2h, *w2l;
    float *qkv, *x1;
    cudaGetSymbolAddress((void**)&y,   g_y);
    cudaGetSymbolAddress((void**)&qkv, g_qkv);
    cudaGetSymbolAddress((void**)&att, g_att);
    cudaGetSymbolAddress((void**)&x1,  g_x1);
    cudaGetSymbolAddress((void**)&hb,  g_h);
    cudaGetSymbolAddress((void**)&wqh, g_wqh);
    cudaGetSymbolAddress((void**)&wql, g_wql);
    cudaGetSymbolAddress((void**)&wph, g_wph);
    cudaGetSymbolAddress((void**)&wpl, g_wpl);
    cudaGetSymbolAddress((void**)&w1h, g_w1h);
    cudaGetSymbolAddress((void**)&w1l, g_w1l);
    cudaGetSymbolAddress((void**)&w2h, g_w2h);
    cudaGetSymbolAddress((void**)&w2l, g_w2l);

    cudaFuncSetAttribute(flash_kernel,
        cudaFuncAttributeMaxDynamicSharedMemorySize, FA_SMEM);
    cudaFuncSetAttribute(gemm_hf,
        cudaFuncAttributeMaxDynamicSharedMemorySize, GEMM_SMEM);

    /* 0. weight transpose + split (fp16 hi/lo) */
    wt_kernel<<<dim3(3*DIM/32, DIM/32), dim3(32,8)>>>(qkvw, wqh, wql, DIM, 3*DIM);
    wt_kernel<<<dim3(DIM/32,   DIM/32), dim3(32,8)>>>(projw, wph, wpl, DIM, DIM);
    wt_kernel<<<dim3(HIDDEN/32,DIM/32), dim3(32,8)>>>(fc1w, w1h, w1l, DIM, HIDDEN);
    wt_kernel<<<dim3(DIM/32,HIDDEN/32), dim3(32,8)>>>(fc2w, w2h, w2l, HIDDEN, DIM);

    /* 1. LN1 -> y fp16 */
    ln_kernel<<<ROWS, 256>>>(x, ln1s, ln1b, y);

    /* 2. QKV = y @ Wq + b  (f32 out) */
    gemm_hf<<<dim3(3*DIM/BN, ROWS/BM), 256, GEMM_SMEM>>>(
        y, wqh, wql, qkvb, nullptr, qkv, nullptr,
        ROWS, 3*DIM, DIM);

    /* 3-5. flash attention -> att fp16 */
    flash_kernel<<<dim3(SEQ / BQ, BATCH * HEADS), 128, FA_SMEM>>>(qkv, att);

    /* 6. x1 = att @ Wp + b + x */
    gemm_hf<<<dim3(DIM/BN, ROWS/BM), 256, GEMM_SMEM>>>(
        att, wph, wpl, projb, x, x1, nullptr,
        ROWS, DIM, DIM);

    /* 7. LN2 -> y fp16 */
    ln_kernel<<<ROWS, 256>>>(x1, ln2s, ln2b, y);

    /* 8. h = gelu(y @ W1 + b)  (fp16 out) */
    gemm_hf<<<dim3(HIDDEN/BN, ROWS/BM), 256, GEMM_SMEM>>>(
        y, w1h, w1l, fc1b, nullptr, nullptr, hb,
        ROWS, HIDDEN, DIM);

    /* 9. out = h @ W2 + b + x1 */
    gemm_hf<<<dim3(DIM/BN, ROWS/BM), 256, GEMM_SMEM>>>(
        hb, w2h, w2l, fc2b, x1, out, nullptr,
        ROWS, DIM, HIDDEN);
}

// round 7
// speedup vs baseline: 6.3729x; 1.4307x over previous
#include <cuda_runtime.h>
#include <cuda_fp16.h>
#include <cstdint>

#define DIM    768
#define SEQ    1024
#define BATCH  8
#define ROWS   (BATCH*SEQ)      /* 8192 */
#define HEADS  12
#define HD     64
#define HIDDEN 3072
#define LN_EPS 1e-6f

typedef __half hf;

/* ---------------- scratch (static device globals; no allocations) -------- */
__device__ __align__(16) hf    g_y  [ROWS * DIM];       /* LN out, fp16 */
__device__ __align__(16) float g_qkv[ROWS * 3 * DIM];
__device__ __align__(16) hf    g_att[ROWS * DIM];       /* attention out */
__device__ __align__(16) float g_x1 [ROWS * DIM];
__device__ __align__(16) hf    g_h  [ROWS * HIDDEN];    /* fc1 out */
/* transposed fp16 weights, [N][K] */
__device__ __align__(16) hf g_wq[3*DIM*DIM];
__device__ __align__(16) hf g_wp[DIM*DIM];
__device__ __align__(16) hf g_w1[HIDDEN*DIM];
__device__ __align__(16) hf g_w2[DIM*HIDDEN];

/* ---------------- helpers -------------------------------------------------- */
__device__ __forceinline__ float gelu_tanh(float u)
{
    return 0.5f * u * (1.0f + tanhf(0.7978845608028654f * (u + 0.044715f * u * u * u)));
}

__device__ __forceinline__ void mma16816(
    float& c0, float& c1, float& c2, float& c3,
    uint32_t a0, uint32_t a1, uint32_t a2, uint32_t a3,
    uint32_t b0, uint32_t b1)
{
    asm volatile(
        "mma.sync.aligned.m16n8k16.row.col.f32.f16.f16.f32 "
        "{%0,%1,%2,%3},{%4,%5,%6,%7},{%8,%9},{%0,%1,%2,%3};"
        : "+f"(c0), "+f"(c1), "+f"(c2), "+f"(c3)
        : "r"(a0), "r"(a1), "r"(a2), "r"(a3), "r"(b0), "r"(b1));
}

__device__ __forceinline__ uint32_t pack1(float x0, float x1)
{
    hf h0 = __float2half_rn(x0), h1 = __float2half_rn(x1);
    return ((uint32_t)__half_as_ushort(h1) << 16) | __half_as_ushort(h0);
}

__device__ __forceinline__ void pack_hl(float x0, float x1, uint32_t& hi, uint32_t& lo)
{
    hf h0 = __float2half_rn(x0), h1 = __float2half_rn(x1);
    float r0 = x0 - __half2float(h0);
    float r1 = x1 - __half2float(h1);
    hi = ((uint32_t)__half_as_ushort(h1) << 16) | __half_as_ushort(h0);
    lo = pack1(r0, r1);
}

/* 8 floats -> single fp16 uint4 */
__device__ __forceinline__ uint4 cvt8s(const float* f)
{
    return make_uint4(pack1(f[0], f[1]), pack1(f[2], f[3]),
                      pack1(f[4], f[5]), pack1(f[6], f[7]));
}

__device__ __forceinline__ void cp16(uint32_t s, const void* g)
{
    asm volatile("cp.async.cg.shared.global [%0], [%1], 16;" :: "r"(s), "l"(g));
}
__device__ __forceinline__ void ldm_x4(uint32_t* r, uint32_t addr)
{
    asm volatile("ldmatrix.sync.aligned.m8n8.x4.shared.b16 {%0,%1,%2,%3}, [%4];"
        : "=r"(r[0]), "=r"(r[1]), "=r"(r[2]), "=r"(r[3]) : "r"(addr));
}

/* ---------------- weight transpose: W[K][N] -> T[N][K] fp16 ---------------- */
__global__ void __launch_bounds__(256) wt_kernel(
    const float* __restrict__ W, hf* __restrict__ Th, int K, int N)
{
    __shared__ float s[32][33];
    int tx = threadIdx.x, ty = threadIdx.y;
    int n0 = blockIdx.x * 32, k0 = blockIdx.y * 32;
    #pragma unroll
    for (int j = 0; j < 4; j++)
        s[ty + j*8][tx] = W[(long)(k0 + ty + j*8) * N + n0 + tx];
    __syncthreads();
    #pragma unroll
    for (int j = 0; j < 4; j++) {
        long o = (long)(n0 + ty + j*8) * K + k0 + tx;
        Th[o] = __float2half_rn(s[tx][ty + j*8]);
    }
}

/* ---------------- layernorm -> single fp16 --------------------------------- */
__global__ void __launch_bounds__(256) ln_kernel(
    const float* __restrict__ x, const float* __restrict__ sc,
    const float* __restrict__ bi, hf* __restrict__ y)
{
    long row = blockIdx.x;
    int  t   = threadIdx.x;
    const float* xr = x + row * DIM;
    float v0 = xr[t], v1 = xr[t + 256], v2 = xr[t + 512];

    __shared__ float sbuf[8];
    __shared__ float s_mu, s_r;

    float s = v0 + v1 + v2;
    #pragma unroll
    for (int o = 16; o > 0; o >>= 1) s += __shfl_xor_sync(0xffffffffu, s, o);
    if ((t & 31) == 0) sbuf[t >> 5] = s;
    __syncthreads();
    if (t < 8) {
        float r = sbuf[t];
        #pragma unroll
        for (int o = 4; o > 0; o >>= 1) r += __shfl_xor_sync(0xffu, r, o);
        if (t == 0) s_mu = r * (1.0f / DIM);
    }
    __syncthreads();
    float mu = s_mu;
    float d0 = v0 - mu, d1 = v1 - mu, d2 = v2 - mu;
    float q = d0*d0 + d1*d1 + d2*d2;
    #pragma unroll
    for (int o = 16; o > 0; o >>= 1) q += __shfl_xor_sync(0xffffffffu, q, o);
    if ((t & 31) == 0) sbuf[t >> 5] = q;
    __syncthreads();
    if (t < 8) {
        float r = sbuf[t];
        #pragma unroll
        for (int o = 4; o > 0; o >>= 1) r += __shfl_xor_sync(0xffu, r, o);
        if (t == 0) s_r = rsqrtf(r * (1.0f / DIM) + LN_EPS);
    }
    __syncthreads();
    float rs = s_r;
    long base = row * DIM;
    y[base + t      ] = __float2half_rn(d0 * rs * sc[t      ] + bi[t      ]);
    y[base + t + 256] = __float2half_rn(d1 * rs * sc[t + 256] + bi[t + 256]);
    y[base + t + 512] = __float2half_rn(d2 * rs * sc[t + 512] + bi[t + 512]);
}

/* ================= flash attention (fp16) ==================================
 * Q single fp16 (pre-scaled), K single, V single transposed, P split hi/lo.
 * S = Q@K : 1 mma ; O += (Ph+Pl)@V : 2 mma.
 */
#define BQ  128
#define BKV 64
#define QST 72
#define SQ_ELE (BQ*QST)
#define SK_ELE (BKV*QST)
#define FA_SMEM ((SQ_ELE + 2*SK_ELE) * 2)     /* 36864 B */

__global__ void __launch_bounds__(128) flash_kernel(
    const float* __restrict__ qkv, hf* __restrict__ att)
{
    extern __shared__ hf sm[];
    hf* Qs = sm;
    hf* Ks = Qs + SQ_ELE;
    hf* Vs = Ks + SK_ELE;
    uint32_t* KW = reinterpret_cast<uint32_t*>(Ks);
    uint32_t* VW = reinterpret_cast<uint32_t*>(Vs);

    int t = threadIdx.x, lane = t & 31, wid = t >> 5;
    int gid = lane >> 2, tig = lane & 3;
    int bh = blockIdx.y, b = bh / HEADS, h = bh % HEADS;
    int q0 = blockIdx.x * BQ;

    const float* Qp = qkv + ((long)b * SEQ + q0) * (3*DIM) + h * HD;
    const float* Kp = qkv + (long)b * SEQ * (3*DIM) + DIM     + h * HD;
    const float* Vp = qkv + (long)b * SEQ * (3*DIM) + 2*DIM   + h * HD;

    /* Q preload: one row per thread, scaled, single fp16 */
    {
        const float* qr = Qp + (long)t * (3*DIM);
        #pragma unroll
        for (int c = 0; c < HD; c += 8) {
            float4 u0 = *reinterpret_cast<const float4*>(qr + c);
            float4 u1 = *reinterpret_cast<const float4*>(qr + c + 4);
            float f[8] = {u0.x*0.125f, u0.y*0.125f, u0.z*0.125f, u0.w*0.125f,
                          u1.x*0.125f, u1.y*0.125f, u1.z*0.125f, u1.w*0.125f};
            *reinterpret_cast<uint4*>(&Qs[t*QST + c]) = cvt8s(f);
        }
    }

    float acc[2][8][4];
    float oacc[2][8][4];
    float mrow[2][2], lrow[2][2];
    #pragma unroll
    for (int i = 0; i < 2; i++) {
        mrow[i][0] = mrow[i][1] = -1e30f;
        lrow[i][0] = lrow[i][1] = 0.0f;
        #pragma unroll
        for (int j = 0; j < 8; j++)
            #pragma unroll
            for (int r = 0; r < 4; r++) oacc[i][j][r] = 0.0f;
    }

    int wm = wid * 32;
    int kr = t >> 1, kh = (t & 1) * 32;
    float kreg[32];
    int vrp = t & 31, vdb = (t >> 5) * 16;
    float vreg[32];

    auto loadK = [&](int it) {
        const float* p = Kp + (long)(it * BKV + kr) * (3*DIM) + kh;
        #pragma unroll
        for (int i = 0; i < 8; i++) {
            float4 v = *reinterpret_cast<const float4*>(p + i*4);
            kreg[i*4] = v.x; kreg[i*4+1] = v.y; kreg[i*4+2] = v.z; kreg[i*4+3] = v.w;
        }
    };
    auto loadV = [&](int it) {
        const float* p0 = Vp + (long)(it * BKV + 2*vrp) * (3*DIM) + vdb;
        const float* p1 = p0 + 3*DIM;
        #pragma unroll
        for (int i = 0; i < 4; i++) {
            float4 a = *reinterpret_cast<const float4*>(p0 + i*4);
            float4 c = *reinterpret_cast<const float4*>(p1 + i*4);
            vreg[i*4] = a.x; vreg[i*4+1] = a.y; vreg[i*4+2] = a.z; vreg[i*4+3] = a.w;
            vreg[16+i*4] = c.x; vreg[16+i*4+1] = c.y; vreg[16+i*4+2] = c.z; vreg[16+i*4+3] = c.w;
        }
    };

    loadK(0);

    for (int it = 0; it < SEQ / BKV; it++) {
        __syncthreads();
        /* store K tile (single fp16) */
        #pragma unroll
        for (int i = 0; i < 4; i++) {
            uint4 s4 = cvt8s(kreg + i*8);
            *reinterpret_cast<uint4*>(&KW[(kr*QST + kh)/2 + i*4]) = s4;
        }
        loadV(it);
        __syncthreads();

        #pragma unroll
        for (int i = 0; i < 2; i++)
            #pragma unroll
            for (int j = 0; j < 8; j++)
                #pragma unroll
                for (int r = 0; r < 4; r++) acc[i][j][r] = 0.0f;

        /* S = Q @ K^T (single term) */
        #pragma unroll
        for (int ks = 0; ks < 4; ks++) {
            uint32_t qa[2][4];
            #pragma unroll
            for (int tm = 0; tm < 2; tm++) {
                int row = wm + tm*16 + gid;
                qa[tm][0] = *reinterpret_cast<const uint32_t*>(&Qs[ row    *QST + ks*16 + tig*2    ]);
                qa[tm][1] = *reinterpret_cast<const uint32_t*>(&Qs[(row+8)*QST + ks*16 + tig*2    ]);
                qa[tm][2] = *reinterpret_cast<const uint32_t*>(&Qs[ row    *QST + ks*16 + tig*2 + 8]);
                qa[tm][3] = *reinterpret_cast<const uint32_t*>(&Qs[(row+8)*QST + ks*16 + tig*2 + 8]);
            }
            #pragma unroll
            for (int tn = 0; tn < 8; tn++) {
                int nr = tn*8 + gid;
                uint32_t b0 = *reinterpret_cast<const uint32_t*>(&Ks[nr*QST + ks*16 + tig*2    ]);
                uint32_t b1 = *reinterpret_cast<const uint32_t*>(&Ks[nr*QST + ks*16 + tig*2 + 8]);
                #pragma unroll
                for (int tm = 0; tm < 2; tm++) {
                    float* c = acc[tm][tn];
                    mma16816(c[0],c[1],c[2],c[3], qa[tm][0],qa[tm][1],qa[tm][2],qa[tm][3], b0,b1);
                }
            }
        }

        /* online softmax update */
        #pragma unroll
        for (int tm = 0; tm < 2; tm++) {
            float mx0 = -1e30f, mx1 = -1e30f;
            #pragma unroll
            for (int tn = 0; tn < 8; tn++) {
                mx0 = fmaxf(mx0, fmaxf(acc[tm][tn][0], acc[tm][tn][1]));
                mx1 = fmaxf(mx1, fmaxf(acc[tm][tn][2], acc[tm][tn][3]));
            }
            #pragma unroll
            for (int o = 1; o <= 2; o <<= 1) {
                mx0 = fmaxf(mx0, __shfl_xor_sync(0xffffffffu, mx0, o));
                mx1 = fmaxf(mx1, __shfl_xor_sync(0xffffffffu, mx1, o));
            }
            float mn0 = fmaxf(mrow[tm][0], mx0);
            float mn1 = fmaxf(mrow[tm][1], mx1);
            float sc0 = __expf(mrow[tm][0] - mn0);
            float sc1 = __expf(mrow[tm][1] - mn1);
            float ls0 = 0.0f, ls1 = 0.0f;
            #pragma unroll
            for (int tn = 0; tn < 8; tn++) {
                float* c = acc[tm][tn];
                c[0] = __expf(c[0] - mn0);
                c[1] = __expf(c[1] - mn0);
                c[2] = __expf(c[2] - mn1);
                c[3] = __expf(c[3] - mn1);
                ls0 += c[0] + c[1];
                ls1 += c[2] + c[3];
            }
            #pragma unroll
            for (int o = 1; o <= 2; o <<= 1) {
                ls0 += __shfl_xor_sync(0xffffffffu, ls0, o);
                ls1 += __shfl_xor_sync(0xffffffffu, ls1, o);
            }
            lrow[tm][0] = lrow[tm][0] * sc0 + ls0;
            lrow[tm][1] = lrow[tm][1] * sc1 + ls1;
            mrow[tm][0] = mn0;
            mrow[tm][1] = mn1;
            #pragma unroll
            for (int to = 0; to < 8; to++) {
                oacc[tm][to][0] *= sc0; oacc[tm][to][1] *= sc0;
                oacc[tm][to][2] *= sc1; oacc[tm][to][3] *= sc1;
            }
        }

        /* store V tile transposed (single fp16, pair-packed) */
        #pragma unroll
        for (int j = 0; j < 16; j++)
            VW[(vdb + j) * (QST/2) + vrp] = pack1(vreg[j], vreg[16 + j]);
        if (it + 1 < SEQ / BKV) loadK(it + 1);
        __syncthreads();

        /* O += (Ph + Pl) @ V */
        #pragma unroll
        for (int j = 0; j < 4; j++) {
            uint32_t pH[2][4], pL[2][4];
            #pragma unroll
            for (int tm = 0; tm < 2; tm++) {
                pack_hl(acc[tm][2*j  ][0], acc[tm][2*j  ][1], pH[tm][0], pL[tm][0]);
                pack_hl(acc[tm][2*j  ][2], acc[tm][2*j  ][3], pH[tm][1], pL[tm][1]);
                pack_hl(acc[tm][2*j+1][0], acc[tm][2*j+1][1], pH[tm][2], pL[tm][2]);
                pack_hl(acc[tm][2*j+1][2], acc[tm][2*j+1][3], pH[tm][3], pL[tm][3]);
            }
            #pragma unroll
            for (int to = 0; to < 8; to++) {
                int d = to*8 + gid;
                uint32_t b0 = *reinterpret_cast<const uint32_t*>(&Vs[d*QST + j*16 + tig*2    ]);
                uint32_t b1 = *reinterpret_cast<const uint32_t*>(&Vs[d*QST + j*16 + tig*2 + 8]);
                #pragma unroll
                for (int tm = 0; tm < 2; tm++) {
                    float* c = oacc[tm][to];
                    mma16816(c[0],c[1],c[2],c[3], pH[tm][0],pH[tm][1],pH[tm][2],pH[tm][3], b0,b1);
                    mma16816(c[0],c[1],c[2],c[3], pL[tm][0],pL[tm][1],pL[tm][2],pL[tm][3], b0,b1);
                }
            }
        }
    }

    /* epilogue: O / l -> att (single fp16) */
    uint32_t* AW = reinterpret_cast<uint32_t*>(att);
    #pragma unroll
    for (int tm = 0; tm < 2; tm++) {
        float inv0 = 1.0f / lrow[tm][0];
        float inv1 = 1.0f / lrow[tm][1];
        int row = q0 + wm + tm*16 + gid;
        #pragma unroll
        for (int to = 0; to < 8; to++) {
            int col = h*HD + to*8 + tig*2;
            float* c = oacc[tm][to];
            long o0 = (((long)b*SEQ + row    ) * DIM + col) >> 1;
            long o1 = (((long)b*SEQ + row + 8) * DIM + col) >> 1;
            AW[o0] = pack1(c[0]*inv0, c[1]*inv0);
            AW[o1] = pack1(c[2]*inv1, c[3]*inv1);
        }
    }
}

/* ================= dense GEMM: pure fp16 ===================================
 * Block 128x128, BK=32, 256 thr (8 warps, warp tile 64x32), 2 CTAs/SM.
 * C = A @ B^T + bias [+residual -> f32] or gelu -> fp16.
 */
#define BM  128
#define BN  128
#define BK2 32
#define SEB 40
#define TSZ (BM*SEB)              /* 5120 half per tile-buffer */
#define GEMM_SMEM (4*TSZ*2)       /* 40960 bytes */

__global__ void __launch_bounds__(256, 2) gemm_hf(
    const hf* __restrict__ Ag, const hf* __restrict__ Bg,
    const float* __restrict__ bias, const float* __restrict__ Rsd,
    float* __restrict__ Cf, hf* __restrict__ Ch,
    int M, int N, int K)
{
    extern __shared__ hf gsm[];
    /* layout: [A0 A1 B0 B1], each TSZ */
    uint32_t sbase = (uint32_t)__cvta_generic_to_shared(gsm);

    int m0 = blockIdx.y * BM;
    int n0 = blockIdx.x * BN;
    int t  = threadIdx.x;
    int lane = t & 31, wid = t >> 5;
    int gid = lane >> 2, tig = lane & 3;
    int warp_m = (wid >> 2) << 6;
    int warp_n = (wid & 3) << 5;

    int r0c = t >> 2,         c0c = (t & 3) * 8;
    int r1c = (t >> 2) + 64;

    auto issue = [&](int kk) {
        int buf = kk & 1;
        long k0 = (long)kk * BK2;
        uint32_t dA = sbase + (buf*TSZ)*2;
        uint32_t dB = sbase + ((2+buf)*TSZ)*2;
        cp16(dA + (r0c*SEB + c0c)*2, Ag + (long)(m0 + r0c)*K + k0 + c0c);
        cp16(dA + (r1c*SEB + c0c)*2, Ag + (long)(m0 + r1c)*K + k0 + c0c);
        cp16(dB + (r0c*SEB + c0c)*2, Bg + (long)(n0 + r0c)*K + k0 + c0c);
        cp16(dB + (r1c*SEB + c0c)*2, Bg + (long)(n0 + r1c)*K + k0 + c0c);
        asm volatile("cp.async.commit_group;");
    };

    float acc[4][4][4];
    #pragma unroll
    for (int i = 0; i < 4; i++)
        #pragma unroll
        for (int j = 0; j < 4; j++)
            #pragma unroll
            for (int r = 0; r < 4; r++) acc[i][j][r] = 0.0f;

    int t4 = lane >> 3, li = lane & 7;
    int a_row = (t4 & 1) * 8 + li,  a_col = (t4 >> 1) * 8;
    int b_row = (t4 >> 1) * 8 + li, b_col = (t4 & 1) * 8;

    int kt = K / BK2;
    issue(0);

    for (int kk = 0; kk < kt; kk++) {
        if (kk + 1 < kt) {
            issue(kk + 1);
            asm volatile("cp.async.wait_group 1;");
        } else {
            asm volatile("cp.async.wait_group 0;");
        }
        __syncthreads();

        int buf = kk & 1;
        uint32_t sA = sbase + (buf*TSZ)*2;
        uint32_t sB = sbase + ((2+buf)*TSZ)*2;

        #pragma unroll
        for (int ks = 0; ks < 2; ks++) {
            int kc = ks * 16;
            uint32_t a[4][4], bb2[2][4];
            #pragma unroll
            for (int tm = 0; tm < 4; tm++)
                ldm_x4(a[tm], sA + ((warp_m + tm*16 + a_row)*SEB + kc + a_col)*2);
            #pragma unroll
            for (int p = 0; p < 2; p++)
                ldm_x4(bb2[p], sB + ((warp_n + p*16 + b_row)*SEB + kc + b_col)*2);

            #pragma unroll
            for (int tm = 0; tm < 4; tm++)
                #pragma unroll
                for (int tn = 0; tn < 4; tn++) {
                    float* c = acc[tm][tn];
                    uint32_t* bb = bb2[tn >> 1];
                    mma16816(c[0],c[1],c[2],c[3],
                             a[tm][0],a[tm][1],a[tm][2],a[tm][3],
                             bb[(tn&1)*2], bb[(tn&1)*2+1]);
                }
        }
        __syncthreads();
    }

    /* epilogue */
    #pragma unroll
    for (int tn = 0; tn < 4; tn++) {
        int col = n0 + warp_n + tn * 8 + tig * 2;
        float b0 = bias ? bias[col]     : 0.0f;
        float b1 = bias ? bias[col + 1] : 0.0f;
        #pragma unroll
        for (int tm = 0; tm < 4; tm++) {
            int row0 = m0 + warp_m + tm * 16 + gid;
            float* c = acc[tm][tn];
            #pragma unroll
            for (int half = 0; half < 2; half++) {
                int row = row0 + half * 8;
                float v0 = c[half*2 + 0] + b0;
                float v1 = c[half*2 + 1] + b1;
                long off = (long)row * N + col;
                if (Ch) {
                    v0 = gelu_tanh(v0);
                    v1 = gelu_tanh(v1);
                    reinterpret_cast<uint32_t*>(Ch)[off >> 1] = pack1(v0, v1);
                } else {
                    if (Rsd) {
                        float2 r = *reinterpret_cast<const float2*>(Rsd + off);
                        v0 += r.x; v1 += r.y;
                    }
                    *reinterpret_cast<float2*>(Cf + off) = make_float2(v0, v1);
                }
            }
        }
    }
}

/* ---------------- launch --------------------------------------------------- */
extern "C" void kernel_launch(void* const* d_in, const int* in_sizes, int n_in,
                              void* d_out, int out_size)
{
    const float* x     = (const float*)d_in[0];
    const float* ln1s  = (const float*)d_in[1];
    const float* ln1b  = (const float*)d_in[2];
    const float* qkvw  = (const float*)d_in[3];
    const float* qkvb  = (const float*)d_in[4];
    const float* projw = (const float*)d_in[5];
    const float* projb = (const float*)d_in[6];
    const float* ln2s  = (const float*)d_in[7];
    const float* ln2b  = (const float*)d_in[8];
    const float* fc1w  = (const float*)d_in[9];
    const float* fc1b  = (const float*)d_in[10];
    const float* fc2w  = (const float*)d_in[11];
    const float* fc2b  = (const float*)d_in[12];
    float* out = (float*)d_out;

    hf *y, *att, *hb, *wq, *wp, *w1, *w2;
    float *qkv, *x1;
    cudaGetSymbolAddress((void**)&y,   g_y);
    cudaGetSymbolAddress((void**)&qkv, g_qkv);
    cudaGetSymbolAddress((void**)&att, g_att);
    cudaGetSymbolAddress((void**)&x1,  g_x1);
    cudaGetSymbolAddress((void**)&hb,  g_h);
    cudaGetSymbolAddress((void**)&wq,  g_wq);
    cudaGetSymbolAddress((void**)&wp,  g_wp);
    cudaGetSymbolAddress((void**)&w1,  g_w1);
    cudaGetSymbolAddress((void**)&w2,  g_w2);

    cudaFuncSetAttribute(flash_kernel,
        cudaFuncAttributeMaxDynamicSharedMemorySize, FA_SMEM);
    cudaFuncSetAttribute(gemm_hf,
        cudaFuncAttributeMaxDynamicSharedMemorySize, GEMM_SMEM);

    /* 0. weight transpose (fp16) */
    wt_kernel<<<dim3(3*DIM/32, DIM/32), dim3(32,8)>>>(qkvw, wq, DIM, 3*DIM);
    wt_kernel<<<dim3(DIM/32,   DIM/32), dim3(32,8)>>>(projw, wp, DIM, DIM);
    wt_kernel<<<dim3(HIDDEN/32,DIM/32), dim3(32,8)>>>(fc1w, w1, DIM, HIDDEN);
    wt_kernel<<<dim3(DIM/32,HIDDEN/32), dim3(32,8)>>>(fc2w, w2, HIDDEN, DIM);

    /* 1. LN1 -> y fp16 */
    ln_kernel<<<ROWS, 256>>>(x, ln1s, ln1b, y);

    /* 2. QKV = y @ Wq + b  (f32 out) */
    gemm_hf<<<dim3(3*DIM/BN, ROWS/BM), 256, GEMM_SMEM>>>(
        y, wq, qkvb, nullptr, qkv, nullptr,
        ROWS, 3*DIM, DIM);

    /* 3-5. flash attention -> att fp16 */
    flash_kernel<<<dim3(SEQ / BQ, BATCH * HEADS), 128, FA_SMEM>>>(qkv, att);

    /* 6. x1 = att @ Wp + b + x */
    gemm_hf<<<dim3(DIM/BN, ROWS/BM), 256, GEMM_SMEM>>>(
        att, wp, projb, x, x1, nullptr,
        ROWS, DIM, DIM);

    /* 7. LN2 -> y fp16 */
    ln_kernel<<<ROWS, 256>>>(x1, ln2s, ln2b, y);

    /* 8. h = gelu(y @ W1 + b)  (fp16 out) */
    gemm_hf<<<dim3(HIDDEN/BN, ROWS/BM), 256, GEMM_SMEM>>>(
        y, w1, fc1b, nullptr, nullptr, hb,
        ROWS, HIDDEN, DIM);

    /* 9. out = h @ W2 + b + x1 */
    gemm_hf<<<dim3(DIM/BN, ROWS/BM), 256, GEMM_SMEM>>>(
        hb, w2, fc2b, x1, out, nullptr,
        ROWS, DIM, HIDDEN);
}

// round 8
// speedup vs baseline: 7.2777x; 1.1420x over previous
#include <cuda_runtime.h>
#include <cuda_fp16.h>
#include <cstdint>

#define DIM    768
#define SEQ    1024
#define BATCH  8
#define ROWS   (BATCH*SEQ)      /* 8192 */
#define HEADS  12
#define HD     64
#define HIDDEN 3072
#define LN_EPS 1e-6f

typedef __half hf;

/* ---------------- scratch (static device globals; no allocations) -------- */
__device__ __align__(16) hf    g_y  [ROWS * DIM];       /* LN out, fp16 */
__device__ __align__(16) hf    g_qkv[ROWS * 3 * DIM];   /* QKV, fp16 */
__device__ __align__(16) hf    g_att[ROWS * DIM];       /* attention out */
__device__ __align__(16) float g_x1 [ROWS * DIM];
__device__ __align__(16) hf    g_h  [ROWS * HIDDEN];    /* fc1 out */
/* transposed fp16 weights, [N][K] */
__device__ __align__(16) hf g_wq[3*DIM*DIM];
__device__ __align__(16) hf g_wp[DIM*DIM];
__device__ __align__(16) hf g_w1[HIDDEN*DIM];
__device__ __align__(16) hf g_w2[DIM*HIDDEN];

/* ---------------- helpers -------------------------------------------------- */
__device__ __forceinline__ float gelu_tanh(float u)
{
    return 0.5f * u * (1.0f + tanhf(0.7978845608028654f * (u + 0.044715f * u * u * u)));
}

__device__ __forceinline__ void mma16816(
    float& c0, float& c1, float& c2, float& c3,
    uint32_t a0, uint32_t a1, uint32_t a2, uint32_t a3,
    uint32_t b0, uint32_t b1)
{
    asm volatile(
        "mma.sync.aligned.m16n8k16.row.col.f32.f16.f16.f32 "
        "{%0,%1,%2,%3},{%4,%5,%6,%7},{%8,%9},{%0,%1,%2,%3};"
        : "+f"(c0), "+f"(c1), "+f"(c2), "+f"(c3)
        : "r"(a0), "r"(a1), "r"(a2), "r"(a3), "r"(b0), "r"(b1));
}

__device__ __forceinline__ uint32_t pack1(float x0, float x1)
{
    hf h0 = __float2half_rn(x0), h1 = __float2half_rn(x1);
    return ((uint32_t)__half_as_ushort(h1) << 16) | __half_as_ushort(h0);
}

__device__ __forceinline__ void pack_hl(float x0, float x1, uint32_t& hi, uint32_t& lo)
{
    hf h0 = __float2half_rn(x0), h1 = __float2half_rn(x1);
    float r0 = x0 - __half2float(h0);
    float r1 = x1 - __half2float(h1);
    hi = ((uint32_t)__half_as_ushort(h1) << 16) | __half_as_ushort(h0);
    lo = pack1(r0, r1);
}

__device__ __forceinline__ void cp16(uint32_t s, const void* g)
{
    asm volatile("cp.async.cg.shared.global [%0], [%1], 16;" :: "r"(s), "l"(g));
}
__device__ __forceinline__ void ldm_x4(uint32_t* r, uint32_t addr)
{
    asm volatile("ldmatrix.sync.aligned.m8n8.x4.shared.b16 {%0,%1,%2,%3}, [%4];"
        : "=r"(r[0]), "=r"(r[1]), "=r"(r[2]), "=r"(r[3]) : "r"(addr));
}

/* ---------------- weight transpose: W[K][N] -> T[N][K] fp16 ---------------- */
__global__ void __launch_bounds__(256) wt_kernel(
    const float* __restrict__ W, hf* __restrict__ Th, int K, int N)
{
    __shared__ float s[32][33];
    int tx = threadIdx.x, ty = threadIdx.y;
    int n0 = blockIdx.x * 32, k0 = blockIdx.y * 32;
    #pragma unroll
    for (int j = 0; j < 4; j++)
        s[ty + j*8][tx] = W[(long)(k0 + ty + j*8) * N + n0 + tx];
    __syncthreads();
    #pragma unroll
    for (int j = 0; j < 4; j++) {
        long o = (long)(n0 + ty + j*8) * K + k0 + tx;
        Th[o] = __float2half_rn(s[tx][ty + j*8]);
    }
}

/* ---------------- layernorm -> single fp16 --------------------------------- */
__global__ void __launch_bounds__(256) ln_kernel(
    const float* __restrict__ x, const float* __restrict__ sc,
    const float* __restrict__ bi, hf* __restrict__ y)
{
    long row = blockIdx.x;
    int  t   = threadIdx.x;
    const float* xr = x + row * DIM;
    float v0 = xr[t], v1 = xr[t + 256], v2 = xr[t + 512];

    __shared__ float sbuf[8];
    __shared__ float s_mu, s_r;

    float s = v0 + v1 + v2;
    #pragma unroll
    for (int o = 16; o > 0; o >>= 1) s += __shfl_xor_sync(0xffffffffu, s, o);
    if ((t & 31) == 0) sbuf[t >> 5] = s;
    __syncthreads();
    if (t < 8) {
        float r = sbuf[t];
        #pragma unroll
        for (int o = 4; o > 0; o >>= 1) r += __shfl_xor_sync(0xffu, r, o);
        if (t == 0) s_mu = r * (1.0f / DIM);
    }
    __syncthreads();
    float mu = s_mu;
    float d0 = v0 - mu, d1 = v1 - mu, d2 = v2 - mu;
    float q = d0*d0 + d1*d1 + d2*d2;
    #pragma unroll
    for (int o = 16; o > 0; o >>= 1) q += __shfl_xor_sync(0xffffffffu, q, o);
    if ((t & 31) == 0) sbuf[t >> 5] = q;
    __syncthreads();
    if (t < 8) {
        float r = sbuf[t];
        #pragma unroll
        for (int o = 4; o > 0; o >>= 1) r += __shfl_xor_sync(0xffu, r, o);
        if (t == 0) s_r = rsqrtf(r * (1.0f / DIM) + LN_EPS);
    }
    __syncthreads();
    float rs = s_r;
    long base = row * DIM;
    y[base + t      ] = __float2half_rn(d0 * rs * sc[t      ] + bi[t      ]);
    y[base + t + 256] = __float2half_rn(d1 * rs * sc[t + 256] + bi[t + 256]);
    y[base + t + 512] = __float2half_rn(d2 * rs * sc[t + 512] + bi[t + 512]);
}

/* ================= flash attention (fp16 qkv in) ===========================
 * Q, K via cp.async (K double buffered). V manual transposed store.
 * S = Q@K (1 mma, scaled by 0.125 post-mma); O += (Ph+Pl)@V (2 mma).
 */
#define BQ  128
#define BKV 64
#define QST 72
#define SQ_ELE (BQ*QST)             /* 9216 halves  */
#define SK_ELE (BKV*QST)            /* 4608 halves  */
#define FA_SMEM ((SQ_ELE + 2*SK_ELE + SK_ELE) * 2)   /* 46080 B */

__global__ void __launch_bounds__(128) flash_kernel(
    const hf* __restrict__ qkv, hf* __restrict__ att)
{
    extern __shared__ hf sm[];
    hf* Qs  = sm;
    hf* Ks0 = Qs + SQ_ELE;          /* two K buffers */
    hf* Vs  = Ks0 + 2*SK_ELE;
    uint32_t* VW = reinterpret_cast<uint32_t*>(Vs);
    uint32_t sQ, sK0, sV;
    {
        uint32_t base = (uint32_t)__cvta_generic_to_shared(sm);
        sQ = base; sK0 = base + SQ_ELE*2; sV = sK0 + 2*SK_ELE*2;
    }
    (void)sV;

    int t = threadIdx.x, lane = t & 31, wid = t >> 5;
    int gid = lane >> 2, tig = lane & 3;
    int bh = blockIdx.y, b = bh / HEADS, h = bh % HEADS;
    int q0 = blockIdx.x * BQ;

    const hf* Qp = qkv + ((long)b * SEQ + q0) * (3*DIM) + h * HD;
    const hf* Kp = qkv + (long)b * SEQ * (3*DIM) + DIM     + h * HD;
    const hf* Vp = qkv + (long)b * SEQ * (3*DIM) + 2*DIM   + h * HD;

    /* cp.async loaders */
    auto issueQ = [&]() {
        #pragma unroll
        for (int i = 0; i < 8; i++) {
            int g = t + i * 128;
            int row = g >> 3, c = g & 7;
            cp16(sQ + (row*QST + c*8)*2, Qp + (long)row*(3*DIM) + c*8);
        }
    };
    auto issueK = [&](int it) {
        uint32_t kb = sK0 + (it & 1) * (SK_ELE*2);
        #pragma unroll
        for (int i = 0; i < 4; i++) {
            int g = t + i * 128;
            int row = g >> 3, c = g & 7;
            cp16(kb + (row*QST + c*8)*2, Kp + (long)(it*BKV + row)*(3*DIM) + c*8);
        }
        asm volatile("cp.async.commit_group;");
    };

    /* V loader: rows 2vrp,2vrp+1 cols vdb..vdb+15 (fp16) */
    int vrp = t & 31, vdb = (t >> 5) * 16;
    uint32_t va[8], vb[8];
    auto loadV = [&](int it) {
        const hf* p0 = Vp + (long)(it * BKV + 2*vrp) * (3*DIM) + vdb;
        const hf* p1 = p0 + 3*DIM;
        uint4 a0 = *reinterpret_cast<const uint4*>(p0);
        uint4 a1 = *reinterpret_cast<const uint4*>(p0 + 8);
        uint4 b0 = *reinterpret_cast<const uint4*>(p1);
        uint4 b1 = *reinterpret_cast<const uint4*>(p1 + 8);
        va[0]=a0.x; va[1]=a0.y; va[2]=a0.z; va[3]=a0.w;
        va[4]=a1.x; va[5]=a1.y; va[6]=a1.z; va[7]=a1.w;
        vb[0]=b0.x; vb[1]=b0.y; vb[2]=b0.z; vb[3]=b0.w;
        vb[4]=b1.x; vb[5]=b1.y; vb[6]=b1.z; vb[7]=b1.w;
    };

    issueQ();
    issueK(0);
    loadV(0);

    float acc[2][8][4];
    float oacc[2][8][4];
    float mrow[2][2], lrow[2][2];
    #pragma unroll
    for (int i = 0; i < 2; i++) {
        mrow[i][0] = mrow[i][1] = -1e30f;
        lrow[i][0] = lrow[i][1] = 0.0f;
        #pragma unroll
        for (int j = 0; j < 8; j++)
            #pragma unroll
            for (int r = 0; r < 4; r++) oacc[i][j][r] = 0.0f;
    }

    int wm = wid * 32;

    for (int it = 0; it < SEQ / BKV; it++) {
        asm volatile("cp.async.wait_group 0;");
        __syncthreads();
        hf* Ks = Ks0 + (it & 1) * SK_ELE;

        #pragma unroll
        for (int i = 0; i < 2; i++)
            #pragma unroll
            for (int j = 0; j < 8; j++)
                #pragma unroll
                for (int r = 0; r < 4; r++) acc[i][j][r] = 0.0f;

        /* S = Q @ K^T */
        #pragma unroll
        for (int ks = 0; ks < 4; ks++) {
            uint32_t qa[2][4];
            #pragma unroll
            for (int tm = 0; tm < 2; tm++) {
                int row = wm + tm*16 + gid;
                qa[tm][0] = *reinterpret_cast<const uint32_t*>(&Qs[ row    *QST + ks*16 + tig*2    ]);
                qa[tm][1] = *reinterpret_cast<const uint32_t*>(&Qs[(row+8)*QST + ks*16 + tig*2    ]);
                qa[tm][2] = *reinterpret_cast<const uint32_t*>(&Qs[ row    *QST + ks*16 + tig*2 + 8]);
                qa[tm][3] = *reinterpret_cast<const uint32_t*>(&Qs[(row+8)*QST + ks*16 + tig*2 + 8]);
            }
            #pragma unroll
            for (int tn = 0; tn < 8; tn++) {
                int nr = tn*8 + gid;
                uint32_t b0 = *reinterpret_cast<const uint32_t*>(&Ks[nr*QST + ks*16 + tig*2    ]);
                uint32_t b1 = *reinterpret_cast<const uint32_t*>(&Ks[nr*QST + ks*16 + tig*2 + 8]);
                #pragma unroll
                for (int tm = 0; tm < 2; tm++) {
                    float* c = acc[tm][tn];
                    mma16816(c[0],c[1],c[2],c[3], qa[tm][0],qa[tm][1],qa[tm][2],qa[tm][3], b0,b1);
                }
            }
        }

        /* scale + online softmax update */
        #pragma unroll
        for (int tm = 0; tm < 2; tm++) {
            float mx0 = -1e30f, mx1 = -1e30f;
            #pragma unroll
            for (int tn = 0; tn < 8; tn++) {
                float* c = acc[tm][tn];
                c[0] *= 0.125f; c[1] *= 0.125f; c[2] *= 0.125f; c[3] *= 0.125f;
                mx0 = fmaxf(mx0, fmaxf(c[0], c[1]));
                mx1 = fmaxf(mx1, fmaxf(c[2], c[3]));
            }
            #pragma unroll
            for (int o = 1; o <= 2; o <<= 1) {
                mx0 = fmaxf(mx0, __shfl_xor_sync(0xffffffffu, mx0, o));
                mx1 = fmaxf(mx1, __shfl_xor_sync(0xffffffffu, mx1, o));
            }
            float mn0 = fmaxf(mrow[tm][0], mx0);
            float mn1 = fmaxf(mrow[tm][1], mx1);
            float sc0 = __expf(mrow[tm][0] - mn0);
            float sc1 = __expf(mrow[tm][1] - mn1);
            float ls0 = 0.0f, ls1 = 0.0f;
            #pragma unroll
            for (int tn = 0; tn < 8; tn++) {
                float* c = acc[tm][tn];
                c[0] = __expf(c[0] - mn0);
                c[1] = __expf(c[1] - mn0);
                c[2] = __expf(c[2] - mn1);
                c[3] = __expf(c[3] - mn1);
                ls0 += c[0] + c[1];
                ls1 += c[2] + c[3];
            }
            #pragma unroll
            for (int o = 1; o <= 2; o <<= 1) {
                ls0 += __shfl_xor_sync(0xffffffffu, ls0, o);
                ls1 += __shfl_xor_sync(0xffffffffu, ls1, o);
            }
            lrow[tm][0] = lrow[tm][0] * sc0 + ls0;
            lrow[tm][1] = lrow[tm][1] * sc1 + ls1;
            mrow[tm][0] = mn0;
            mrow[tm][1] = mn1;
            #pragma unroll
            for (int to = 0; to < 8; to++) {
                oacc[tm][to][0] *= sc0; oacc[tm][to][1] *= sc0;
                oacc[tm][to][2] *= sc1; oacc[tm][to][3] *= sc1;
            }
        }

        /* store V tile transposed (pair-pack via prmt) */
        #pragma unroll
        for (int k = 0; k < 8; k++) {
            VW[(vdb + 2*k    ) * (QST/2) + vrp] = __byte_perm(va[k], vb[k], 0x5410);
            VW[(vdb + 2*k + 1) * (QST/2) + vrp] = __byte_perm(va[k], vb[k], 0x7632);
        }
        if (it + 1 < SEQ / BKV) {
            issueK(it + 1);
            loadV(it + 1);
        }
        __syncthreads();

        /* O += (Ph + Pl) @ V */
        #pragma unroll
        for (int j = 0; j < 4; j++) {
            uint32_t pH[2][4], pL[2][4];
            #pragma unroll
            for (int tm = 0; tm < 2; tm++) {
                pack_hl(acc[tm][2*j  ][0], acc[tm][2*j  ][1], pH[tm][0], pL[tm][0]);
                pack_hl(acc[tm][2*j  ][2], acc[tm][2*j  ][3], pH[tm][1], pL[tm][1]);
                pack_hl(acc[tm][2*j+1][0], acc[tm][2*j+1][1], pH[tm][2], pL[tm][2]);
                pack_hl(acc[tm][2*j+1][2], acc[tm][2*j+1][3], pH[tm][3], pL[tm][3]);
            }
            #pragma unroll
            for (int to = 0; to < 8; to++) {
                int d = to*8 + gid;
                uint32_t b0 = *reinterpret_cast<const uint32_t*>(&Vs[d*QST + j*16 + tig*2    ]);
                uint32_t b1 = *reinterpret_cast<const uint32_t*>(&Vs[d*QST + j*16 + tig*2 + 8]);
                #pragma unroll
                for (int tm = 0; tm < 2; tm++) {
                    float* c = oacc[tm][to];
                    mma16816(c[0],c[1],c[2],c[3], pH[tm][0],pH[tm][1],pH[tm][2],pH[tm][3], b0,b1);
                    mma16816(c[0],c[1],c[2],c[3], pL[tm][0],pL[tm][1],pL[tm][2],pL[tm][3], b0,b1);
                }
            }
        }
    }

    /* epilogue: O / l -> att (single fp16) */
    uint32_t* AW = reinterpret_cast<uint32_t*>(att);
    #pragma unroll
    for (int tm = 0; tm < 2; tm++) {
        float inv0 = 1.0f / lrow[tm][0];
        float inv1 = 1.0f / lrow[tm][1];
        int row = q0 + wm + tm*16 + gid;
        #pragma unroll
        for (int to = 0; to < 8; to++) {
            int col = h*HD + to*8 + tig*2;
            float* c = oacc[tm][to];
            long o0 = (((long)b*SEQ + row    ) * DIM + col) >> 1;
            long o1 = (((long)b*SEQ + row + 8) * DIM + col) >> 1;
            AW[o0] = pack1(c[0]*inv0, c[1]*inv0);
            AW[o1] = pack1(c[2]*inv1, c[3]*inv1);
        }
    }
}

/* ================= dense GEMM: pure fp16, 4-buffer depth-3 pipeline ========
 * Block 128x128, BK=32, 256 thr (8 warps, warp tile 64x32), 2 CTAs/SM.
 * C = A @ B^T + bias [+residual -> f32] or [gelu] -> fp16.
 */
#define BM  128
#define BN  128
#define BK2 32
#define SEB 40
#define TSZ (BM*SEB)              /* 5120 half per tile-buffer */
#define NSTG 4
#define GEMM_SMEM (2*NSTG*TSZ*2)  /* 81920 bytes */

__global__ void __launch_bounds__(256, 2) gemm_hf(
    const hf* __restrict__ Ag, const hf* __restrict__ Bg,
    const float* __restrict__ bias, const float* __restrict__ Rsd,
    float* __restrict__ Cf, hf* __restrict__ Ch, int doGelu,
    int M, int N, int K)
{
    extern __shared__ hf gsm[];
    /* layout: [A0..A3 B0..B3], each TSZ */
    uint32_t sbase = (uint32_t)__cvta_generic_to_shared(gsm);

    int m0 = blockIdx.y * BM;
    int n0 = blockIdx.x * BN;
    int t  = threadIdx.x;
    int lane = t & 31, wid = t >> 5;
    int gid = lane >> 2, tig = lane & 3;
    int warp_m = (wid >> 2) << 6;
    int warp_n = (wid & 3) << 5;

    int r0c = t >> 2, c0c = (t & 3) * 8;
    int r1c = r0c + 64;

    auto issue = [&](int st) {
        int buf = st & (NSTG-1);
        long k0 = (long)st * BK2;
        uint32_t dA = sbase + (buf*TSZ)*2;
        uint32_t dB = sbase + ((NSTG+buf)*TSZ)*2;
        cp16(dA + (r0c*SEB + c0c)*2, Ag + (long)(m0 + r0c)*K + k0 + c0c);
        cp16(dA + (r1c*SEB + c0c)*2, Ag + (long)(m0 + r1c)*K + k0 + c0c);
        cp16(dB + (r0c*SEB + c0c)*2, Bg + (long)(n0 + r0c)*K + k0 + c0c);
        cp16(dB + (r1c*SEB + c0c)*2, Bg + (long)(n0 + r1c)*K + k0 + c0c);
        asm volatile("cp.async.commit_group;");
    };

    float acc[4][4][4];
    #pragma unroll
    for (int i = 0; i < 4; i++)
        #pragma unroll
        for (int j = 0; j < 4; j++)
            #pragma unroll
            for (int r = 0; r < 4; r++) acc[i][j][r] = 0.0f;

    int t4 = lane >> 3, li = lane & 7;
    int a_row = (t4 & 1) * 8 + li,  a_col = (t4 >> 1) * 8;
    int b_row = (t4 >> 1) * 8 + li, b_col = (t4 & 1) * 8;

    int kt = K / BK2;
    issue(0); issue(1); issue(2);

    for (int kk = 0; kk < kt; kk++) {
        int rem = kt - 1 - kk;
        if (rem >= 2)      asm volatile("cp.async.wait_group 2;");
        else if (rem == 1) asm volatile("cp.async.wait_group 1;");
        else               asm volatile("cp.async.wait_group 0;");
        __syncthreads();
        if (kk + 3 < kt) issue(kk + 3);

        int buf = kk & (NSTG-1);
        uint32_t sA = sbase + (buf*TSZ)*2;
        uint32_t sB = sbase + ((NSTG+buf)*TSZ)*2;

        #pragma unroll
        for (int ks = 0; ks < 2; ks++) {
            int kc = ks * 16;
            uint32_t a[4][4], bb2[2][4];
            #pragma unroll
            for (int tm = 0; tm < 4; tm++)
                ldm_x4(a[tm], sA + ((warp_m + tm*16 + a_row)*SEB + kc + a_col)*2);
            #pragma unroll
            for (int p = 0; p < 2; p++)
                ldm_x4(bb2[p], sB + ((warp_n + p*16 + b_row)*SEB + kc + b_col)*2);

            #pragma unroll
            for (int tm = 0; tm < 4; tm++)
                #pragma unroll
                for (int tn = 0; tn < 4; tn++) {
                    float* c = acc[tm][tn];
                    uint32_t* bb = bb2[tn >> 1];
                    mma16816(c[0],c[1],c[2],c[3],
                             a[tm][0],a[tm][1],a[tm][2],a[tm][3],
                             bb[(tn&1)*2], bb[(tn&1)*2+1]);
                }
        }
    }

    /* epilogue */
    #pragma unroll
    for (int tn = 0; tn < 4; tn++) {
        int col = n0 + warp_n + tn * 8 + tig * 2;
        float b0 = bias ? bias[col]     : 0.0f;
        float b1 = bias ? bias[col + 1] : 0.0f;
        #pragma unroll
        for (int tm = 0; tm < 4; tm++) {
            int row0 = m0 + warp_m + tm * 16 + gid;
            float* c = acc[tm][tn];
            #pragma unroll
            for (int half = 0; half < 2; half++) {
                int row = row0 + half * 8;
                float v0 = c[half*2 + 0] + b0;
                float v1 = c[half*2 + 1] + b1;
                long off = (long)row * N + col;
                if (Ch) {
                    if (doGelu) { v0 = gelu_tanh(v0); v1 = gelu_tanh(v1); }
                    reinterpret_cast<uint32_t*>(Ch)[off >> 1] = pack1(v0, v1);
                } else {
                    if (Rsd) {
                        float2 r = *reinterpret_cast<const float2*>(Rsd + off);
                        v0 += r.x; v1 += r.y;
                    }
                    *reinterpret_cast<float2*>(Cf + off) = make_float2(v0, v1);
                }
            }
        }
    }
}

/* ---------------- launch --------------------------------------------------- */
extern "C" void kernel_launch(void* const* d_in, const int* in_sizes, int n_in,
                              void* d_out, int out_size)
{
    const float* x     = (const float*)d_in[0];
    const float* ln1s  = (const float*)d_in[1];
    const float* ln1b  = (const float*)d_in[2];
    const float* qkvw  = (const float*)d_in[3];
    const float* qkvb  = (const float*)d_in[4];
    const float* projw = (const float*)d_in[5];
    const float* projb = (const float*)d_in[6];
    const float* ln2s  = (const float*)d_in[7];
    const float* ln2b  = (const float*)d_in[8];
    const float* fc1w  = (const float*)d_in[9];
    const float* fc1b  = (const float*)d_in[10];
    const float* fc2w  = (const float*)d_in[11];
    const float* fc2b  = (const float*)d_in[12];
    float* out = (float*)d_out;

    hf *y, *qkvh, *att, *hb, *wq, *wp, *w1, *w2;
    float *x1;
    cudaGetSymbolAddress((void**)&y,    g_y);
    cudaGetSymbolAddress((void**)&qkvh, g_qkv);
    cudaGetSymbolAddress((void**)&att,  g_att);
    cudaGetSymbolAddress((void**)&x1,   g_x1);
    cudaGetSymbolAddress((void**)&hb,   g_h);
    cudaGetSymbolAddress((void**)&wq,   g_wq);
    cudaGetSymbolAddress((void**)&wp,   g_wp);
    cudaGetSymbolAddress((void**)&w1,   g_w1);
    cudaGetSymbolAddress((void**)&w2,   g_w2);

    cudaFuncSetAttribute(flash_kernel,
        cudaFuncAttributeMaxDynamicSharedMemorySize, FA_SMEM);
    cudaFuncSetAttribute(gemm_hf,
        cudaFuncAttributeMaxDynamicSharedMemorySize, GEMM_SMEM);

    /* 0. weight transpose (fp16) */
    wt_kernel<<<dim3(3*DIM/32, DIM/32), dim3(32,8)>>>(qkvw, wq, DIM, 3*DIM);
    wt_kernel<<<dim3(DIM/32,   DIM/32), dim3(32,8)>>>(projw, wp, DIM, DIM);
    wt_kernel<<<dim3(HIDDEN/32,DIM/32), dim3(32,8)>>>(fc1w, w1, DIM, HIDDEN);
    wt_kernel<<<dim3(DIM/32,HIDDEN/32), dim3(32,8)>>>(fc2w, w2, HIDDEN, DIM);

    /* 1. LN1 -> y fp16 */
    ln_kernel<<<ROWS, 256>>>(x, ln1s, ln1b, y);

    /* 2. QKV = y @ Wq + b  (fp16 out, no gelu) */
    gemm_hf<<<dim3(3*DIM/BN, ROWS/BM), 256, GEMM_SMEM>>>(
        y, wq, qkvb, nullptr, nullptr, qkvh, 0,
        ROWS, 3*DIM, DIM);

    /* 3-5. flash attention -> att fp16 */
    flash_kernel<<<dim3(SEQ / BQ, BATCH * HEADS), 128, FA_SMEM>>>(qkvh, att);

    /* 6. x1 = att @ Wp + b + x  (f32 out) */
    gemm_hf<<<dim3(DIM/BN, ROWS/BM), 256, GEMM_SMEM>>>(
        att, wp, projb, x, x1, nullptr, 0,
        ROWS, DIM, DIM);

    /* 7. LN2 -> y fp16 */
    ln_kernel<<<ROWS, 256>>>(x1, ln2s, ln2b, y);

    /* 8. h = gelu(y @ W1 + b)  (fp16 out) */
    gemm_hf<<<dim3(HIDDEN/BN, ROWS/BM), 256, GEMM_SMEM>>>(
        y, w1, fc1b, nullptr, nullptr, hb, 1,
        ROWS, HIDDEN, DIM);

    /* 9. out = h @ W2 + b + x1  (f32 out) */
    gemm_hf<<<dim3(DIM/BN, ROWS/BM), 256, GEMM_SMEM>>>(
        hb, w2, fc2b, x1, out, nullptr, 0,
        ROWS, DIM, HIDDEN);
}

// round 9
// speedup vs baseline: 7.6762x; 1.0547x over previous
#include <cuda_runtime.h>
#include <cuda_fp16.h>
#include <cstdint>

#define DIM    768
#define SEQ    1024
#define BATCH  8
#define ROWS   (BATCH*SEQ)      /* 8192 */
#define HEADS  12
#define HD     64
#define HIDDEN 3072
#define LN_EPS 1e-6f

typedef __half hf;

/* ---------------- scratch (static device globals; no allocations) -------- */
__device__ __align__(16) hf    g_y  [ROWS * DIM];       /* LN out, fp16 */
__device__ __align__(16) hf    g_qkv[ROWS * 3 * DIM];   /* QKV, fp16 */
__device__ __align__(16) hf    g_att[ROWS * DIM];       /* attention out */
__device__ __align__(16) float g_x1 [ROWS * DIM];
__device__ __align__(16) hf    g_h  [ROWS * HIDDEN];    /* fc1 out */
/* transposed fp16 weights, [N][K] */
__device__ __align__(16) hf g_wq[3*DIM*DIM];
__device__ __align__(16) hf g_wp[DIM*DIM];
__device__ __align__(16) hf g_w1[HIDDEN*DIM];
__device__ __align__(16) hf g_w2[DIM*HIDDEN];

/* ---------------- helpers -------------------------------------------------- */
__device__ __forceinline__ float gelu_tanh(float u)
{
    return 0.5f * u * (1.0f + tanhf(0.7978845608028654f * (u + 0.044715f * u * u * u)));
}

__device__ __forceinline__ void mma16816(
    float& c0, float& c1, float& c2, float& c3,
    uint32_t a0, uint32_t a1, uint32_t a2, uint32_t a3,
    uint32_t b0, uint32_t b1)
{
    asm volatile(
        "mma.sync.aligned.m16n8k16.row.col.f32.f16.f16.f32 "
        "{%0,%1,%2,%3},{%4,%5,%6,%7},{%8,%9},{%0,%1,%2,%3};"
        : "+f"(c0), "+f"(c1), "+f"(c2), "+f"(c3)
        : "r"(a0), "r"(a1), "r"(a2), "r"(a3), "r"(b0), "r"(b1));
}

__device__ __forceinline__ uint32_t pack1(float x0, float x1)
{
    hf h0 = __float2half_rn(x0), h1 = __float2half_rn(x1);
    return ((uint32_t)__half_as_ushort(h1) << 16) | __half_as_ushort(h0);
}

__device__ __forceinline__ void cp16(uint32_t s, const void* g)
{
    asm volatile("cp.async.cg.shared.global [%0], [%1], 16;" :: "r"(s), "l"(g));
}
__device__ __forceinline__ void ldm_x4(uint32_t* r, uint32_t addr)
{
    asm volatile("ldmatrix.sync.aligned.m8n8.x4.shared.b16 {%0,%1,%2,%3}, [%4];"
        : "=r"(r[0]), "=r"(r[1]), "=r"(r[2]), "=r"(r[3]) : "r"(addr));
}

/* ---------------- weight transpose: W[K][N] -> T[N][K] fp16 ---------------- */
__global__ void __launch_bounds__(256) wt_kernel(
    const float* __restrict__ W, hf* __restrict__ Th, int K, int N)
{
    __shared__ float s[32][33];
    int tx = threadIdx.x, ty = threadIdx.y;
    int n0 = blockIdx.x * 32, k0 = blockIdx.y * 32;
    #pragma unroll
    for (int j = 0; j < 4; j++)
        s[ty + j*8][tx] = W[(long)(k0 + ty + j*8) * N + n0 + tx];
    __syncthreads();
    #pragma unroll
    for (int j = 0; j < 4; j++) {
        long o = (long)(n0 + ty + j*8) * K + k0 + tx;
        Th[o] = __float2half_rn(s[tx][ty + j*8]);
    }
}

/* ---------------- layernorm -> single fp16 --------------------------------- */
__global__ void __launch_bounds__(256) ln_kernel(
    const float* __restrict__ x, const float* __restrict__ sc,
    const float* __restrict__ bi, hf* __restrict__ y)
{
    long row = blockIdx.x;
    int  t   = threadIdx.x;
    const float* xr = x + row * DIM;
    float v0 = xr[t], v1 = xr[t + 256], v2 = xr[t + 512];

    __shared__ float sbuf[8];
    __shared__ float s_mu, s_r;

    float s = v0 + v1 + v2;
    #pragma unroll
    for (int o = 16; o > 0; o >>= 1) s += __shfl_xor_sync(0xffffffffu, s, o);
    if ((t & 31) == 0) sbuf[t >> 5] = s;
    __syncthreads();
    if (t < 8) {
        float r = sbuf[t];
        #pragma unroll
        for (int o = 4; o > 0; o >>= 1) r += __shfl_xor_sync(0xffu, r, o);
        if (t == 0) s_mu = r * (1.0f / DIM);
    }
    __syncthreads();
    float mu = s_mu;
    float d0 = v0 - mu, d1 = v1 - mu, d2 = v2 - mu;
    float q = d0*d0 + d1*d1 + d2*d2;
    #pragma unroll
    for (int o = 16; o > 0; o >>= 1) q += __shfl_xor_sync(0xffffffffu, q, o);
    if ((t & 31) == 0) sbuf[t >> 5] = q;
    __syncthreads();
    if (t < 8) {
        float r = sbuf[t];
        #pragma unroll
        for (int o = 4; o > 0; o >>= 1) r += __shfl_xor_sync(0xffu, r, o);
        if (t == 0) s_r = rsqrtf(r * (1.0f / DIM) + LN_EPS);
    }
    __syncthreads();
    float rs = s_r;
    long base = row * DIM;
    y[base + t      ] = __float2half_rn(d0 * rs * sc[t      ] + bi[t      ]);
    y[base + t + 256] = __float2half_rn(d1 * rs * sc[t + 256] + bi[t + 256]);
    y[base + t + 512] = __float2half_rn(d2 * rs * sc[t + 512] + bi[t + 512]);
}

/* ================= flash attention (fp16 qkv in) ===========================
 * Q, K via cp.async (K double buffered). V manual transposed store.
 * S = Q@K (1 mma, scaled by 0.125 post-mma); O += P@V (1 mma, P fp16).
 */
#define BQ  128
#define BKV 64
#define QST 72
#define SQ_ELE (BQ*QST)             /* 9216 halves  */
#define SK_ELE (BKV*QST)            /* 4608 halves  */
#define FA_SMEM ((SQ_ELE + 2*SK_ELE + SK_ELE) * 2)   /* 46080 B */

__global__ void __launch_bounds__(128) flash_kernel(
    const hf* __restrict__ qkv, hf* __restrict__ att)
{
    extern __shared__ hf sm[];
    hf* Qs  = sm;
    hf* Ks0 = Qs + SQ_ELE;          /* two K buffers */
    hf* Vs  = Ks0 + 2*SK_ELE;
    uint32_t* VW = reinterpret_cast<uint32_t*>(Vs);
    uint32_t sQ, sK0;
    {
        uint32_t base = (uint32_t)__cvta_generic_to_shared(sm);
        sQ = base; sK0 = base + SQ_ELE*2;
    }

    int t = threadIdx.x, lane = t & 31, wid = t >> 5;
    int gid = lane >> 2, tig = lane & 3;
    int bh = blockIdx.y, b = bh / HEADS, h = bh % HEADS;
    int q0 = blockIdx.x * BQ;

    const hf* Qp = qkv + ((long)b * SEQ + q0) * (3*DIM) + h * HD;
    const hf* Kp = qkv + (long)b * SEQ * (3*DIM) + DIM     + h * HD;
    const hf* Vp = qkv + (long)b * SEQ * (3*DIM) + 2*DIM   + h * HD;

    /* cp.async loaders */
    auto issueQ = [&]() {
        #pragma unroll
        for (int i = 0; i < 8; i++) {
            int g = t + i * 128;
            int row = g >> 3, c = g & 7;
            cp16(sQ + (row*QST + c*8)*2, Qp + (long)row*(3*DIM) + c*8);
        }
    };
    auto issueK = [&](int it) {
        uint32_t kb = sK0 + (it & 1) * (SK_ELE*2);
        #pragma unroll
        for (int i = 0; i < 4; i++) {
            int g = t + i * 128;
            int row = g >> 3, c = g & 7;
            cp16(kb + (row*QST + c*8)*2, Kp + (long)(it*BKV + row)*(3*DIM) + c*8);
        }
        asm volatile("cp.async.commit_group;");
    };

    /* V loader: rows 2vrp,2vrp+1 cols vdb..vdb+15 (fp16) */
    int vrp = t & 31, vdb = (t >> 5) * 16;
    uint32_t va[8], vb[8];
    auto loadV = [&](int it) {
        const hf* p0 = Vp + (long)(it * BKV + 2*vrp) * (3*DIM) + vdb;
        const hf* p1 = p0 + 3*DIM;
        uint4 a0 = *reinterpret_cast<const uint4*>(p0);
        uint4 a1 = *reinterpret_cast<const uint4*>(p0 + 8);
        uint4 b0 = *reinterpret_cast<const uint4*>(p1);
        uint4 b1 = *reinterpret_cast<const uint4*>(p1 + 8);
        va[0]=a0.x; va[1]=a0.y; va[2]=a0.z; va[3]=a0.w;
        va[4]=a1.x; va[5]=a1.y; va[6]=a1.z; va[7]=a1.w;
        vb[0]=b0.x; vb[1]=b0.y; vb[2]=b0.z; vb[3]=b0.w;
        vb[4]=b1.x; vb[5]=b1.y; vb[6]=b1.z; vb[7]=b1.w;
    };

    issueQ();
    issueK(0);
    loadV(0);

    float acc[2][8][4];
    float oacc[2][8][4];
    float mrow[2][2], lrow[2][2];
    #pragma unroll
    for (int i = 0; i < 2; i++) {
        mrow[i][0] = mrow[i][1] = -1e30f;
        lrow[i][0] = lrow[i][1] = 0.0f;
        #pragma unroll
        for (int j = 0; j < 8; j++)
            #pragma unroll
            for (int r = 0; r < 4; r++) oacc[i][j][r] = 0.0f;
    }

    int wm = wid * 32;

    for (int it = 0; it < SEQ / BKV; it++) {
        asm volatile("cp.async.wait_group 0;");
        __syncthreads();
        hf* Ks = Ks0 + (it & 1) * SK_ELE;

        #pragma unroll
        for (int i = 0; i < 2; i++)
            #pragma unroll
            for (int j = 0; j < 8; j++)
                #pragma unroll
                for (int r = 0; r < 4; r++) acc[i][j][r] = 0.0f;

        /* S = Q @ K^T */
        #pragma unroll
        for (int ks = 0; ks < 4; ks++) {
            uint32_t qa[2][4];
            #pragma unroll
            for (int tm = 0; tm < 2; tm++) {
                int row = wm + tm*16 + gid;
                qa[tm][0] = *reinterpret_cast<const uint32_t*>(&Qs[ row    *QST + ks*16 + tig*2    ]);
                qa[tm][1] = *reinterpret_cast<const uint32_t*>(&Qs[(row+8)*QST + ks*16 + tig*2    ]);
                qa[tm][2] = *reinterpret_cast<const uint32_t*>(&Qs[ row    *QST + ks*16 + tig*2 + 8]);
                qa[tm][3] = *reinterpret_cast<const uint32_t*>(&Qs[(row+8)*QST + ks*16 + tig*2 + 8]);
            }
            #pragma unroll
            for (int tn = 0; tn < 8; tn++) {
                int nr = tn*8 + gid;
                uint32_t b0 = *reinterpret_cast<const uint32_t*>(&Ks[nr*QST + ks*16 + tig*2    ]);
                uint32_t b1 = *reinterpret_cast<const uint32_t*>(&Ks[nr*QST + ks*16 + tig*2 + 8]);
                #pragma unroll
                for (int tm = 0; tm < 2; tm++) {
                    float* c = acc[tm][tn];
                    mma16816(c[0],c[1],c[2],c[3], qa[tm][0],qa[tm][1],qa[tm][2],qa[tm][3], b0,b1);
                }
            }
        }

        /* scale + online softmax update */
        #pragma unroll
        for (int tm = 0; tm < 2; tm++) {
            float mx0 = -1e30f, mx1 = -1e30f;
            #pragma unroll
            for (int tn = 0; tn < 8; tn++) {
                float* c = acc[tm][tn];
                c[0] *= 0.125f; c[1] *= 0.125f; c[2] *= 0.125f; c[3] *= 0.125f;
                mx0 = fmaxf(mx0, fmaxf(c[0], c[1]));
                mx1 = fmaxf(mx1, fmaxf(c[2], c[3]));
            }
            #pragma unroll
            for (int o = 1; o <= 2; o <<= 1) {
                mx0 = fmaxf(mx0, __shfl_xor_sync(0xffffffffu, mx0, o));
                mx1 = fmaxf(mx1, __shfl_xor_sync(0xffffffffu, mx1, o));
            }
            float mn0 = fmaxf(mrow[tm][0], mx0);
            float mn1 = fmaxf(mrow[tm][1], mx1);
            float sc0 = __expf(mrow[tm][0] - mn0);
            float sc1 = __expf(mrow[tm][1] - mn1);
            float ls0 = 0.0f, ls1 = 0.0f;
            #pragma unroll
            for (int tn = 0; tn < 8; tn++) {
                float* c = acc[tm][tn];
                c[0] = __expf(c[0] - mn0);
                c[1] = __expf(c[1] - mn0);
                c[2] = __expf(c[2] - mn1);
                c[3] = __expf(c[3] - mn1);
                ls0 += c[0] + c[1];
                ls1 += c[2] + c[3];
            }
            #pragma unroll
            for (int o = 1; o <= 2; o <<= 1) {
                ls0 += __shfl_xor_sync(0xffffffffu, ls0, o);
                ls1 += __shfl_xor_sync(0xffffffffu, ls1, o);
            }
            lrow[tm][0] = lrow[tm][0] * sc0 + ls0;
            lrow[tm][1] = lrow[tm][1] * sc1 + ls1;
            mrow[tm][0] = mn0;
            mrow[tm][1] = mn1;
            #pragma unroll
            for (int to = 0; to < 8; to++) {
                oacc[tm][to][0] *= sc0; oacc[tm][to][1] *= sc0;
                oacc[tm][to][2] *= sc1; oacc[tm][to][3] *= sc1;
            }
        }

        /* store V tile transposed (pair-pack via prmt) */
        #pragma unroll
        for (int k = 0; k < 8; k++) {
            VW[(vdb + 2*k    ) * (QST/2) + vrp] = __byte_perm(va[k], vb[k], 0x5410);
            VW[(vdb + 2*k + 1) * (QST/2) + vrp] = __byte_perm(va[k], vb[k], 0x7632);
        }
        if (it + 1 < SEQ / BKV) {
            issueK(it + 1);
            loadV(it + 1);
        }
        __syncthreads();

        /* O += P @ V  (P quantized to fp16) */
        #pragma unroll
        for (int j = 0; j < 4; j++) {
            uint32_t pH[2][4];
            #pragma unroll
            for (int tm = 0; tm < 2; tm++) {
                pH[tm][0] = pack1(acc[tm][2*j  ][0], acc[tm][2*j  ][1]);
                pH[tm][1] = pack1(acc[tm][2*j  ][2], acc[tm][2*j  ][3]);
                pH[tm][2] = pack1(acc[tm][2*j+1][0], acc[tm][2*j+1][1]);
                pH[tm][3] = pack1(acc[tm][2*j+1][2], acc[tm][2*j+1][3]);
            }
            #pragma unroll
            for (int to = 0; to < 8; to++) {
                int d = to*8 + gid;
                uint32_t b0 = *reinterpret_cast<const uint32_t*>(&Vs[d*QST + j*16 + tig*2    ]);
                uint32_t b1 = *reinterpret_cast<const uint32_t*>(&Vs[d*QST + j*16 + tig*2 + 8]);
                #pragma unroll
                for (int tm = 0; tm < 2; tm++) {
                    float* c = oacc[tm][to];
                    mma16816(c[0],c[1],c[2],c[3], pH[tm][0],pH[tm][1],pH[tm][2],pH[tm][3], b0,b1);
                }
            }
        }
    }

    /* epilogue: O / l -> att (single fp16) */
    uint32_t* AW = reinterpret_cast<uint32_t*>(att);
    #pragma unroll
    for (int tm = 0; tm < 2; tm++) {
        float inv0 = 1.0f / lrow[tm][0];
        float inv1 = 1.0f / lrow[tm][1];
        int row = q0 + wm + tm*16 + gid;
        #pragma unroll
        for (int to = 0; to < 8; to++) {
            int col = h*HD + to*8 + tig*2;
            float* c = oacc[tm][to];
            long o0 = (((long)b*SEQ + row    ) * DIM + col) >> 1;
            long o1 = (((long)b*SEQ + row + 8) * DIM + col) >> 1;
            AW[o0] = pack1(c[0]*inv0, c[1]*inv0);
            AW[o1] = pack1(c[2]*inv1, c[3]*inv1);
        }
    }
}

/* ================= dense GEMM: pure fp16, 4-buffer depth-3 pipeline ========
 * Block 128x128, BK=32, 256 thr (8 warps, warp tile 64x32), 2 CTAs/SM.
 * C = A @ B^T + bias [+residual -> f32] or [gelu] -> fp16.
 */
#define BM  128
#define BN  128
#define BK2 32
#define SEB 40
#define TSZ (BM*SEB)              /* 5120 half per tile-buffer */
#define NSTG 4
#define GEMM_SMEM (2*NSTG*TSZ*2)  /* 81920 bytes */

__global__ void __launch_bounds__(256, 2) gemm_hf(
    const hf* __restrict__ Ag, const hf* __restrict__ Bg,
    const float* __restrict__ bias, const float* __restrict__ Rsd,
    float* __restrict__ Cf, hf* __restrict__ Ch, int doGelu,
    int M, int N, int K)
{
    extern __shared__ hf gsm[];
    /* layout: [A0..A3 B0..B3], each TSZ */
    uint32_t sbase = (uint32_t)__cvta_generic_to_shared(gsm);

    int m0 = blockIdx.y * BM;
    int n0 = blockIdx.x * BN;
    int t  = threadIdx.x;
    int lane = t & 31, wid = t >> 5;
    int gid = lane >> 2, tig = lane & 3;
    int warp_m = (wid >> 2) << 6;
    int warp_n = (wid & 3) << 5;

    int r0c = t >> 2, c0c = (t & 3) * 8;
    int r1c = r0c + 64;

    auto issue = [&](int st) {
        int buf = st & (NSTG-1);
        long k0 = (long)st * BK2;
        uint32_t dA = sbase + (buf*TSZ)*2;
        uint32_t dB = sbase + ((NSTG+buf)*TSZ)*2;
        cp16(dA + (r0c*SEB + c0c)*2, Ag + (long)(m0 + r0c)*K + k0 + c0c);
        cp16(dA + (r1c*SEB + c0c)*2, Ag + (long)(m0 + r1c)*K + k0 + c0c);
        cp16(dB + (r0c*SEB + c0c)*2, Bg + (long)(n0 + r0c)*K + k0 + c0c);
        cp16(dB + (r1c*SEB + c0c)*2, Bg + (long)(n0 + r1c)*K + k0 + c0c);
        asm volatile("cp.async.commit_group;");
    };

    float acc[4][4][4];
    #pragma unroll
    for (int i = 0; i < 4; i++)
        #pragma unroll
        for (int j = 0; j < 4; j++)
            #pragma unroll
            for (int r = 0; r < 4; r++) acc[i][j][r] = 0.0f;

    int t4 = lane >> 3, li = lane & 7;
    int a_row = (t4 & 1) * 8 + li,  a_col = (t4 >> 1) * 8;
    int b_row = (t4 >> 1) * 8 + li, b_col = (t4 & 1) * 8;

    int kt = K / BK2;
    issue(0); issue(1); issue(2);

    for (int kk = 0; kk < kt; kk++) {
        int rem = kt - 1 - kk;
        if (rem >= 2)      asm volatile("cp.async.wait_group 2;");
        else if (rem == 1) asm volatile("cp.async.wait_group 1;");
        else               asm volatile("cp.async.wait_group 0;");
        __syncthreads();
        if (kk + 3 < kt) issue(kk + 3);

        int buf = kk & (NSTG-1);
        uint32_t sA = sbase + (buf*TSZ)*2;
        uint32_t sB = sbase + ((NSTG+buf)*TSZ)*2;

        #pragma unroll
        for (int ks = 0; ks < 2; ks++) {
            int kc = ks * 16;
            uint32_t a[4][4], bb2[2][4];
            #pragma unroll
            for (int tm = 0; tm < 4; tm++)
                ldm_x4(a[tm], sA + ((warp_m + tm*16 + a_row)*SEB + kc + a_col)*2);
            #pragma unroll
            for (int p = 0; p < 2; p++)
                ldm_x4(bb2[p], sB + ((warp_n + p*16 + b_row)*SEB + kc + b_col)*2);

            #pragma unroll
            for (int tm = 0; tm < 4; tm++)
                #pragma unroll
                for (int tn = 0; tn < 4; tn++) {
                    float* c = acc[tm][tn];
                    uint32_t* bb = bb2[tn >> 1];
                    mma16816(c[0],c[1],c[2],c[3],
                             a[tm][0],a[tm][1],a[tm][2],a[tm][3],
                             bb[(tn&1)*2], bb[(tn&1)*2+1]);
                }
        }
    }

    /* epilogue */
    #pragma unroll
    for (int tn = 0; tn < 4; tn++) {
        int col = n0 + warp_n + tn * 8 + tig * 2;
        float b0 = bias ? bias[col]     : 0.0f;
        float b1 = bias ? bias[col + 1] : 0.0f;
        #pragma unroll
        for (int tm = 0; tm < 4; tm++) {
            int row0 = m0 + warp_m + tm * 16 + gid;
            float* c = acc[tm][tn];
            #pragma unroll
            for (int half = 0; half < 2; half++) {
                int row = row0 + half * 8;
                float v0 = c[half*2 + 0] + b0;
                float v1 = c[half*2 + 1] + b1;
                long off = (long)row * N + col;
                if (Ch) {
                    if (doGelu) { v0 = gelu_tanh(v0); v1 = gelu_tanh(v1); }
                    reinterpret_cast<uint32_t*>(Ch)[off >> 1] = pack1(v0, v1);
                } else {
                    if (Rsd) {
                        float2 r = *reinterpret_cast<const float2*>(Rsd + off);
                        v0 += r.x; v1 += r.y;
                    }
                    *reinterpret_cast<float2*>(Cf + off) = make_float2(v0, v1);
                }
            }
        }
    }
}

/* ---------------- launch --------------------------------------------------- */
extern "C" void kernel_launch(void* const* d_in, const int* in_sizes, int n_in,
                              void* d_out, int out_size)
{
    const float* x     = (const float*)d_in[0];
    const float* ln1s  = (const float*)d_in[1];
    const float* ln1b  = (const float*)d_in[2];
    const float* qkvw  = (const float*)d_in[3];
    const float* qkvb  = (const float*)d_in[4];
    const float* projw = (const float*)d_in[5];
    const float* projb = (const float*)d_in[6];
    const float* ln2s  = (const float*)d_in[7];
    const float* ln2b  = (const float*)d_in[8];
    const float* fc1w  = (const float*)d_in[9];
    const float* fc1b  = (const float*)d_in[10];
    const float* fc2w  = (const float*)d_in[11];
    const float* fc2b  = (const float*)d_in[12];
    float* out = (float*)d_out;

    hf *y, *qkvh, *att, *hb, *wq, *wp, *w1, *w2;
    float *x1;
    cudaGetSymbolAddress((void**)&y,    g_y);
    cudaGetSymbolAddress((void**)&qkvh, g_qkv);
    cudaGetSymbolAddress((void**)&att,  g_att);
    cudaGetSymbolAddress((void**)&x1,   g_x1);
    cudaGetSymbolAddress((void**)&hb,   g_h);
    cudaGetSymbolAddress((void**)&wq,   g_wq);
    cudaGetSymbolAddress((void**)&wp,   g_wp);
    cudaGetSymbolAddress((void**)&w1,   g_w1);
    cudaGetSymbolAddress((void**)&w2,   g_w2);

    cudaFuncSetAttribute(flash_kernel,
        cudaFuncAttributeMaxDynamicSharedMemorySize, FA_SMEM);
    cudaFuncSetAttribute(gemm_hf,
        cudaFuncAttributeMaxDynamicSharedMemorySize, GEMM_SMEM);

    /* 0. weight transpose (fp16) */
    wt_kernel<<<dim3(3*DIM/32, DIM/32), dim3(32,8)>>>(qkvw, wq, DIM, 3*DIM);
    wt_kernel<<<dim3(DIM/32,   DIM/32), dim3(32,8)>>>(projw, wp, DIM, DIM);
    wt_kernel<<<dim3(HIDDEN/32,DIM/32), dim3(32,8)>>>(fc1w, w1, DIM, HIDDEN);
    wt_kernel<<<dim3(DIM/32,HIDDEN/32), dim3(32,8)>>>(fc2w, w2, HIDDEN, DIM);

    /* 1. LN1 -> y fp16 */
    ln_kernel<<<ROWS, 256>>>(x, ln1s, ln1b, y);

    /* 2. QKV = y @ Wq + b  (fp16 out) */
    gemm_hf<<<dim3(3*DIM/BN, ROWS/BM), 256, GEMM_SMEM>>>(
        y, wq, qkvb, nullptr, nullptr, qkvh, 0,
        ROWS, 3*DIM, DIM);

    /* 3-5. flash attention -> att fp16 */
    flash_kernel<<<dim3(SEQ / BQ, BATCH * HEADS), 128, FA_SMEM>>>(qkvh, att);

    /* 6. x1 = att @ Wp + b + x  (f32 out) */
    gemm_hf<<<dim3(DIM/BN, ROWS/BM), 256, GEMM_SMEM>>>(
        att, wp, projb, x, x1, nullptr, 0,
        ROWS, DIM, DIM);

    /* 7. LN2 -> y fp16 */
    ln_kernel<<<ROWS, 256>>>(x1, ln2s, ln2b, y);

    /* 8. h = gelu(y @ W1 + b)  (fp16 out) */
    gemm_hf<<<dim3(HIDDEN/BN, ROWS/BM), 256, GEMM_SMEM>>>(
        y, w1, fc1b, nullptr, nullptr, hb, 1,
        ROWS, HIDDEN, DIM);

    /* 9. out = h @ W2 + b + x1  (f32 out) */
    gemm_hf<<<dim3(DIM/BN, ROWS/BM), 256, GEMM_SMEM>>>(
        hb, w2, fc2b, x1, out, nullptr, 0,
        ROWS, DIM, HIDDEN);
}

// round 10
// speedup vs baseline: 7.9166x; 1.0313x over previous
#include <cuda_runtime.h>
#include <cuda_fp16.h>
#include <cstdint>

#define DIM    768
#define SEQ    1024
#define BATCH  8
#define ROWS   (BATCH*SEQ)      /* 8192 */
#define HEADS  12
#define HD     64
#define HIDDEN 3072
#define LN_EPS 1e-6f

typedef __half hf;

/* ---------------- scratch (static device globals; no allocations) -------- */
__device__ __align__(16) hf    g_y  [ROWS * DIM];       /* LN out, fp16 */
__device__ __align__(16) hf    g_qkv[ROWS * 3 * DIM];   /* QKV, fp16 */
__device__ __align__(16) hf    g_att[ROWS * DIM];       /* attention out */
__device__ __align__(16) float g_x1 [ROWS * DIM];
__device__ __align__(16) hf    g_h  [ROWS * HIDDEN];    /* fc1 out */
/* transposed fp16 weights, [N][K] */
__device__ __align__(16) hf g_wq[3*DIM*DIM];
__device__ __align__(16) hf g_wp[DIM*DIM];
__device__ __align__(16) hf g_w1[HIDDEN*DIM];
__device__ __align__(16) hf g_w2[DIM*HIDDEN];

/* ---------------- helpers -------------------------------------------------- */
__device__ __forceinline__ float gelu_tanh(float u)
{
    return 0.5f * u * (1.0f + tanhf(0.7978845608028654f * (u + 0.044715f * u * u * u)));
}

__device__ __forceinline__ void mma16816(
    float& c0, float& c1, float& c2, float& c3,
    uint32_t a0, uint32_t a1, uint32_t a2, uint32_t a3,
    uint32_t b0, uint32_t b1)
{
    asm volatile(
        "mma.sync.aligned.m16n8k16.row.col.f32.f16.f16.f32 "
        "{%0,%1,%2,%3},{%4,%5,%6,%7},{%8,%9},{%0,%1,%2,%3};"
        : "+f"(c0), "+f"(c1), "+f"(c2), "+f"(c3)
        : "r"(a0), "r"(a1), "r"(a2), "r"(a3), "r"(b0), "r"(b1));
}

__device__ __forceinline__ uint32_t pack1(float x0, float x1)
{
    hf h0 = __float2half_rn(x0), h1 = __float2half_rn(x1);
    return ((uint32_t)__half_as_ushort(h1) << 16) | __half_as_ushort(h0);
}

__device__ __forceinline__ void cp16(uint32_t s, const void* g)
{
    asm volatile("cp.async.cg.shared.global [%0], [%1], 16;" :: "r"(s), "l"(g));
}
__device__ __forceinline__ void ldm_x4(uint32_t* r, uint32_t addr)
{
    asm volatile("ldmatrix.sync.aligned.m8n8.x4.shared.b16 {%0,%1,%2,%3}, [%4];"
        : "=r"(r[0]), "=r"(r[1]), "=r"(r[2]), "=r"(r[3]) : "r"(addr));
}

/* ---------------- merged weight transpose: 4 weights, one launch ----------- */
/* tiles: qkv 72x24=1728, proj 24x24=576, fc1 96x24=2304, fc2 24x96=2304 */
__global__ void __launch_bounds__(256) wt_all_kernel(
    const float* __restrict__ qkvw, const float* __restrict__ projw,
    const float* __restrict__ fc1w, const float* __restrict__ fc2w,
    hf* __restrict__ wq, hf* __restrict__ wp,
    hf* __restrict__ w1, hf* __restrict__ w2)
{
    int id = blockIdx.x;
    const float* W; hf* T; int K, N, tile;
    if (id < 1728)      { W = qkvw; T = wq; K = DIM;    N = 3*DIM;  tile = id; }
    else if (id < 2304) { W = projw; T = wp; K = DIM;   N = DIM;    tile = id - 1728; }
    else if (id < 4608) { W = fc1w; T = w1; K = DIM;    N = HIDDEN; tile = id - 2304; }
    else                { W = fc2w; T = w2; K = HIDDEN; N = DIM;    tile = id - 4608; }
    int nx = N >> 5;
    int n0 = (tile % nx) << 5, k0 = (tile / nx) << 5;

    __shared__ float s[32][33];
    int tx = threadIdx.x, ty = threadIdx.y;
    #pragma unroll
    for (int j = 0; j < 4; j++)
        s[ty + j*8][tx] = W[(long)(k0 + ty + j*8) * N + n0 + tx];
    __syncthreads();
    #pragma unroll
    for (int j = 0; j < 4; j++) {
        long o = (long)(n0 + ty + j*8) * K + k0 + tx;
        T[o] = __float2half_rn(s[tx][ty + j*8]);
    }
}

/* ---------------- layernorm -> single fp16 --------------------------------- */
__global__ void __launch_bounds__(256) ln_kernel(
    const float* __restrict__ x, const float* __restrict__ sc,
    const float* __restrict__ bi, hf* __restrict__ y)
{
    long row = blockIdx.x;
    int  t   = threadIdx.x;
    const float* xr = x + row * DIM;
    float v0 = xr[t], v1 = xr[t + 256], v2 = xr[t + 512];

    __shared__ float sbuf[8];
    __shared__ float s_mu, s_r;

    float s = v0 + v1 + v2;
    #pragma unroll
    for (int o = 16; o > 0; o >>= 1) s += __shfl_xor_sync(0xffffffffu, s, o);
    if ((t & 31) == 0) sbuf[t >> 5] = s;
    __syncthreads();
    if (t < 8) {
        float r = sbuf[t];
        #pragma unroll
        for (int o = 4; o > 0; o >>= 1) r += __shfl_xor_sync(0xffu, r, o);
        if (t == 0) s_mu = r * (1.0f / DIM);
    }
    __syncthreads();
    float mu = s_mu;
    float d0 = v0 - mu, d1 = v1 - mu, d2 = v2 - mu;
    float q = d0*d0 + d1*d1 + d2*d2;
    #pragma unroll
    for (int o = 16; o > 0; o >>= 1) q += __shfl_xor_sync(0xffffffffu, q, o);
    if ((t & 31) == 0) sbuf[t >> 5] = q;
    __syncthreads();
    if (t < 8) {
        float r = sbuf[t];
        #pragma unroll
        for (int o = 4; o > 0; o >>= 1) r += __shfl_xor_sync(0xffu, r, o);
        if (t == 0) s_r = rsqrtf(r * (1.0f / DIM) + LN_EPS);
    }
    __syncthreads();
    float rs = s_r;
    long base = row * DIM;
    y[base + t      ] = __float2half_rn(d0 * rs * sc[t      ] + bi[t      ]);
    y[base + t + 256] = __float2half_rn(d1 * rs * sc[t + 256] + bi[t + 256]);
    y[base + t + 512] = __float2half_rn(d2 * rs * sc[t + 512] + bi[t + 512]);
}

/* ================= flash attention (fp16 qkv in) =========================== */
#define BQ  128
#define BKV 64
#define QST 72
#define SQ_ELE (BQ*QST)
#define SK_ELE (BKV*QST)
#define FA_SMEM ((SQ_ELE + 2*SK_ELE + SK_ELE) * 2)   /* 46080 B */

__global__ void __launch_bounds__(128) flash_kernel(
    const hf* __restrict__ qkv, hf* __restrict__ att)
{
    extern __shared__ hf sm[];
    hf* Qs  = sm;
    hf* Ks0 = Qs + SQ_ELE;
    hf* Vs  = Ks0 + 2*SK_ELE;
    uint32_t* VW = reinterpret_cast<uint32_t*>(Vs);
    uint32_t sQ, sK0;
    {
        uint32_t base = (uint32_t)__cvta_generic_to_shared(sm);
        sQ = base; sK0 = base + SQ_ELE*2;
    }

    int t = threadIdx.x, lane = t & 31, wid = t >> 5;
    int gid = lane >> 2, tig = lane & 3;
    int bh = blockIdx.y, b = bh / HEADS, h = bh % HEADS;
    int q0 = blockIdx.x * BQ;

    const hf* Qp = qkv + ((long)b * SEQ + q0) * (3*DIM) + h * HD;
    const hf* Kp = qkv + (long)b * SEQ * (3*DIM) + DIM     + h * HD;
    const hf* Vp = qkv + (long)b * SEQ * (3*DIM) + 2*DIM   + h * HD;

    auto issueQ = [&]() {
        #pragma unroll
        for (int i = 0; i < 8; i++) {
            int g = t + i * 128;
            int row = g >> 3, c = g & 7;
            cp16(sQ + (row*QST + c*8)*2, Qp + (long)row*(3*DIM) + c*8);
        }
    };
    auto issueK = [&](int it) {
        uint32_t kb = sK0 + (it & 1) * (SK_ELE*2);
        #pragma unroll
        for (int i = 0; i < 4; i++) {
            int g = t + i * 128;
            int row = g >> 3, c = g & 7;
            cp16(kb + (row*QST + c*8)*2, Kp + (long)(it*BKV + row)*(3*DIM) + c*8);
        }
        asm volatile("cp.async.commit_group;");
    };

    int vrp = t & 31, vdb = (t >> 5) * 16;
    uint32_t va[8], vb[8];
    auto loadV = [&](int it) {
        const hf* p0 = Vp + (long)(it * BKV + 2*vrp) * (3*DIM) + vdb;
        const hf* p1 = p0 + 3*DIM;
        uint4 a0 = *reinterpret_cast<const uint4*>(p0);
        uint4 a1 = *reinterpret_cast<const uint4*>(p0 + 8);
        uint4 b0 = *reinterpret_cast<const uint4*>(p1);
        uint4 b1 = *reinterpret_cast<const uint4*>(p1 + 8);
        va[0]=a0.x; va[1]=a0.y; va[2]=a0.z; va[3]=a0.w;
        va[4]=a1.x; va[5]=a1.y; va[6]=a1.z; va[7]=a1.w;
        vb[0]=b0.x; vb[1]=b0.y; vb[2]=b0.z; vb[3]=b0.w;
        vb[4]=b1.x; vb[5]=b1.y; vb[6]=b1.z; vb[7]=b1.w;
    };

    issueQ();
    issueK(0);
    loadV(0);

    float acc[2][8][4];
    float oacc[2][8][4];
    float mrow[2][2], lrow[2][2];
    #pragma unroll
    for (int i = 0; i < 2; i++) {
        mrow[i][0] = mrow[i][1] = -1e30f;
        lrow[i][0] = lrow[i][1] = 0.0f;
        #pragma unroll
        for (int j = 0; j < 8; j++)
            #pragma unroll
            for (int r = 0; r < 4; r++) oacc[i][j][r] = 0.0f;
    }

    int wm = wid * 32;

    for (int it = 0; it < SEQ / BKV; it++) {
        asm volatile("cp.async.wait_group 0;");
        __syncthreads();
        hf* Ks = Ks0 + (it & 1) * SK_ELE;

        #pragma unroll
        for (int i = 0; i < 2; i++)
            #pragma unroll
            for (int j = 0; j < 8; j++)
                #pragma unroll
                for (int r = 0; r < 4; r++) acc[i][j][r] = 0.0f;

        /* S = Q @ K^T */
        #pragma unroll
        for (int ks = 0; ks < 4; ks++) {
            uint32_t qa[2][4];
            #pragma unroll
            for (int tm = 0; tm < 2; tm++) {
                int row = wm + tm*16 + gid;
                qa[tm][0] = *reinterpret_cast<const uint32_t*>(&Qs[ row    *QST + ks*16 + tig*2    ]);
                qa[tm][1] = *reinterpret_cast<const uint32_t*>(&Qs[(row+8)*QST + ks*16 + tig*2    ]);
                qa[tm][2] = *reinterpret_cast<const uint32_t*>(&Qs[ row    *QST + ks*16 + tig*2 + 8]);
                qa[tm][3] = *reinterpret_cast<const uint32_t*>(&Qs[(row+8)*QST + ks*16 + tig*2 + 8]);
            }
            #pragma unroll
            for (int tn = 0; tn < 8; tn++) {
                int nr = tn*8 + gid;
                uint32_t b0 = *reinterpret_cast<const uint32_t*>(&Ks[nr*QST + ks*16 + tig*2    ]);
                uint32_t b1 = *reinterpret_cast<const uint32_t*>(&Ks[nr*QST + ks*16 + tig*2 + 8]);
                #pragma unroll
                for (int tm = 0; tm < 2; tm++) {
                    float* c = acc[tm][tn];
                    mma16816(c[0],c[1],c[2],c[3], qa[tm][0],qa[tm][1],qa[tm][2],qa[tm][3], b0,b1);
                }
            }
        }

        /* scale + online softmax update */
        #pragma unroll
        for (int tm = 0; tm < 2; tm++) {
            float mx0 = -1e30f, mx1 = -1e30f;
            #pragma unroll
            for (int tn = 0; tn < 8; tn++) {
                float* c = acc[tm][tn];
                c[0] *= 0.125f; c[1] *= 0.125f; c[2] *= 0.125f; c[3] *= 0.125f;
                mx0 = fmaxf(mx0, fmaxf(c[0], c[1]));
                mx1 = fmaxf(mx1, fmaxf(c[2], c[3]));
            }
            #pragma unroll
            for (int o = 1; o <= 2; o <<= 1) {
                mx0 = fmaxf(mx0, __shfl_xor_sync(0xffffffffu, mx0, o));
                mx1 = fmaxf(mx1, __shfl_xor_sync(0xffffffffu, mx1, o));
            }
            float mn0 = fmaxf(mrow[tm][0], mx0);
            float mn1 = fmaxf(mrow[tm][1], mx1);
            float sc0 = __expf(mrow[tm][0] - mn0);
            float sc1 = __expf(mrow[tm][1] - mn1);
            float ls0 = 0.0f, ls1 = 0.0f;
            #pragma unroll
            for (int tn = 0; tn < 8; tn++) {
                float* c = acc[tm][tn];
                c[0] = __expf(c[0] - mn0);
                c[1] = __expf(c[1] - mn0);
                c[2] = __expf(c[2] - mn1);
                c[3] = __expf(c[3] - mn1);
                ls0 += c[0] + c[1];
                ls1 += c[2] + c[3];
            }
            #pragma unroll
            for (int o = 1; o <= 2; o <<= 1) {
                ls0 += __shfl_xor_sync(0xffffffffu, ls0, o);
                ls1 += __shfl_xor_sync(0xffffffffu, ls1, o);
            }
            lrow[tm][0] = lrow[tm][0] * sc0 + ls0;
            lrow[tm][1] = lrow[tm][1] * sc1 + ls1;
            mrow[tm][0] = mn0;
            mrow[tm][1] = mn1;
            #pragma unroll
            for (int to = 0; to < 8; to++) {
                oacc[tm][to][0] *= sc0; oacc[tm][to][1] *= sc0;
                oacc[tm][to][2] *= sc1; oacc[tm][to][3] *= sc1;
            }
        }

        /* store V tile transposed (pair-pack via prmt) */
        #pragma unroll
        for (int k = 0; k < 8; k++) {
            VW[(vdb + 2*k    ) * (QST/2) + vrp] = __byte_perm(va[k], vb[k], 0x5410);
            VW[(vdb + 2*k + 1) * (QST/2) + vrp] = __byte_perm(va[k], vb[k], 0x7632);
        }
        if (it + 1 < SEQ / BKV) {
            issueK(it + 1);
            loadV(it + 1);
        }
        __syncthreads();

        /* O += P @ V  (P fp16) */
        #pragma unroll
        for (int j = 0; j < 4; j++) {
            uint32_t pH[2][4];
            #pragma unroll
            for (int tm = 0; tm < 2; tm++) {
                pH[tm][0] = pack1(acc[tm][2*j  ][0], acc[tm][2*j  ][1]);
                pH[tm][1] = pack1(acc[tm][2*j  ][2], acc[tm][2*j  ][3]);
                pH[tm][2] = pack1(acc[tm][2*j+1][0], acc[tm][2*j+1][1]);
                pH[tm][3] = pack1(acc[tm][2*j+1][2], acc[tm][2*j+1][3]);
            }
            #pragma unroll
            for (int to = 0; to < 8; to++) {
                int d = to*8 + gid;
                uint32_t b0 = *reinterpret_cast<const uint32_t*>(&Vs[d*QST + j*16 + tig*2    ]);
                uint32_t b1 = *reinterpret_cast<const uint32_t*>(&Vs[d*QST + j*16 + tig*2 + 8]);
                #pragma unroll
                for (int tm = 0; tm < 2; tm++) {
                    float* c = oacc[tm][to];
                    mma16816(c[0],c[1],c[2],c[3], pH[tm][0],pH[tm][1],pH[tm][2],pH[tm][3], b0,b1);
                }
            }
        }
    }

    /* epilogue: O / l -> att (single fp16) */
    uint32_t* AW = reinterpret_cast<uint32_t*>(att);
    #pragma unroll
    for (int tm = 0; tm < 2; tm++) {
        float inv0 = 1.0f / lrow[tm][0];
        float inv1 = 1.0f / lrow[tm][1];
        int row = q0 + wm + tm*16 + gid;
        #pragma unroll
        for (int to = 0; to < 8; to++) {
            int col = h*HD + to*8 + tig*2;
            float* c = oacc[tm][to];
            long o0 = (((long)b*SEQ + row    ) * DIM + col) >> 1;
            long o1 = (((long)b*SEQ + row + 8) * DIM + col) >> 1;
            AW[o0] = pack1(c[0]*inv0, c[1]*inv0);
            AW[o1] = pack1(c[2]*inv1, c[3]*inv1);
        }
    }
}

/* ================= dense GEMM: pure fp16, templated BM =====================
 * BMT=128: 256 thr, 8 warps (2x4), 2 CTAs/SM.
 * BMT=64 : 128 thr, 4 warps (1x4), 3 CTAs/SM — for small-N GEMMs (tail fix).
 * Warp tile 64x32 in both; identical accumulation order -> identical bits.
 * 4-buffer depth-3 cp.async pipeline, one __syncthreads per chunk.
 */
#define BN  128
#define BK2 32
#define SEB 40

template <int BMT>
__global__ void __launch_bounds__(BMT*2, (BMT==128)?2:3) gemm_hf(
    const hf* __restrict__ Ag, const hf* __restrict__ Bg,
    const float* __restrict__ bias, const float* __restrict__ Rsd,
    float* __restrict__ Cf, hf* __restrict__ Ch, int doGelu,
    int M, int N, int K)
{
    constexpr int TSZA = BMT * SEB;
    constexpr int TSZB = BN  * SEB;
    extern __shared__ hf gsm[];
    uint32_t sbase = (uint32_t)__cvta_generic_to_shared(gsm);

    int m0 = blockIdx.y * BMT;
    int n0 = blockIdx.x * BN;
    int t  = threadIdx.x;
    int lane = t & 31, wid = t >> 5;
    int gid = lane >> 2, tig = lane & 3;
    int warp_m = (BMT == 128) ? ((wid >> 2) << 6) : 0;
    int warp_n = (wid & 3) << 5;

    int r0c = t >> 2, c0c = (t & 3) * 8;   /* r0c: 0..BMT/2-1 */

    auto issue = [&](int st) {
        int buf = st & 3;
        long k0 = (long)st * BK2;
        uint32_t dA = sbase + (buf*TSZA)*2;
        uint32_t dB = sbase + (4*TSZA + buf*TSZB)*2;
        /* A: BMT rows, 2 cp per thread */
        cp16(dA + ( r0c         *SEB + c0c)*2, Ag + (long)(m0 + r0c         )*K + k0 + c0c);
        cp16(dA + ((r0c+BMT/2)  *SEB + c0c)*2, Ag + (long)(m0 + r0c + BMT/2 )*K + k0 + c0c);
        /* B: 128 rows */
        if (BMT == 128) {
            cp16(dB + ( r0c     *SEB + c0c)*2, Bg + (long)(n0 + r0c     )*K + k0 + c0c);
            cp16(dB + ((r0c+64) *SEB + c0c)*2, Bg + (long)(n0 + r0c + 64)*K + k0 + c0c);
        } else {
            #pragma unroll
            for (int p = 0; p < 4; p++)
                cp16(dB + ((r0c + p*32)*SEB + c0c)*2,
                     Bg + (long)(n0 + r0c + p*32)*K + k0 + c0c);
        }
        asm volatile("cp.async.commit_group;");
    };

    float acc[4][4][4];
    #pragma unroll
    for (int i = 0; i < 4; i++)
        #pragma unroll
        for (int j = 0; j < 4; j++)
            #pragma unroll
            for (int r = 0; r < 4; r++) acc[i][j][r] = 0.0f;

    int t4 = lane >> 3, li = lane & 7;
    int a_row = (t4 & 1) * 8 + li,  a_col = (t4 >> 1) * 8;
    int b_row = (t4 >> 1) * 8 + li, b_col = (t4 & 1) * 8;

    int kt = K / BK2;
    issue(0); issue(1); issue(2);

    for (int kk = 0; kk < kt; kk++) {
        int rem = kt - 1 - kk;
        if (rem >= 2)      asm volatile("cp.async.wait_group 2;");
        else if (rem == 1) asm volatile("cp.async.wait_group 1;");
        else               asm volatile("cp.async.wait_group 0;");
        __syncthreads();
        if (kk + 3 < kt) issue(kk + 3);

        int buf = kk & 3;
        uint32_t sA = sbase + (buf*TSZA)*2;
        uint32_t sB = sbase + (4*TSZA + buf*TSZB)*2;

        #pragma unroll
        for (int ks = 0; ks < 2; ks++) {
            int kc = ks * 16;
            uint32_t a[4][4], bb2[2][4];
            #pragma unroll
            for (int tm = 0; tm < 4; tm++)
                ldm_x4(a[tm], sA + ((warp_m + tm*16 + a_row)*SEB + kc + a_col)*2);
            #pragma unroll
            for (int p = 0; p < 2; p++)
                ldm_x4(bb2[p], sB + ((warp_n + p*16 + b_row)*SEB + kc + b_col)*2);

            #pragma unroll
            for (int tm = 0; tm < 4; tm++)
                #pragma unroll
                for (int tn = 0; tn < 4; tn++) {
                    float* c = acc[tm][tn];
                    uint32_t* bb = bb2[tn >> 1];
                    mma16816(c[0],c[1],c[2],c[3],
                             a[tm][0],a[tm][1],a[tm][2],a[tm][3],
                             bb[(tn&1)*2], bb[(tn&1)*2+1]);
                }
        }
    }

    /* epilogue */
    #pragma unroll
    for (int tn = 0; tn < 4; tn++) {
        int col = n0 + warp_n + tn * 8 + tig * 2;
        float b0 = bias ? bias[col]     : 0.0f;
        float b1 = bias ? bias[col + 1] : 0.0f;
        #pragma unroll
        for (int tm = 0; tm < 4; tm++) {
            int row0 = m0 + warp_m + tm * 16 + gid;
            float* c = acc[tm][tn];
            #pragma unroll
            for (int half = 0; half < 2; half++) {
                int row = row0 + half * 8;
                float v0 = c[half*2 + 0] + b0;
                float v1 = c[half*2 + 1] + b1;
                long off = (long)row * N + col;
                if (Ch) {
                    if (doGelu) { v0 = gelu_tanh(v0); v1 = gelu_tanh(v1); }
                    reinterpret_cast<uint32_t*>(Ch)[off >> 1] = pack1(v0, v1);
                } else {
                    if (Rsd) {
                        float2 r = *reinterpret_cast<const float2*>(Rsd + off);
                        v0 += r.x; v1 += r.y;
                    }
                    *reinterpret_cast<float2*>(Cf + off) = make_float2(v0, v1);
                }
            }
        }
    }
}

#define GEMM_SMEM_128 (4*(128+128)*SEB*2)   /* 81920 */
#define GEMM_SMEM_64  (4*( 64+128)*SEB*2)   /* 61440 */

/* ---------------- launch --------------------------------------------------- */
extern "C" void kernel_launch(void* const* d_in, const int* in_sizes, int n_in,
                              void* d_out, int out_size)
{
    const float* x     = (const float*)d_in[0];
    const float* ln1s  = (const float*)d_in[1];
    const float* ln1b  = (const float*)d_in[2];
    const float* qkvw  = (const float*)d_in[3];
    const float* qkvb  = (const float*)d_in[4];
    const float* projw = (const float*)d_in[5];
    const float* projb = (const float*)d_in[6];
    const float* ln2s  = (const float*)d_in[7];
    const float* ln2b  = (const float*)d_in[8];
    const float* fc1w  = (const float*)d_in[9];
    const float* fc1b  = (const float*)d_in[10];
    const float* fc2w  = (const float*)d_in[11];
    const float* fc2b  = (const float*)d_in[12];
    float* out = (float*)d_out;

    hf *y, *qkvh, *att, *hb, *wq, *wp, *w1, *w2;
    float *x1;
    cudaGetSymbolAddress((void**)&y,    g_y);
    cudaGetSymbolAddress((void**)&qkvh, g_qkv);
    cudaGetSymbolAddress((void**)&att,  g_att);
    cudaGetSymbolAddress((void**)&x1,   g_x1);
    cudaGetSymbolAddress((void**)&hb,   g_h);
    cudaGetSymbolAddress((void**)&wq,   g_wq);
    cudaGetSymbolAddress((void**)&wp,   g_wp);
    cudaGetSymbolAddress((void**)&w1,   g_w1);
    cudaGetSymbolAddress((void**)&w2,   g_w2);

    cudaFuncSetAttribute(flash_kernel,
        cudaFuncAttributeMaxDynamicSharedMemorySize, FA_SMEM);
    cudaFuncSetAttribute(gemm_hf<128>,
        cudaFuncAttributeMaxDynamicSharedMemorySize, GEMM_SMEM_128);
    cudaFuncSetAttribute(gemm_hf<64>,
        cudaFuncAttributeMaxDynamicSharedMemorySize, GEMM_SMEM_64);

    /* 0. all weight transposes, one launch */
    wt_all_kernel<<<6912, dim3(32,8)>>>(qkvw, projw, fc1w, fc2w, wq, wp, w1, w2);

    /* 1. LN1 -> y fp16 */
    ln_kernel<<<ROWS, 256>>>(x, ln1s, ln1b, y);

    /* 2. QKV = y @ Wq + b  (fp16 out)  — 1152 CTAs, BM=128 */
    gemm_hf<128><<<dim3(3*DIM/BN, ROWS/128), 256, GEMM_SMEM_128>>>(
        y, wq, qkvb, nullptr, nullptr, qkvh, 0,
        ROWS, 3*DIM, DIM);

    /* 3-5. flash attention -> att fp16 */
    flash_kernel<<<dim3(SEQ / BQ, BATCH * HEADS), 128, FA_SMEM>>>(qkvh, att);

    /* 6. x1 = att @ Wp + b + x  (f32 out)  — 768 CTAs, BM=64 (tail fix) */
    gemm_hf<64><<<dim3(DIM/BN, ROWS/64), 128, GEMM_SMEM_64>>>(
        att, wp, projb, x, x1, nullptr, 0,
        ROWS, DIM, DIM);

    /* 7. LN2 -> y fp16 */
    ln_kernel<<<ROWS, 256>>>(x1, ln2s, ln2b, y);

    /* 8. h = gelu(y @ W1 + b)  (fp16 out)  — 1536 CTAs, BM=128 */
    gemm_hf<128><<<dim3(HIDDEN/BN, ROWS/128), 256, GEMM_SMEM_128>>>(
        y, w1, fc1b, nullptr, nullptr, hb, 1,
        ROWS, HIDDEN, DIM);

    /* 9. out = h @ W2 + b + x1  (f32 out)  — 768 CTAs, BM=64 (tail fix) */
    gemm_hf<64><<<dim3(DIM/BN, ROWS/64), 128, GEMM_SMEM_64>>>(
        hb, w2, fc2b, x1, out, nullptr, 0,
        ROWS, DIM, HIDDEN);
}